// round 5
// baseline (speedup 1.0000x reference)
#include <cuda_runtime.h>
#include <math.h>

#define H    1024
#define NH   16
#define HD   64
#define FF   4096
#define SEQ  2048
#define BTOK 8192   // 4 * 2048 tokens

// ---------------------------------------------------------------------------
// Scratch (static __device__ globals: allocation-free rule)
// ---------------------------------------------------------------------------
__device__ float g_q[BTOK * H];
__device__ float g_k[BTOK * H];
__device__ float g_v[BTOK * H];
__device__ float g_ctx[BTOK * H];
__device__ float g_x[BTOK * H];
__device__ float g_inter[(size_t)BTOK * FF];
__device__ float g_ffn[BTOK * H];

// ---------------------------------------------------------------------------
// Generic SGEMM: C[M,N] = A[M,K] @ B[K,N] + bias, optional exact-gelu+clamp.
// 128x128 block tile, BK=8, 256 threads, 8x8 register micro-tile.
// Assumes M%128==0, N%128==0, K%8==0 (true for all shapes here).
// ---------------------------------------------------------------------------
__device__ __forceinline__ float gelu_exact(float x) {
    return 0.5f * x * (1.0f + erff(x * 0.70710678118654752f));
}

template <int EPI>  // 0: +bias   1: gelu(+bias) with clamp
__global__ __launch_bounds__(256, 2)
void sgemm_k(const float* __restrict__ A, const float* __restrict__ B,
             const float* __restrict__ bias, float* __restrict__ C,
             int M, int N, int K)
{
    __shared__ float As[8][128];
    __shared__ float Bs[8][128];

    const int tid = threadIdx.x;
    const int tx  = tid & 15;        // 0..15 -> N micro
    const int ty  = tid >> 4;        // 0..15 -> M micro
    const int row0 = blockIdx.y * 128;
    const int col0 = blockIdx.x * 128;

    const int arow = tid >> 1;       // 0..127
    const int acol = (tid & 1) * 4;  // 0 or 4
    const int brow = tid >> 5;       // 0..7
    const int bcol = (tid & 31) * 4; // 0..124

    const float* Aptr = A + (size_t)(row0 + arow) * K + acol;
    const float* Bptr = B + (size_t)brow * N + col0 + bcol;

    float acc[8][8];
#pragma unroll
    for (int i = 0; i < 8; i++)
#pragma unroll
        for (int j = 0; j < 8; j++) acc[i][j] = 0.0f;

    for (int k0 = 0; k0 < K; k0 += 8) {
        float4 a = *(const float4*)(Aptr + k0);
        float4 b = *(const float4*)(Bptr + (size_t)k0 * N);
        As[acol + 0][arow] = a.x;
        As[acol + 1][arow] = a.y;
        As[acol + 2][arow] = a.z;
        As[acol + 3][arow] = a.w;
        *(float4*)&Bs[brow][bcol] = b;
        __syncthreads();

#pragma unroll
        for (int kk = 0; kk < 8; kk++) {
            float ra[8], rb[8];
#pragma unroll
            for (int i = 0; i < 8; i++) ra[i] = As[kk][ty * 8 + i];
#pragma unroll
            for (int j = 0; j < 8; j++) rb[j] = Bs[kk][tx * 8 + j];
#pragma unroll
            for (int i = 0; i < 8; i++)
#pragma unroll
                for (int j = 0; j < 8; j++) acc[i][j] = fmaf(ra[i], rb[j], acc[i][j]);
        }
        __syncthreads();
    }

    // epilogue
    float bz[8];
#pragma unroll
    for (int j = 0; j < 8; j++) bz[j] = bias[col0 + tx * 8 + j];

#pragma unroll
    for (int i = 0; i < 8; i++) {
        const int r = row0 + ty * 8 + i;
        float v[8];
#pragma unroll
        for (int j = 0; j < 8; j++) {
            float t = acc[i][j] + bz[j];
            if (EPI == 1) {
                t = gelu_exact(t);
                t = fminf(fmaxf(t, -1e9f), 1e9f);
            }
            v[j] = t;
        }
        float4 o0 = make_float4(v[0], v[1], v[2], v[3]);
        float4 o1 = make_float4(v[4], v[5], v[6], v[7]);
        float* cp = C + (size_t)r * N + col0 + tx * 8;
        *(float4*)(cp + 0) = o0;
        *(float4*)(cp + 4) = o1;
    }
}

// ---------------------------------------------------------------------------
// Flash-style attention, SIMT. One block = 64 queries of one (b,h).
// 256 threads: 16x16 grid, 4x4 micro-tiles for both QK^T and PV.
// K tile stored transposed in smem (KsT[kk][key]) for conflict-free float4.
// ctx = softmax(QK^T/8 clamp)@V + 1e-9 * colsum(V)  (epsilon fold-in).
// ---------------------------------------------------------------------------
#define ATTN_PAD  68           // row stride (keeps 16B alignment + bank spread)
#define ATTN_TILE (64 * ATTN_PAD)
#define ATTN_SMEM ((4 * ATTN_TILE + 3 * 64) * 4)

__global__ __launch_bounds__(256)
void attn_kernel(const float* __restrict__ Q, const float* __restrict__ K,
                 const float* __restrict__ V, float* __restrict__ O)
{
    extern __shared__ float sm[];
    float* Qs   = sm;                       // [q][d]   stride 68
    float* KsT  = sm + ATTN_TILE;           // [d][key] stride 68 (transposed)
    float* Vs   = sm + 2 * ATTN_TILE;       // [key][d] stride 68
    float* Ss   = sm + 3 * ATTN_TILE;       // [q][key] stride 68
    float* m_s  = sm + 4 * ATTN_TILE;
    float* l_s  = m_s + 64;
    float* sc_s = l_s + 64;

    const int tid = threadIdx.x;
    const int tx  = tid & 15;
    const int ty  = tid >> 4;
    const int q0  = ty * 4;

    const int bh = blockIdx.y;
    const int b  = bh >> 4;
    const int h  = bh & 15;
    const int qstart = blockIdx.x * 64;
    const size_t base = (size_t)b * SEQ * H + (size_t)h * HD;

    // load Q tile
#pragma unroll
    for (int it = 0; it < 16; it++) {
        int idx = tid + it * 256;
        int r = idx >> 6, c = idx & 63;
        Qs[r * ATTN_PAD + c] = Q[base + (size_t)(qstart + r) * H + c];
    }
    if (tid < 64) { m_s[tid] = -1e30f; l_s[tid] = 0.0f; }

    float acc[4][4];
#pragma unroll
    for (int i = 0; i < 4; i++)
#pragma unroll
        for (int j = 0; j < 4; j++) acc[i][j] = 0.0f;
    float sv[4] = {0.f, 0.f, 0.f, 0.f};

    __syncthreads();

    for (int kt = 0; kt < SEQ / 64; kt++) {
        const int kstart = kt * 64;
        // load K (transposed) and V tiles
#pragma unroll
        for (int it = 0; it < 16; it++) {
            int idx = tid + it * 256;
            int r = idx >> 6, c = idx & 63;
            size_t gi = base + (size_t)(kstart + r) * H + c;
            KsT[c * ATTN_PAD + r] = K[gi];
            Vs[r * ATTN_PAD + c]  = V[gi];
        }
        __syncthreads();

        // scores: s[i][j] = Q[q0+i,:] . K[tx*4+j,:]
        float s[4][4];
#pragma unroll
        for (int i = 0; i < 4; i++)
#pragma unroll
            for (int j = 0; j < 4; j++) s[i][j] = 0.0f;

#pragma unroll
        for (int kk = 0; kk < 64; kk++) {
            float rq[4];
#pragma unroll
            for (int i = 0; i < 4; i++) rq[i] = Qs[(q0 + i) * ATTN_PAD + kk];
            float4 rk4 = *(const float4*)&KsT[kk * ATTN_PAD + tx * 4];
            float rk[4] = {rk4.x, rk4.y, rk4.z, rk4.w};
#pragma unroll
            for (int i = 0; i < 4; i++)
#pragma unroll
                for (int j = 0; j < 4; j++) s[i][j] = fmaf(rq[i], rk[j], s[i][j]);
        }

        // scale, clamp, stage into Ss
#pragma unroll
        for (int i = 0; i < 4; i++)
#pragma unroll
            for (int j = 0; j < 4; j++) {
                float v = s[i][j] * 0.125f;
                v = fminf(fmaxf(v, -1e9f), 1e9f);
                Ss[(q0 + i) * ATTN_PAD + tx * 4 + j] = v;
            }
        __syncthreads();

        // online softmax per row (threads 0..63)
        if (tid < 64) {
            const int r = tid;
            float mo = m_s[r];
            float mt = mo;
#pragma unroll 8
            for (int j = 0; j < 64; j++) mt = fmaxf(mt, Ss[r * ATTN_PAD + j]);
            float sc = __expf(mo - mt);
            float sum = 0.0f;
#pragma unroll 8
            for (int j = 0; j < 64; j++) {
                float e = __expf(Ss[r * ATTN_PAD + j] - mt);
                Ss[r * ATTN_PAD + j] = e;
                sum += e;
            }
            m_s[r]  = mt;
            l_s[r]  = l_s[r] * sc + sum;
            sc_s[r] = sc;
        }
        __syncthreads();

        // rescale accumulators
        float scl[4];
#pragma unroll
        for (int i = 0; i < 4; i++) scl[i] = sc_s[q0 + i];
#pragma unroll
        for (int i = 0; i < 4; i++)
#pragma unroll
            for (int j = 0; j < 4; j++) acc[i][j] *= scl[i];

        // PV: acc += P @ V; also accumulate colsum(V) for the 1e-9 epsilon
#pragma unroll
        for (int kk = 0; kk < 64; kk++) {
            float rp[4];
#pragma unroll
            for (int i = 0; i < 4; i++) rp[i] = Ss[(q0 + i) * ATTN_PAD + kk];
            float4 rv4 = *(const float4*)&Vs[kk * ATTN_PAD + tx * 4];
            float rv[4] = {rv4.x, rv4.y, rv4.z, rv4.w};
#pragma unroll
            for (int j = 0; j < 4; j++) sv[j] += rv[j];
#pragma unroll
            for (int i = 0; i < 4; i++)
#pragma unroll
                for (int j = 0; j < 4; j++) acc[i][j] = fmaf(rp[i], rv[j], acc[i][j]);
        }
        __syncthreads();
    }

    // epilogue: normalize + epsilon term, write ctx
    float linv[4];
#pragma unroll
    for (int i = 0; i < 4; i++) linv[i] = 1.0f / l_s[q0 + i];
#pragma unroll
    for (int i = 0; i < 4; i++) {
        float4 o;
        o.x = acc[i][0] * linv[i] + 1e-9f * sv[0];
        o.y = acc[i][1] * linv[i] + 1e-9f * sv[1];
        o.z = acc[i][2] * linv[i] + 1e-9f * sv[2];
        o.w = acc[i][3] * linv[i] + 1e-9f * sv[3];
        *(float4*)&O[base + (size_t)(qstart + q0 + i) * H + tx * 4] = o;
    }
}

// ---------------------------------------------------------------------------
// Fused residual-add + LayerNorm over H=1024. One block per row, 256 threads,
// one float4 per thread.
// ---------------------------------------------------------------------------
__global__ __launch_bounds__(256)
void add_ln_kernel(const float* __restrict__ A, const float* __restrict__ Bres,
                   const float* __restrict__ gam, const float* __restrict__ bet,
                   float* __restrict__ out)
{
    const int row = blockIdx.x;
    const int tid = threadIdx.x;
    const float4 va = ((const float4*)(A    + (size_t)row * H))[tid];
    const float4 vb = ((const float4*)(Bres + (size_t)row * H))[tid];
    float x0 = va.x + vb.x, x1 = va.y + vb.y, x2 = va.z + vb.z, x3 = va.w + vb.w;

    __shared__ float red[8];
    __shared__ float s_mu, s_rstd;

    float s = x0 + x1 + x2 + x3;
#pragma unroll
    for (int o = 16; o; o >>= 1) s += __shfl_down_sync(0xffffffffu, s, o);
    if ((tid & 31) == 0) red[tid >> 5] = s;
    __syncthreads();
    if (tid == 0) {
        float t = 0.f;
#pragma unroll
        for (int i = 0; i < 8; i++) t += red[i];
        s_mu = t * (1.0f / H);
    }
    __syncthreads();
    const float mu = s_mu;
    float d0 = x0 - mu, d1 = x1 - mu, d2 = x2 - mu, d3 = x3 - mu;
    float ss = d0 * d0 + d1 * d1 + d2 * d2 + d3 * d3;
#pragma unroll
    for (int o = 16; o; o >>= 1) ss += __shfl_down_sync(0xffffffffu, ss, o);
    __syncthreads();               // red reuse safety
    if ((tid & 31) == 0) red[tid >> 5] = ss;
    __syncthreads();
    if (tid == 0) {
        float t = 0.f;
#pragma unroll
        for (int i = 0; i < 8; i++) t += red[i];
        s_rstd = rsqrtf(t * (1.0f / H) + 1e-12f);
    }
    __syncthreads();
    const float rstd = s_rstd;

    const float4 g4 = ((const float4*)gam)[tid];
    const float4 b4 = ((const float4*)bet)[tid];
    float4 o;
    o.x = d0 * rstd * g4.x + b4.x;
    o.y = d1 * rstd * g4.y + b4.y;
    o.z = d2 * rstd * g4.z + b4.z;
    o.w = d3 * rstd * g4.w + b4.w;
    ((float4*)(out + (size_t)row * H))[tid] = o;
}

// ---------------------------------------------------------------------------
// Launch
// ---------------------------------------------------------------------------
extern "C" void kernel_launch(void* const* d_in, const int* in_sizes, int n_in,
                              void* d_out, int out_size)
{
    const float* hs   = (const float*)d_in[0];
    const float* Wq   = (const float*)d_in[1];
    const float* bq   = (const float*)d_in[2];
    const float* Wk   = (const float*)d_in[3];
    const float* bk   = (const float*)d_in[4];
    const float* Wv   = (const float*)d_in[5];
    const float* bv   = (const float*)d_in[6];
    const float* ln1g = (const float*)d_in[7];
    const float* ln1b = (const float*)d_in[8];
    const float* W1   = (const float*)d_in[9];
    const float* b1   = (const float*)d_in[10];
    const float* W2   = (const float*)d_in[11];
    const float* b2   = (const float*)d_in[12];
    const float* ln2g = (const float*)d_in[13];
    const float* ln2b = (const float*)d_in[14];
    float* out = (float*)d_out;

    static float *pq = nullptr, *pk = nullptr, *pv = nullptr, *pctx = nullptr,
                 *px = nullptr, *pinter = nullptr, *pffn = nullptr;
    if (!pq) {  // first call is the (uncaptured) correctness run
        cudaGetSymbolAddress((void**)&pq,     g_q);
        cudaGetSymbolAddress((void**)&pk,     g_k);
        cudaGetSymbolAddress((void**)&pv,     g_v);
        cudaGetSymbolAddress((void**)&pctx,   g_ctx);
        cudaGetSymbolAddress((void**)&px,     g_x);
        cudaGetSymbolAddress((void**)&pinter, g_inter);
        cudaGetSymbolAddress((void**)&pffn,   g_ffn);
        cudaFuncSetAttribute(attn_kernel,
                             cudaFuncAttributeMaxDynamicSharedMemorySize,
                             ATTN_SMEM);
    }

    const dim3 blk(256);
    // QKV projections
    sgemm_k<0><<<dim3(H / 128, BTOK / 128), blk>>>(hs, Wq, bq, pq, BTOK, H, H);
    sgemm_k<0><<<dim3(H / 128, BTOK / 128), blk>>>(hs, Wk, bk, pk, BTOK, H, H);
    sgemm_k<0><<<dim3(H / 128, BTOK / 128), blk>>>(hs, Wv, bv, pv, BTOK, H, H);
    // attention -> ctx
    attn_kernel<<<dim3(SEQ / 64, 4 * NH), 256, ATTN_SMEM>>>(pq, pk, pv, pctx);
    // residual + LN1 -> x
    add_ln_kernel<<<BTOK, 256>>>(hs, pctx, ln1g, ln1b, px);
    // FFN
    sgemm_k<1><<<dim3(FF / 128, BTOK / 128), blk>>>(px, W1, b1, pinter, BTOK, FF, H);
    sgemm_k<0><<<dim3(H / 128, BTOK / 128), blk>>>(pinter, W2, b2, pffn, BTOK, H, FF);
    // residual + LN2 -> out
    add_ln_kernel<<<BTOK, 256>>>(pffn, px, ln2g, ln2b, out);
}

// round 7
// speedup vs baseline: 1.7725x; 1.7725x over previous
#include <cuda_runtime.h>
#include <math.h>
#include <stdint.h>

#define H    1024
#define NH   16
#define HD   64
#define FF   4096
#define SEQ  2048
#define BTOK 8192   // 4 * 2048 tokens

// ---------------------------------------------------------------------------
// Scratch (static __device__ globals: allocation-free rule)
// ---------------------------------------------------------------------------
__device__ float g_q[BTOK * H];
__device__ float g_k[BTOK * H];
__device__ float g_v[BTOK * H];
__device__ float g_ctx[BTOK * H];
__device__ float g_x[BTOK * H];
__device__ float g_inter[(size_t)BTOK * FF];
__device__ float g_ffn[BTOK * H];
// transposed (tf32-rounded) weights: Wt[n][k] = tf32(W[k][n])
__device__ float g_wtq[H * H];
__device__ float g_wtk[H * H];
__device__ float g_wtv[H * H];
__device__ float g_wt1[(size_t)H * FF];   // [FF][H]
__device__ float g_wt2[(size_t)FF * H];   // [H][FF]

// ---------------------------------------------------------------------------
// Helpers
// ---------------------------------------------------------------------------
__device__ __forceinline__ float tf32r(float x) {
    uint32_t u;
    asm("cvt.rna.tf32.f32 %0, %1;" : "=r"(u) : "f"(x));
    return __uint_as_float(u);
}
__device__ __forceinline__ float gelu_exact(float x) {
    return 0.5f * x * (1.0f + erff(x * 0.70710678118654752f));
}

// ---------------------------------------------------------------------------
// Weight transpose + tf32 rounding: W[K][N] -> Wt[N][K]
// ---------------------------------------------------------------------------
__global__ __launch_bounds__(256)
void transpose_tf32_k(const float* __restrict__ W, float* __restrict__ Wt,
                      int K, int N)
{
    __shared__ float t[32][33];
    const int tx = threadIdx.x & 31;
    const int ty = threadIdx.x >> 5;   // 0..7
    const int n0 = blockIdx.x * 32;
    const int k0 = blockIdx.y * 32;
#pragma unroll
    for (int i = 0; i < 4; i++) {
        int r = ty + i * 8;
        t[r][tx] = tf32r(W[(size_t)(k0 + r) * N + n0 + tx]);
    }
    __syncthreads();
#pragma unroll
    for (int i = 0; i < 4; i++) {
        int r = ty + i * 8;
        Wt[(size_t)(n0 + r) * K + k0 + tx] = t[tx][r];
    }
}

// ---------------------------------------------------------------------------
// TF32 tensor-core GEMM via mma.sync.m16n8k8 (warp-level HMMA path; no
// tcgen05 — ptxas target is plain sm_103).
//   C[M,N] = A[M,K] @ Bt[N,K]^T + bias   (EPI=1: exact gelu + clamp)
// CTA tile 128x128, BK=16, 256 threads = 8 warps (4M x 2N), warp tile 32x64.
// Smem layout [row][k] with row stride 20 floats: fragment LDS pattern
// (20*r + c) mod 32 hits all 32 banks -> conflict-free.
// Double-buffered; LDG register-staged so loads overlap the 32 MMAs/warp.
// ---------------------------------------------------------------------------
#define BM 128
#define BN 128
#define BKG 16
#define PADK 20

#define MMA_TF32(ACC, A0, A1, A2, A3, B0, B1)                                  \
    asm volatile(                                                              \
        "mma.sync.aligned.m16n8k8.row.col.f32.tf32.tf32.f32 "                  \
        "{%0,%1,%2,%3}, {%4,%5,%6,%7}, {%8,%9}, {%0,%1,%2,%3};"                \
        : "+f"((ACC)[0]), "+f"((ACC)[1]), "+f"((ACC)[2]), "+f"((ACC)[3])       \
        : "r"(A0), "r"(A1), "r"(A2), "r"(A3), "r"(B0), "r"(B1))

template <int EPI>  // 0: +bias   1: gelu(+bias)+clamp
__global__ __launch_bounds__(256)
void mma_gemm(const float* __restrict__ A, const float* __restrict__ Bt,
              const float* __restrict__ bias, float* __restrict__ C,
              int M, int N, int K)
{
    __shared__ float As[2][BM][PADK];
    __shared__ float Bs[2][BN][PADK];

    const int tid  = threadIdx.x;
    const int lane = tid & 31;
    const int wid  = tid >> 5;
    const int wm0  = (wid >> 1) * 32;   // 0,32,64,96
    const int wn0  = (wid & 1) * 64;    // 0,64
    const int r    = lane >> 2;         // 0..7
    const int c    = lane & 3;          // 0..3

    const int row0 = blockIdx.y * BM;
    const int col0 = blockIdx.x * BN;

    const int ldr = tid >> 2;           // 0..63
    const int ldc = (tid & 3) * 4;      // 0,4,8,12

    const float* Ap = A  + (size_t)(row0 + ldr) * K + ldc;
    const float* Bp = Bt + (size_t)(col0 + ldr) * K + ldc;
    const size_t stride64 = (size_t)64 * K;

    float acc[2][8][4];
#pragma unroll
    for (int mt = 0; mt < 2; mt++)
#pragma unroll
        for (int nt = 0; nt < 8; nt++)
#pragma unroll
            for (int u = 0; u < 4; u++) acc[mt][nt][u] = 0.0f;

    float4 ra0, ra1, rb0, rb1;

    // prologue: stage 0
    ra0 = *(const float4*)(Ap);
    ra1 = *(const float4*)(Ap + stride64);
    rb0 = *(const float4*)(Bp);
    rb1 = *(const float4*)(Bp + stride64);
    {
        float4 t0 = make_float4(tf32r(ra0.x), tf32r(ra0.y), tf32r(ra0.z), tf32r(ra0.w));
        float4 t1 = make_float4(tf32r(ra1.x), tf32r(ra1.y), tf32r(ra1.z), tf32r(ra1.w));
        *(float4*)&As[0][ldr][ldc]      = t0;
        *(float4*)&As[0][ldr + 64][ldc] = t1;
        *(float4*)&Bs[0][ldr][ldc]      = rb0;
        *(float4*)&Bs[0][ldr + 64][ldc] = rb1;
    }
    __syncthreads();

    const int NS = K / BKG;
    for (int s = 0; s < NS; s++) {
        const int cur = s & 1;
        if (s + 1 < NS) {
            const int k0 = (s + 1) * BKG;
            ra0 = *(const float4*)(Ap + k0);
            ra1 = *(const float4*)(Ap + stride64 + k0);
            rb0 = *(const float4*)(Bp + k0);
            rb1 = *(const float4*)(Bp + stride64 + k0);
        }

#pragma unroll
        for (int ks = 0; ks < 2; ks++) {
            const int k = ks * 8;
            uint32_t af[2][4];
#pragma unroll
            for (int mt = 0; mt < 2; mt++) {
                const int m = wm0 + mt * 16 + r;
                af[mt][0] = __float_as_uint(As[cur][m][k + c]);
                af[mt][1] = __float_as_uint(As[cur][m + 8][k + c]);
                af[mt][2] = __float_as_uint(As[cur][m][k + c + 4]);
                af[mt][3] = __float_as_uint(As[cur][m + 8][k + c + 4]);
            }
#pragma unroll
            for (int nt = 0; nt < 8; nt++) {
                const int n = wn0 + nt * 8 + r;
                const uint32_t b0 = __float_as_uint(Bs[cur][n][k + c]);
                const uint32_t b1 = __float_as_uint(Bs[cur][n][k + c + 4]);
                MMA_TF32(acc[0][nt], af[0][0], af[0][1], af[0][2], af[0][3], b0, b1);
                MMA_TF32(acc[1][nt], af[1][0], af[1][1], af[1][2], af[1][3], b0, b1);
            }
        }

        if (s + 1 < NS) {
            const int nxt = (s + 1) & 1;
            float4 t0 = make_float4(tf32r(ra0.x), tf32r(ra0.y), tf32r(ra0.z), tf32r(ra0.w));
            float4 t1 = make_float4(tf32r(ra1.x), tf32r(ra1.y), tf32r(ra1.z), tf32r(ra1.w));
            *(float4*)&As[nxt][ldr][ldc]      = t0;
            *(float4*)&As[nxt][ldr + 64][ldc] = t1;
            *(float4*)&Bs[nxt][ldr][ldc]      = rb0;
            *(float4*)&Bs[nxt][ldr + 64][ldc] = rb1;
        }
        __syncthreads();
    }

    // epilogue
#pragma unroll
    for (int mt = 0; mt < 2; mt++) {
        const int rowA = row0 + wm0 + mt * 16 + r;
#pragma unroll
        for (int nt = 0; nt < 8; nt++) {
            const int col = col0 + wn0 + nt * 8 + 2 * c;
            const float bz0 = bias[col];
            const float bz1 = bias[col + 1];
            float v0 = acc[mt][nt][0] + bz0;
            float v1 = acc[mt][nt][1] + bz1;
            float v2 = acc[mt][nt][2] + bz0;
            float v3 = acc[mt][nt][3] + bz1;
            if (EPI == 1) {
                v0 = fminf(fmaxf(gelu_exact(v0), -1e9f), 1e9f);
                v1 = fminf(fmaxf(gelu_exact(v1), -1e9f), 1e9f);
                v2 = fminf(fmaxf(gelu_exact(v2), -1e9f), 1e9f);
                v3 = fminf(fmaxf(gelu_exact(v3), -1e9f), 1e9f);
            }
            *(float2*)(C + (size_t)rowA * N + col)       = make_float2(v0, v1);
            *(float2*)(C + (size_t)(rowA + 8) * N + col) = make_float2(v2, v3);
        }
    }
}

// ---------------------------------------------------------------------------
// Flash-style attention, SIMT (unchanged — fp32 exact path).
// ---------------------------------------------------------------------------
#define ATTN_PAD  68
#define ATTN_TILE (64 * ATTN_PAD)
#define ATTN_SMEM ((4 * ATTN_TILE + 3 * 64) * 4)

__global__ __launch_bounds__(256)
void attn_kernel(const float* __restrict__ Q, const float* __restrict__ K,
                 const float* __restrict__ V, float* __restrict__ O)
{
    extern __shared__ float smf[];
    float* Qs   = smf;
    float* KsT  = smf + ATTN_TILE;
    float* Vs   = smf + 2 * ATTN_TILE;
    float* Ss   = smf + 3 * ATTN_TILE;
    float* m_s  = smf + 4 * ATTN_TILE;
    float* l_s  = m_s + 64;
    float* sc_s = l_s + 64;

    const int tid = threadIdx.x;
    const int tx  = tid & 15;
    const int ty  = tid >> 4;
    const int q0  = ty * 4;

    const int bh = blockIdx.y;
    const int b  = bh >> 4;
    const int h  = bh & 15;
    const int qstart = blockIdx.x * 64;
    const size_t base = (size_t)b * SEQ * H + (size_t)h * HD;

#pragma unroll
    for (int it = 0; it < 16; it++) {
        int idx = tid + it * 256;
        int r = idx >> 6, c = idx & 63;
        Qs[r * ATTN_PAD + c] = Q[base + (size_t)(qstart + r) * H + c];
    }
    if (tid < 64) { m_s[tid] = -1e30f; l_s[tid] = 0.0f; }

    float acc[4][4];
#pragma unroll
    for (int i = 0; i < 4; i++)
#pragma unroll
        for (int j = 0; j < 4; j++) acc[i][j] = 0.0f;
    float sv[4] = {0.f, 0.f, 0.f, 0.f};

    __syncthreads();

    for (int kt = 0; kt < SEQ / 64; kt++) {
        const int kstart = kt * 64;
#pragma unroll
        for (int it = 0; it < 16; it++) {
            int idx = tid + it * 256;
            int r = idx >> 6, c = idx & 63;
            size_t gi = base + (size_t)(kstart + r) * H + c;
            KsT[c * ATTN_PAD + r] = K[gi];
            Vs[r * ATTN_PAD + c]  = V[gi];
        }
        __syncthreads();

        float s[4][4];
#pragma unroll
        for (int i = 0; i < 4; i++)
#pragma unroll
            for (int j = 0; j < 4; j++) s[i][j] = 0.0f;

#pragma unroll
        for (int kk = 0; kk < 64; kk++) {
            float rq[4];
#pragma unroll
            for (int i = 0; i < 4; i++) rq[i] = Qs[(q0 + i) * ATTN_PAD + kk];
            float4 rk4 = *(const float4*)&KsT[kk * ATTN_PAD + tx * 4];
            float rk[4] = {rk4.x, rk4.y, rk4.z, rk4.w};
#pragma unroll
            for (int i = 0; i < 4; i++)
#pragma unroll
                for (int j = 0; j < 4; j++) s[i][j] = fmaf(rq[i], rk[j], s[i][j]);
        }

#pragma unroll
        for (int i = 0; i < 4; i++)
#pragma unroll
            for (int j = 0; j < 4; j++) {
                float v = s[i][j] * 0.125f;
                v = fminf(fmaxf(v, -1e9f), 1e9f);
                Ss[(q0 + i) * ATTN_PAD + tx * 4 + j] = v;
            }
        __syncthreads();

        if (tid < 64) {
            const int r = tid;
            float mo = m_s[r];
            float mt = mo;
#pragma unroll 8
            for (int j = 0; j < 64; j++) mt = fmaxf(mt, Ss[r * ATTN_PAD + j]);
            float sc = __expf(mo - mt);
            float sum = 0.0f;
#pragma unroll 8
            for (int j = 0; j < 64; j++) {
                float e = __expf(Ss[r * ATTN_PAD + j] - mt);
                Ss[r * ATTN_PAD + j] = e;
                sum += e;
            }
            m_s[r]  = mt;
            l_s[r]  = l_s[r] * sc + sum;
            sc_s[r] = sc;
        }
        __syncthreads();

        float scl[4];
#pragma unroll
        for (int i = 0; i < 4; i++) scl[i] = sc_s[q0 + i];
#pragma unroll
        for (int i = 0; i < 4; i++)
#pragma unroll
            for (int j = 0; j < 4; j++) acc[i][j] *= scl[i];

#pragma unroll
        for (int kk = 0; kk < 64; kk++) {
            float rp[4];
#pragma unroll
            for (int i = 0; i < 4; i++) rp[i] = Ss[(q0 + i) * ATTN_PAD + kk];
            float4 rv4 = *(const float4*)&Vs[kk * ATTN_PAD + tx * 4];
            float rv[4] = {rv4.x, rv4.y, rv4.z, rv4.w};
#pragma unroll
            for (int j = 0; j < 4; j++) sv[j] += rv[j];
#pragma unroll
            for (int i = 0; i < 4; i++)
#pragma unroll
                for (int j = 0; j < 4; j++) acc[i][j] = fmaf(rp[i], rv[j], acc[i][j]);
        }
        __syncthreads();
    }

    float linv[4];
#pragma unroll
    for (int i = 0; i < 4; i++) linv[i] = 1.0f / l_s[q0 + i];
#pragma unroll
    for (int i = 0; i < 4; i++) {
        float4 o;
        o.x = acc[i][0] * linv[i] + 1e-9f * sv[0];
        o.y = acc[i][1] * linv[i] + 1e-9f * sv[1];
        o.z = acc[i][2] * linv[i] + 1e-9f * sv[2];
        o.w = acc[i][3] * linv[i] + 1e-9f * sv[3];
        *(float4*)&O[base + (size_t)(qstart + q0 + i) * H + tx * 4] = o;
    }
}

// ---------------------------------------------------------------------------
// Fused residual-add + LayerNorm (unchanged).
// ---------------------------------------------------------------------------
__global__ __launch_bounds__(256)
void add_ln_kernel(const float* __restrict__ A, const float* __restrict__ Bres,
                   const float* __restrict__ gam, const float* __restrict__ bet,
                   float* __restrict__ out)
{
    const int row = blockIdx.x;
    const int tid = threadIdx.x;
    const float4 va = ((const float4*)(A    + (size_t)row * H))[tid];
    const float4 vb = ((const float4*)(Bres + (size_t)row * H))[tid];
    float x0 = va.x + vb.x, x1 = va.y + vb.y, x2 = va.z + vb.z, x3 = va.w + vb.w;

    __shared__ float red[8];
    __shared__ float s_mu, s_rstd;

    float s = x0 + x1 + x2 + x3;
#pragma unroll
    for (int o = 16; o; o >>= 1) s += __shfl_down_sync(0xffffffffu, s, o);
    if ((tid & 31) == 0) red[tid >> 5] = s;
    __syncthreads();
    if (tid == 0) {
        float t = 0.f;
#pragma unroll
        for (int i = 0; i < 8; i++) t += red[i];
        s_mu = t * (1.0f / H);
    }
    __syncthreads();
    const float mu = s_mu;
    float d0 = x0 - mu, d1 = x1 - mu, d2 = x2 - mu, d3 = x3 - mu;
    float ss = d0 * d0 + d1 * d1 + d2 * d2 + d3 * d3;
#pragma unroll
    for (int o = 16; o; o >>= 1) ss += __shfl_down_sync(0xffffffffu, ss, o);
    __syncthreads();
    if ((tid & 31) == 0) red[tid >> 5] = ss;
    __syncthreads();
    if (tid == 0) {
        float t = 0.f;
#pragma unroll
        for (int i = 0; i < 8; i++) t += red[i];
        s_rstd = rsqrtf(t * (1.0f / H) + 1e-12f);
    }
    __syncthreads();
    const float rstd = s_rstd;

    const float4 g4 = ((const float4*)gam)[tid];
    const float4 b4 = ((const float4*)bet)[tid];
    float4 o;
    o.x = d0 * rstd * g4.x + b4.x;
    o.y = d1 * rstd * g4.y + b4.y;
    o.z = d2 * rstd * g4.z + b4.z;
    o.w = d3 * rstd * g4.w + b4.w;
    ((float4*)(out + (size_t)row * H))[tid] = o;
}

// ---------------------------------------------------------------------------
// Launch
// ---------------------------------------------------------------------------
extern "C" void kernel_launch(void* const* d_in, const int* in_sizes, int n_in,
                              void* d_out, int out_size)
{
    const float* hs   = (const float*)d_in[0];
    const float* Wq   = (const float*)d_in[1];
    const float* bq   = (const float*)d_in[2];
    const float* Wk   = (const float*)d_in[3];
    const float* bk   = (const float*)d_in[4];
    const float* Wv   = (const float*)d_in[5];
    const float* bv   = (const float*)d_in[6];
    const float* ln1g = (const float*)d_in[7];
    const float* ln1b = (const float*)d_in[8];
    const float* W1   = (const float*)d_in[9];
    const float* b1   = (const float*)d_in[10];
    const float* W2   = (const float*)d_in[11];
    const float* b2   = (const float*)d_in[12];
    const float* ln2g = (const float*)d_in[13];
    const float* ln2b = (const float*)d_in[14];
    float* out = (float*)d_out;

    static float *pq = nullptr, *pk = nullptr, *pv = nullptr, *pctx = nullptr,
                 *px = nullptr, *pinter = nullptr, *pffn = nullptr,
                 *pwtq = nullptr, *pwtk = nullptr, *pwtv = nullptr,
                 *pwt1 = nullptr, *pwt2 = nullptr;
    if (!pq) {  // first call is the (uncaptured) correctness run
        cudaGetSymbolAddress((void**)&pq,     g_q);
        cudaGetSymbolAddress((void**)&pk,     g_k);
        cudaGetSymbolAddress((void**)&pv,     g_v);
        cudaGetSymbolAddress((void**)&pctx,   g_ctx);
        cudaGetSymbolAddress((void**)&px,     g_x);
        cudaGetSymbolAddress((void**)&pinter, g_inter);
        cudaGetSymbolAddress((void**)&pffn,   g_ffn);
        cudaGetSymbolAddress((void**)&pwtq,   g_wtq);
        cudaGetSymbolAddress((void**)&pwtk,   g_wtk);
        cudaGetSymbolAddress((void**)&pwtv,   g_wtv);
        cudaGetSymbolAddress((void**)&pwt1,   g_wt1);
        cudaGetSymbolAddress((void**)&pwt2,   g_wt2);
        cudaFuncSetAttribute(attn_kernel,
                             cudaFuncAttributeMaxDynamicSharedMemorySize, ATTN_SMEM);
    }

    // weight transposes (+ tf32 rounding), every replay: ~11us
    transpose_tf32_k<<<dim3(H / 32, H / 32), 256>>>(Wq, pwtq, H, H);
    transpose_tf32_k<<<dim3(H / 32, H / 32), 256>>>(Wk, pwtk, H, H);
    transpose_tf32_k<<<dim3(H / 32, H / 32), 256>>>(Wv, pwtv, H, H);
    transpose_tf32_k<<<dim3(FF / 32, H / 32), 256>>>(W1, pwt1, H, FF);
    transpose_tf32_k<<<dim3(H / 32, FF / 32), 256>>>(W2, pwt2, FF, H);

    // QKV projections (tf32 mma.sync)
    mma_gemm<0><<<dim3(H / 128, BTOK / 128), 256>>>(hs, pwtq, bq, pq, BTOK, H, H);
    mma_gemm<0><<<dim3(H / 128, BTOK / 128), 256>>>(hs, pwtk, bk, pk, BTOK, H, H);
    mma_gemm<0><<<dim3(H / 128, BTOK / 128), 256>>>(hs, pwtv, bv, pv, BTOK, H, H);
    // attention -> ctx (fp32 SIMT)
    attn_kernel<<<dim3(SEQ / 64, 4 * NH), 256, ATTN_SMEM>>>(pq, pk, pv, pctx);
    // residual + LN1 -> x
    add_ln_kernel<<<BTOK, 256>>>(hs, pctx, ln1g, ln1b, px);
    // FFN (tf32 mma.sync)
    mma_gemm<1><<<dim3(FF / 128, BTOK / 128), 256>>>(px, pwt1, b1, pinter, BTOK, FF, H);
    mma_gemm<0><<<dim3(H / 128, BTOK / 128), 256>>>(pinter, pwt2, b2, pffn, BTOK, H, FF);
    // residual + LN2 -> out
    add_ln_kernel<<<BTOK, 256>>>(pffn, px, ln2g, ln2b, out);
}

// round 8
// speedup vs baseline: 2.4901x; 1.4049x over previous
#include <cuda_runtime.h>
#include <math.h>
#include <stdint.h>

#define H    1024
#define NH   16
#define HD   64
#define FF   4096
#define SEQ  2048
#define BTOK 8192   // 4 * 2048 tokens

// ---------------------------------------------------------------------------
// Scratch (static __device__ globals: allocation-free rule)
// ---------------------------------------------------------------------------
__device__ float g_q[BTOK * H];
__device__ float g_k[BTOK * H];
__device__ float g_v[BTOK * H];
__device__ float g_ctx[BTOK * H];
__device__ float g_x[BTOK * H];
__device__ float g_inter[(size_t)BTOK * FF];
__device__ float g_ffn[BTOK * H];
// transposed (tf32-rounded) weights: Wt[n][k] = tf32(W[k][n])
__device__ float g_wtq[H * H];
__device__ float g_wtk[H * H];
__device__ float g_wtv[H * H];
__device__ float g_wt1[(size_t)H * FF];   // [FF][H]
__device__ float g_wt2[(size_t)FF * H];   // [H][FF]

// ---------------------------------------------------------------------------
// Helpers
// ---------------------------------------------------------------------------
__device__ __forceinline__ float tf32r(float x) {
    uint32_t u;
    asm("cvt.rna.tf32.f32 %0, %1;" : "=r"(u) : "f"(x));
    return __uint_as_float(u);
}
__device__ __forceinline__ float gelu_exact(float x) {
    return 0.5f * x * (1.0f + erff(x * 0.70710678118654752f));
}

#define MMA_TF32(ACC, A0, A1, A2, A3, B0, B1)                                  \
    asm volatile(                                                              \
        "mma.sync.aligned.m16n8k8.row.col.f32.tf32.tf32.f32 "                  \
        "{%0,%1,%2,%3}, {%4,%5,%6,%7}, {%8,%9}, {%0,%1,%2,%3};"                \
        : "+f"((ACC)[0]), "+f"((ACC)[1]), "+f"((ACC)[2]), "+f"((ACC)[3])       \
        : "r"(A0), "r"(A1), "r"(A2), "r"(A3), "r"(B0), "r"(B1))

// ---------------------------------------------------------------------------
// Weight transpose + tf32 rounding: W[K][N] -> Wt[N][K]
// ---------------------------------------------------------------------------
__global__ __launch_bounds__(256)
void transpose_tf32_k(const float* __restrict__ W, float* __restrict__ Wt,
                      int K, int N)
{
    __shared__ float t[32][33];
    const int tx = threadIdx.x & 31;
    const int ty = threadIdx.x >> 5;   // 0..7
    const int n0 = blockIdx.x * 32;
    const int k0 = blockIdx.y * 32;
#pragma unroll
    for (int i = 0; i < 4; i++) {
        int r = ty + i * 8;
        t[r][tx] = tf32r(W[(size_t)(k0 + r) * N + n0 + tx]);
    }
    __syncthreads();
#pragma unroll
    for (int i = 0; i < 4; i++) {
        int r = ty + i * 8;
        Wt[(size_t)(n0 + r) * K + k0 + tx] = t[tx][r];
    }
}

// ---------------------------------------------------------------------------
// TF32 tensor-core GEMM via mma.sync.m16n8k8 (unchanged from R6 — proven).
// ---------------------------------------------------------------------------
#define BM 128
#define BN 128
#define BKG 16
#define PADK 20

template <int EPI>  // 0: +bias   1: gelu(+bias)+clamp
__global__ __launch_bounds__(256)
void mma_gemm(const float* __restrict__ A, const float* __restrict__ Bt,
              const float* __restrict__ bias, float* __restrict__ C,
              int M, int N, int K)
{
    __shared__ float As[2][BM][PADK];
    __shared__ float Bs[2][BN][PADK];

    const int tid  = threadIdx.x;
    const int lane = tid & 31;
    const int wid  = tid >> 5;
    const int wm0  = (wid >> 1) * 32;   // 0,32,64,96
    const int wn0  = (wid & 1) * 64;    // 0,64
    const int r    = lane >> 2;         // 0..7
    const int c    = lane & 3;          // 0..3

    const int row0 = blockIdx.y * BM;
    const int col0 = blockIdx.x * BN;

    const int ldr = tid >> 2;           // 0..63
    const int ldc = (tid & 3) * 4;      // 0,4,8,12

    const float* Ap = A  + (size_t)(row0 + ldr) * K + ldc;
    const float* Bp = Bt + (size_t)(col0 + ldr) * K + ldc;
    const size_t stride64 = (size_t)64 * K;

    float acc[2][8][4];
#pragma unroll
    for (int mt = 0; mt < 2; mt++)
#pragma unroll
        for (int nt = 0; nt < 8; nt++)
#pragma unroll
            for (int u = 0; u < 4; u++) acc[mt][nt][u] = 0.0f;

    float4 ra0, ra1, rb0, rb1;

    ra0 = *(const float4*)(Ap);
    ra1 = *(const float4*)(Ap + stride64);
    rb0 = *(const float4*)(Bp);
    rb1 = *(const float4*)(Bp + stride64);
    {
        float4 t0 = make_float4(tf32r(ra0.x), tf32r(ra0.y), tf32r(ra0.z), tf32r(ra0.w));
        float4 t1 = make_float4(tf32r(ra1.x), tf32r(ra1.y), tf32r(ra1.z), tf32r(ra1.w));
        *(float4*)&As[0][ldr][ldc]      = t0;
        *(float4*)&As[0][ldr + 64][ldc] = t1;
        *(float4*)&Bs[0][ldr][ldc]      = rb0;
        *(float4*)&Bs[0][ldr + 64][ldc] = rb1;
    }
    __syncthreads();

    const int NS = K / BKG;
    for (int s = 0; s < NS; s++) {
        const int cur = s & 1;
        if (s + 1 < NS) {
            const int k0 = (s + 1) * BKG;
            ra0 = *(const float4*)(Ap + k0);
            ra1 = *(const float4*)(Ap + stride64 + k0);
            rb0 = *(const float4*)(Bp + k0);
            rb1 = *(const float4*)(Bp + stride64 + k0);
        }

#pragma unroll
        for (int ks = 0; ks < 2; ks++) {
            const int k = ks * 8;
            uint32_t af[2][4];
#pragma unroll
            for (int mt = 0; mt < 2; mt++) {
                const int m = wm0 + mt * 16 + r;
                af[mt][0] = __float_as_uint(As[cur][m][k + c]);
                af[mt][1] = __float_as_uint(As[cur][m + 8][k + c]);
                af[mt][2] = __float_as_uint(As[cur][m][k + c + 4]);
                af[mt][3] = __float_as_uint(As[cur][m + 8][k + c + 4]);
            }
#pragma unroll
            for (int nt = 0; nt < 8; nt++) {
                const int n = wn0 + nt * 8 + r;
                const uint32_t b0 = __float_as_uint(Bs[cur][n][k + c]);
                const uint32_t b1 = __float_as_uint(Bs[cur][n][k + c + 4]);
                MMA_TF32(acc[0][nt], af[0][0], af[0][1], af[0][2], af[0][3], b0, b1);
                MMA_TF32(acc[1][nt], af[1][0], af[1][1], af[1][2], af[1][3], b0, b1);
            }
        }

        if (s + 1 < NS) {
            const int nxt = (s + 1) & 1;
            float4 t0 = make_float4(tf32r(ra0.x), tf32r(ra0.y), tf32r(ra0.z), tf32r(ra0.w));
            float4 t1 = make_float4(tf32r(ra1.x), tf32r(ra1.y), tf32r(ra1.z), tf32r(ra1.w));
            *(float4*)&As[nxt][ldr][ldc]      = t0;
            *(float4*)&As[nxt][ldr + 64][ldc] = t1;
            *(float4*)&Bs[nxt][ldr][ldc]      = rb0;
            *(float4*)&Bs[nxt][ldr + 64][ldc] = rb1;
        }
        __syncthreads();
    }

#pragma unroll
    for (int mt = 0; mt < 2; mt++) {
        const int rowA = row0 + wm0 + mt * 16 + r;
#pragma unroll
        for (int nt = 0; nt < 8; nt++) {
            const int col = col0 + wn0 + nt * 8 + 2 * c;
            const float bz0 = bias[col];
            const float bz1 = bias[col + 1];
            float v0 = acc[mt][nt][0] + bz0;
            float v1 = acc[mt][nt][1] + bz1;
            float v2 = acc[mt][nt][2] + bz0;
            float v3 = acc[mt][nt][3] + bz1;
            if (EPI == 1) {
                v0 = fminf(fmaxf(gelu_exact(v0), -1e9f), 1e9f);
                v1 = fminf(fmaxf(gelu_exact(v1), -1e9f), 1e9f);
                v2 = fminf(fmaxf(gelu_exact(v2), -1e9f), 1e9f);
                v3 = fminf(fmaxf(gelu_exact(v3), -1e9f), 1e9f);
            }
            *(float2*)(C + (size_t)rowA * N + col)       = make_float2(v0, v1);
            *(float2*)(C + (size_t)(rowA + 8) * N + col) = make_float2(v2, v3);
        }
    }
}

// ---------------------------------------------------------------------------
// Flash attention on tensor cores (mma.sync tf32).
// Block: 64 queries of one (b,h); 256 threads = 8 warps (4 qm x 2 n-half).
// S = Q K^T via mma (A=Qs[q][d], B=Ks[kv][d]); softmax fp32 (4 threads/row);
// O = P V via mma (A=Ss[q][kv] tf32-rounded probs, B=Vt[d][kv]).
// All tiles stride 68: fragment gather r*68+c == r*4+c (mod 32) -> conflict-free.
// ---------------------------------------------------------------------------
#define APAD 68
#define ATILE (64 * APAD)
// Qs,Ks,Vt,Ss + m,l,sc + sv_red[4][64] + sv
#define ATTN_SMEM ((4 * ATILE + 3 * 64 + 256 + 64) * 4)

__global__ __launch_bounds__(256)
void attn_mma_kernel(const float* __restrict__ Q, const float* __restrict__ K,
                     const float* __restrict__ V, float* __restrict__ O)
{
    extern __shared__ float smf[];
    float* Qs    = smf;                   // [q][d]
    float* Ks    = smf + ATILE;           // [kv][d]
    float* Vt    = smf + 2 * ATILE;       // [d][kv]
    float* Ss    = smf + 3 * ATILE;       // [q][kv] scores/probs
    float* m_s   = smf + 4 * ATILE;
    float* l_s   = m_s + 64;
    float* sc_s  = l_s + 64;
    float* svr   = sc_s + 64;             // [4][64] partial colsum(V)
    float* sv_s  = svr + 256;             // [64] final 1e-9*colsum

    const int tid  = threadIdx.x;
    const int lane = tid & 31;
    const int wid  = tid >> 5;
    const int wq0  = (wid >> 1) * 16;     // 0,16,32,48
    const int wn0  = (wid & 1) * 32;      // 0,32
    const int r    = lane >> 2;           // 0..7
    const int c    = lane & 3;            // 0..3

    const int bh = blockIdx.y;
    const int b  = bh >> 4;
    const int h  = bh & 15;
    const int qstart = blockIdx.x * 64;
    const size_t base = (size_t)b * SEQ * H + (size_t)h * HD;

    // load Q tile (tf32-rounded)
#pragma unroll
    for (int it = 0; it < 16; it++) {
        int idx = tid + it * 256;
        int qr = idx >> 6, qc = idx & 63;
        Qs[qr * APAD + qc] = tf32r(Q[base + (size_t)(qstart + qr) * H + qc]);
    }
    if (tid < 64) { m_s[tid] = -1e30f; l_s[tid] = 0.0f; }

    float oacc[4][4];
#pragma unroll
    for (int nt = 0; nt < 4; nt++)
#pragma unroll
        for (int u = 0; u < 4; u++) oacc[nt][u] = 0.0f;
    float sv_local = 0.0f;                // colsum(V) partial; d = tid&63 fixed

    __syncthreads();

    for (int kt = 0; kt < SEQ / 64; kt++) {
        const int kstart = kt * 64;
        // stage K (natural) and V (transposed), tf32-rounded
#pragma unroll
        for (int it = 0; it < 16; it++) {
            int idx = tid + it * 256;
            int rr = idx >> 6, cc = idx & 63;
            size_t gi = base + (size_t)(kstart + rr) * H + cc;
            Ks[rr * APAD + cc] = tf32r(K[gi]);
            float vr = tf32r(V[gi]);
            Vt[cc * APAD + rr] = vr;
            sv_local += vr;
        }
        __syncthreads();

        // ---- S = Q K^T (warp tile 16q x 32kv) ----
        float sacc[4][4];
#pragma unroll
        for (int nt = 0; nt < 4; nt++)
#pragma unroll
            for (int u = 0; u < 4; u++) sacc[nt][u] = 0.0f;

#pragma unroll
        for (int ks = 0; ks < 8; ks++) {
            const int k = ks * 8;
            const int m = wq0 + r;
            const uint32_t a0 = __float_as_uint(Qs[m * APAD + k + c]);
            const uint32_t a1 = __float_as_uint(Qs[(m + 8) * APAD + k + c]);
            const uint32_t a2 = __float_as_uint(Qs[m * APAD + k + c + 4]);
            const uint32_t a3 = __float_as_uint(Qs[(m + 8) * APAD + k + c + 4]);
#pragma unroll
            for (int nt = 0; nt < 4; nt++) {
                const int n = wn0 + nt * 8 + r;
                const uint32_t b0 = __float_as_uint(Ks[n * APAD + k + c]);
                const uint32_t b1 = __float_as_uint(Ks[n * APAD + k + c + 4]);
                MMA_TF32(sacc[nt], a0, a1, a2, a3, b0, b1);
            }
        }
        // scale + clamp, stage to Ss
#pragma unroll
        for (int nt = 0; nt < 4; nt++) {
            const int col = wn0 + nt * 8 + 2 * c;
            const int row = wq0 + r;
            float v0 = fminf(fmaxf(sacc[nt][0] * 0.125f, -1e9f), 1e9f);
            float v1 = fminf(fmaxf(sacc[nt][1] * 0.125f, -1e9f), 1e9f);
            float v2 = fminf(fmaxf(sacc[nt][2] * 0.125f, -1e9f), 1e9f);
            float v3 = fminf(fmaxf(sacc[nt][3] * 0.125f, -1e9f), 1e9f);
            *(float2*)&Ss[row * APAD + col]       = make_float2(v0, v1);
            *(float2*)&Ss[(row + 8) * APAD + col] = make_float2(v2, v3);
        }
        __syncthreads();

        // ---- online softmax: 4 threads per row, strided (conflict-free) ----
        {
            const int row = tid >> 2;
            const int p   = tid & 3;
            float* srow = &Ss[row * APAD];
            float mt = -1e30f;
#pragma unroll
            for (int j = 0; j < 16; j++) mt = fmaxf(mt, srow[p + 4 * j]);
            mt = fmaxf(mt, __shfl_xor_sync(0xffffffffu, mt, 1));
            mt = fmaxf(mt, __shfl_xor_sync(0xffffffffu, mt, 2));
            const float mo = m_s[row];
            mt = fmaxf(mt, mo);
            float sum = 0.0f;
#pragma unroll
            for (int j = 0; j < 16; j++) {
                float e = __expf(srow[p + 4 * j] - mt);
                srow[p + 4 * j] = tf32r(e);
                sum += e;
            }
            sum += __shfl_xor_sync(0xffffffffu, sum, 1);
            sum += __shfl_xor_sync(0xffffffffu, sum, 2);
            if (p == 0) {
                const float sc = __expf(mo - mt);
                m_s[row]  = mt;
                l_s[row]  = l_s[row] * sc + sum;
                sc_s[row] = sc;
            }
        }
        __syncthreads();

        // rescale accumulators
        {
            const float sc0 = sc_s[wq0 + r];
            const float sc1 = sc_s[wq0 + r + 8];
#pragma unroll
            for (int nt = 0; nt < 4; nt++) {
                oacc[nt][0] *= sc0; oacc[nt][1] *= sc0;
                oacc[nt][2] *= sc1; oacc[nt][3] *= sc1;
            }
        }

        // ---- O += P V (warp tile 16q x 32d) ----
#pragma unroll
        for (int ks = 0; ks < 8; ks++) {
            const int k = ks * 8;
            const int m = wq0 + r;
            const uint32_t a0 = __float_as_uint(Ss[m * APAD + k + c]);
            const uint32_t a1 = __float_as_uint(Ss[(m + 8) * APAD + k + c]);
            const uint32_t a2 = __float_as_uint(Ss[m * APAD + k + c + 4]);
            const uint32_t a3 = __float_as_uint(Ss[(m + 8) * APAD + k + c + 4]);
#pragma unroll
            for (int nt = 0; nt < 4; nt++) {
                const int n = wn0 + nt * 8 + r;
                const uint32_t b0 = __float_as_uint(Vt[n * APAD + k + c]);
                const uint32_t b1 = __float_as_uint(Vt[n * APAD + k + c + 4]);
                MMA_TF32(oacc[nt], a0, a1, a2, a3, b0, b1);
            }
        }
        __syncthreads();
    }

    // reduce colsum(V): 4 partials per d
    svr[(tid >> 6) * 64 + (tid & 63)] = sv_local;
    __syncthreads();
    if (tid < 64)
        sv_s[tid] = 1e-9f * (svr[tid] + svr[64 + tid] + svr[128 + tid] + svr[192 + tid]);
    __syncthreads();

    // epilogue
    {
        const float linv0 = 1.0f / l_s[wq0 + r];
        const float linv1 = 1.0f / l_s[wq0 + r + 8];
        const int row = qstart + wq0 + r;
#pragma unroll
        for (int nt = 0; nt < 4; nt++) {
            const int col = wn0 + nt * 8 + 2 * c;
            const float e0 = sv_s[col], e1 = sv_s[col + 1];
            float2 o0 = make_float2(oacc[nt][0] * linv0 + e0,
                                    oacc[nt][1] * linv0 + e1);
            float2 o1 = make_float2(oacc[nt][2] * linv1 + e0,
                                    oacc[nt][3] * linv1 + e1);
            *(float2*)&O[base + (size_t)row * H + col]       = o0;
            *(float2*)&O[base + (size_t)(row + 8) * H + col] = o1;
        }
    }
}

// ---------------------------------------------------------------------------
// Fused residual-add + LayerNorm (unchanged).
// ---------------------------------------------------------------------------
__global__ __launch_bounds__(256)
void add_ln_kernel(const float* __restrict__ A, const float* __restrict__ Bres,
                   const float* __restrict__ gam, const float* __restrict__ bet,
                   float* __restrict__ out)
{
    const int row = blockIdx.x;
    const int tid = threadIdx.x;
    const float4 va = ((const float4*)(A    + (size_t)row * H))[tid];
    const float4 vb = ((const float4*)(Bres + (size_t)row * H))[tid];
    float x0 = va.x + vb.x, x1 = va.y + vb.y, x2 = va.z + vb.z, x3 = va.w + vb.w;

    __shared__ float red[8];
    __shared__ float s_mu, s_rstd;

    float s = x0 + x1 + x2 + x3;
#pragma unroll
    for (int o = 16; o; o >>= 1) s += __shfl_down_sync(0xffffffffu, s, o);
    if ((tid & 31) == 0) red[tid >> 5] = s;
    __syncthreads();
    if (tid == 0) {
        float t = 0.f;
#pragma unroll
        for (int i = 0; i < 8; i++) t += red[i];
        s_mu = t * (1.0f / H);
    }
    __syncthreads();
    const float mu = s_mu;
    float d0 = x0 - mu, d1 = x1 - mu, d2 = x2 - mu, d3 = x3 - mu;
    float ss = d0 * d0 + d1 * d1 + d2 * d2 + d3 * d3;
#pragma unroll
    for (int o = 16; o; o >>= 1) ss += __shfl_down_sync(0xffffffffu, ss, o);
    __syncthreads();
    if ((tid & 31) == 0) red[tid >> 5] = ss;
    __syncthreads();
    if (tid == 0) {
        float t = 0.f;
#pragma unroll
        for (int i = 0; i < 8; i++) t += red[i];
        s_rstd = rsqrtf(t * (1.0f / H) + 1e-12f);
    }
    __syncthreads();
    const float rstd = s_rstd;

    const float4 g4 = ((const float4*)gam)[tid];
    const float4 b4 = ((const float4*)bet)[tid];
    float4 o;
    o.x = d0 * rstd * g4.x + b4.x;
    o.y = d1 * rstd * g4.y + b4.y;
    o.z = d2 * rstd * g4.z + b4.z;
    o.w = d3 * rstd * g4.w + b4.w;
    ((float4*)(out + (size_t)row * H))[tid] = o;
}

// ---------------------------------------------------------------------------
// Launch
// ---------------------------------------------------------------------------
extern "C" void kernel_launch(void* const* d_in, const int* in_sizes, int n_in,
                              void* d_out, int out_size)
{
    const float* hs   = (const float*)d_in[0];
    const float* Wq   = (const float*)d_in[1];
    const float* bq   = (const float*)d_in[2];
    const float* Wk   = (const float*)d_in[3];
    const float* bk   = (const float*)d_in[4];
    const float* Wv   = (const float*)d_in[5];
    const float* bv   = (const float*)d_in[6];
    const float* ln1g = (const float*)d_in[7];
    const float* ln1b = (const float*)d_in[8];
    const float* W1   = (const float*)d_in[9];
    const float* b1   = (const float*)d_in[10];
    const float* W2   = (const float*)d_in[11];
    const float* b2   = (const float*)d_in[12];
    const float* ln2g = (const float*)d_in[13];
    const float* ln2b = (const float*)d_in[14];
    float* out = (float*)d_out;

    static float *pq = nullptr, *pk = nullptr, *pv = nullptr, *pctx = nullptr,
                 *px = nullptr, *pinter = nullptr, *pffn = nullptr,
                 *pwtq = nullptr, *pwtk = nullptr, *pwtv = nullptr,
                 *pwt1 = nullptr, *pwt2 = nullptr;
    if (!pq) {  // first call is the (uncaptured) correctness run
        cudaGetSymbolAddress((void**)&pq,     g_q);
        cudaGetSymbolAddress((void**)&pk,     g_k);
        cudaGetSymbolAddress((void**)&pv,     g_v);
        cudaGetSymbolAddress((void**)&pctx,   g_ctx);
        cudaGetSymbolAddress((void**)&px,     g_x);
        cudaGetSymbolAddress((void**)&pinter, g_inter);
        cudaGetSymbolAddress((void**)&pffn,   g_ffn);
        cudaGetSymbolAddress((void**)&pwtq,   g_wtq);
        cudaGetSymbolAddress((void**)&pwtk,   g_wtk);
        cudaGetSymbolAddress((void**)&pwtv,   g_wtv);
        cudaGetSymbolAddress((void**)&pwt1,   g_wt1);
        cudaGetSymbolAddress((void**)&pwt2,   g_wt2);
        cudaFuncSetAttribute(attn_mma_kernel,
                             cudaFuncAttributeMaxDynamicSharedMemorySize, ATTN_SMEM);
    }

    // weight transposes (+ tf32 rounding), every replay: ~45us
    transpose_tf32_k<<<dim3(H / 32, H / 32), 256>>>(Wq, pwtq, H, H);
    transpose_tf32_k<<<dim3(H / 32, H / 32), 256>>>(Wk, pwtk, H, H);
    transpose_tf32_k<<<dim3(H / 32, H / 32), 256>>>(Wv, pwtv, H, H);
    transpose_tf32_k<<<dim3(FF / 32, H / 32), 256>>>(W1, pwt1, H, FF);
    transpose_tf32_k<<<dim3(H / 32, FF / 32), 256>>>(W2, pwt2, FF, H);

    // QKV projections (tf32 mma.sync)
    mma_gemm<0><<<dim3(H / 128, BTOK / 128), 256>>>(hs, pwtq, bq, pq, BTOK, H, H);
    mma_gemm<0><<<dim3(H / 128, BTOK / 128), 256>>>(hs, pwtk, bk, pk, BTOK, H, H);
    mma_gemm<0><<<dim3(H / 128, BTOK / 128), 256>>>(hs, pwtv, bv, pv, BTOK, H, H);
    // attention -> ctx (tf32 mma.sync flash)
    attn_mma_kernel<<<dim3(SEQ / 64, 4 * NH), 256, ATTN_SMEM>>>(pq, pk, pv, pctx);
    // residual + LN1 -> x
    add_ln_kernel<<<BTOK, 256>>>(hs, pctx, ln1g, ln1b, px);
    // FFN (tf32 mma.sync)
    mma_gemm<1><<<dim3(FF / 128, BTOK / 128), 256>>>(px, pwt1, b1, pinter, BTOK, FF, H);
    mma_gemm<0><<<dim3(H / 128, BTOK / 128), 256>>>(pinter, pwt2, b2, pffn, BTOK, H, FF);
    // residual + LN2 -> out
    add_ln_kernel<<<BTOK, 256>>>(pffn, px, ln2g, ln2b, out);
}

// round 9
// speedup vs baseline: 2.4907x; 1.0002x over previous
#include <cuda_runtime.h>
#include <math.h>
#include <stdint.h>

#define H    1024
#define NH   16
#define HD   64
#define FF   4096
#define SEQ  2048
#define BTOK 8192   // 4 * 2048 tokens

// ---------------------------------------------------------------------------
// Scratch (static __device__ globals: allocation-free rule)
// ---------------------------------------------------------------------------
__device__ float g_q[BTOK * H];
__device__ float g_k[BTOK * H];
__device__ float g_v[BTOK * H];
__device__ float g_ctx[BTOK * H];
__device__ float g_x[BTOK * H];
__device__ float g_inter[(size_t)BTOK * FF];
__device__ float g_ffn[BTOK * H];
// transposed (tf32-rounded) weights: Wt[n][k] = tf32(W[k][n])
__device__ float g_wtq[H * H];
__device__ float g_wtk[H * H];
__device__ float g_wtv[H * H];
__device__ float g_wt1[(size_t)H * FF];   // [FF][H]
__device__ float g_wt2[(size_t)FF * H];   // [H][FF]

// ---------------------------------------------------------------------------
// Helpers
// ---------------------------------------------------------------------------
__device__ __forceinline__ float tf32r(float x) {
    uint32_t u;
    asm("cvt.rna.tf32.f32 %0, %1;" : "=r"(u) : "f"(x));
    return __uint_as_float(u);
}
__device__ __forceinline__ float gelu_exact(float x) {
    return 0.5f * x * (1.0f + erff(x * 0.70710678118654752f));
}

#define MMA_TF32(ACC, A0, A1, A2, A3, B0, B1)                                  \
    asm volatile(                                                              \
        "mma.sync.aligned.m16n8k8.row.col.f32.tf32.tf32.f32 "                  \
        "{%0,%1,%2,%3}, {%4,%5,%6,%7}, {%8,%9}, {%0,%1,%2,%3};"                \
        : "+f"((ACC)[0]), "+f"((ACC)[1]), "+f"((ACC)[2]), "+f"((ACC)[3])       \
        : "r"(A0), "r"(A1), "r"(A2), "r"(A3), "r"(B0), "r"(B1))

// ---------------------------------------------------------------------------
// Weight transpose + tf32 rounding: W[K][N] -> Wt[N][K]
// ---------------------------------------------------------------------------
__global__ __launch_bounds__(256)
void transpose_tf32_k(const float* __restrict__ W, float* __restrict__ Wt,
                      int K, int N)
{
    __shared__ float t[32][33];
    const int tx = threadIdx.x & 31;
    const int ty = threadIdx.x >> 5;   // 0..7
    const int n0 = blockIdx.x * 32;
    const int k0 = blockIdx.y * 32;
#pragma unroll
    for (int i = 0; i < 4; i++) {
        int r = ty + i * 8;
        t[r][tx] = tf32r(W[(size_t)(k0 + r) * N + n0 + tx]);
    }
    __syncthreads();
#pragma unroll
    for (int i = 0; i < 4; i++) {
        int r = ty + i * 8;
        Wt[(size_t)(n0 + r) * K + k0 + tx] = t[tx][r];
    }
}

// ---------------------------------------------------------------------------
// TF32 tensor-core GEMM via mma.sync.m16n8k8 (unchanged from R6 — proven).
// ---------------------------------------------------------------------------
#define BM 128
#define BN 128
#define BKG 16
#define PADK 20

template <int EPI>  // 0: +bias   1: gelu(+bias)+clamp
__global__ __launch_bounds__(256)
void mma_gemm(const float* __restrict__ A, const float* __restrict__ Bt,
              const float* __restrict__ bias, float* __restrict__ C,
              int M, int N, int K)
{
    __shared__ float As[2][BM][PADK];
    __shared__ float Bs[2][BN][PADK];

    const int tid  = threadIdx.x;
    const int lane = tid & 31;
    const int wid  = tid >> 5;
    const int wm0  = (wid >> 1) * 32;   // 0,32,64,96
    const int wn0  = (wid & 1) * 64;    // 0,64
    const int r    = lane >> 2;         // 0..7
    const int c    = lane & 3;          // 0..3

    const int row0 = blockIdx.y * BM;
    const int col0 = blockIdx.x * BN;

    const int ldr = tid >> 2;           // 0..63
    const int ldc = (tid & 3) * 4;      // 0,4,8,12

    const float* Ap = A  + (size_t)(row0 + ldr) * K + ldc;
    const float* Bp = Bt + (size_t)(col0 + ldr) * K + ldc;
    const size_t stride64 = (size_t)64 * K;

    float acc[2][8][4];
#pragma unroll
    for (int mt = 0; mt < 2; mt++)
#pragma unroll
        for (int nt = 0; nt < 8; nt++)
#pragma unroll
            for (int u = 0; u < 4; u++) acc[mt][nt][u] = 0.0f;

    float4 ra0, ra1, rb0, rb1;

    ra0 = *(const float4*)(Ap);
    ra1 = *(const float4*)(Ap + stride64);
    rb0 = *(const float4*)(Bp);
    rb1 = *(const float4*)(Bp + stride64);
    {
        float4 t0 = make_float4(tf32r(ra0.x), tf32r(ra0.y), tf32r(ra0.z), tf32r(ra0.w));
        float4 t1 = make_float4(tf32r(ra1.x), tf32r(ra1.y), tf32r(ra1.z), tf32r(ra1.w));
        *(float4*)&As[0][ldr][ldc]      = t0;
        *(float4*)&As[0][ldr + 64][ldc] = t1;
        *(float4*)&Bs[0][ldr][ldc]      = rb0;
        *(float4*)&Bs[0][ldr + 64][ldc] = rb1;
    }
    __syncthreads();

    const int NS = K / BKG;
    for (int s = 0; s < NS; s++) {
        const int cur = s & 1;
        if (s + 1 < NS) {
            const int k0 = (s + 1) * BKG;
            ra0 = *(const float4*)(Ap + k0);
            ra1 = *(const float4*)(Ap + stride64 + k0);
            rb0 = *(const float4*)(Bp + k0);
            rb1 = *(const float4*)(Bp + stride64 + k0);
        }

#pragma unroll
        for (int ks = 0; ks < 2; ks++) {
            const int k = ks * 8;
            uint32_t af[2][4];
#pragma unroll
            for (int mt = 0; mt < 2; mt++) {
                const int m = wm0 + mt * 16 + r;
                af[mt][0] = __float_as_uint(As[cur][m][k + c]);
                af[mt][1] = __float_as_uint(As[cur][m + 8][k + c]);
                af[mt][2] = __float_as_uint(As[cur][m][k + c + 4]);
                af[mt][3] = __float_as_uint(As[cur][m + 8][k + c + 4]);
            }
#pragma unroll
            for (int nt = 0; nt < 8; nt++) {
                const int n = wn0 + nt * 8 + r;
                const uint32_t b0 = __float_as_uint(Bs[cur][n][k + c]);
                const uint32_t b1 = __float_as_uint(Bs[cur][n][k + c + 4]);
                MMA_TF32(acc[0][nt], af[0][0], af[0][1], af[0][2], af[0][3], b0, b1);
                MMA_TF32(acc[1][nt], af[1][0], af[1][1], af[1][2], af[1][3], b0, b1);
            }
        }

        if (s + 1 < NS) {
            const int nxt = (s + 1) & 1;
            float4 t0 = make_float4(tf32r(ra0.x), tf32r(ra0.y), tf32r(ra0.z), tf32r(ra0.w));
            float4 t1 = make_float4(tf32r(ra1.x), tf32r(ra1.y), tf32r(ra1.z), tf32r(ra1.w));
            *(float4*)&As[nxt][ldr][ldc]      = t0;
            *(float4*)&As[nxt][ldr + 64][ldc] = t1;
            *(float4*)&Bs[nxt][ldr][ldc]      = rb0;
            *(float4*)&Bs[nxt][ldr + 64][ldc] = rb1;
        }
        __syncthreads();
    }

#pragma unroll
    for (int mt = 0; mt < 2; mt++) {
        const int rowA = row0 + wm0 + mt * 16 + r;
#pragma unroll
        for (int nt = 0; nt < 8; nt++) {
            const int col = col0 + wn0 + nt * 8 + 2 * c;
            const float bz0 = bias[col];
            const float bz1 = bias[col + 1];
            float v0 = acc[mt][nt][0] + bz0;
            float v1 = acc[mt][nt][1] + bz1;
            float v2 = acc[mt][nt][2] + bz0;
            float v3 = acc[mt][nt][3] + bz1;
            if (EPI == 1) {
                v0 = fminf(fmaxf(gelu_exact(v0), -1e9f), 1e9f);
                v1 = fminf(fmaxf(gelu_exact(v1), -1e9f), 1e9f);
                v2 = fminf(fmaxf(gelu_exact(v2), -1e9f), 1e9f);
                v3 = fminf(fmaxf(gelu_exact(v3), -1e9f), 1e9f);
            }
            *(float2*)(C + (size_t)rowA * N + col)       = make_float2(v0, v1);
            *(float2*)(C + (size_t)(rowA + 8) * N + col) = make_float2(v2, v3);
        }
    }
}

// ---------------------------------------------------------------------------
// Flash attention on tensor cores (mma.sync tf32).
// Block: 64 queries of one (b,h); 256 threads = 8 warps (4 qm x 2 n-half).
// S = Q K^T via mma (A=Qs[q][d], B=Ks[kv][d]); softmax fp32 (4 threads/row);
// O = P V via mma (A=Ss[q][kv] tf32-rounded probs, B=Vt[d][kv]).
// All tiles stride 68: fragment gather r*68+c == r*4+c (mod 32) -> conflict-free.
// ---------------------------------------------------------------------------
#define APAD 68
#define ATILE (64 * APAD)
// Qs,Ks,Vt,Ss + m,l,sc + sv_red[4][64] + sv
#define ATTN_SMEM ((4 * ATILE + 3 * 64 + 256 + 64) * 4)

__global__ __launch_bounds__(256)
void attn_mma_kernel(const float* __restrict__ Q, const float* __restrict__ K,
                     const float* __restrict__ V, float* __restrict__ O)
{
    extern __shared__ float smf[];
    float* Qs    = smf;                   // [q][d]
    float* Ks    = smf + ATILE;           // [kv][d]
    float* Vt    = smf + 2 * ATILE;       // [d][kv]
    float* Ss    = smf + 3 * ATILE;       // [q][kv] scores/probs
    float* m_s   = smf + 4 * ATILE;
    float* l_s   = m_s + 64;
    float* sc_s  = l_s + 64;
    float* svr   = sc_s + 64;             // [4][64] partial colsum(V)
    float* sv_s  = svr + 256;             // [64] final 1e-9*colsum

    const int tid  = threadIdx.x;
    const int lane = tid & 31;
    const int wid  = tid >> 5;
    const int wq0  = (wid >> 1) * 16;     // 0,16,32,48
    const int wn0  = (wid & 1) * 32;      // 0,32
    const int r    = lane >> 2;           // 0..7
    const int c    = lane & 3;            // 0..3

    const int bh = blockIdx.y;
    const int b  = bh >> 4;
    const int h  = bh & 15;
    const int qstart = blockIdx.x * 64;
    const size_t base = (size_t)b * SEQ * H + (size_t)h * HD;

    // load Q tile (tf32-rounded)
#pragma unroll
    for (int it = 0; it < 16; it++) {
        int idx = tid + it * 256;
        int qr = idx >> 6, qc = idx & 63;
        Qs[qr * APAD + qc] = tf32r(Q[base + (size_t)(qstart + qr) * H + qc]);
    }
    if (tid < 64) { m_s[tid] = -1e30f; l_s[tid] = 0.0f; }

    float oacc[4][4];
#pragma unroll
    for (int nt = 0; nt < 4; nt++)
#pragma unroll
        for (int u = 0; u < 4; u++) oacc[nt][u] = 0.0f;
    float sv_local = 0.0f;                // colsum(V) partial; d = tid&63 fixed

    __syncthreads();

    for (int kt = 0; kt < SEQ / 64; kt++) {
        const int kstart = kt * 64;
        // stage K (natural) and V (transposed), tf32-rounded
#pragma unroll
        for (int it = 0; it < 16; it++) {
            int idx = tid + it * 256;
            int rr = idx >> 6, cc = idx & 63;
            size_t gi = base + (size_t)(kstart + rr) * H + cc;
            Ks[rr * APAD + cc] = tf32r(K[gi]);
            float vr = tf32r(V[gi]);
            Vt[cc * APAD + rr] = vr;
            sv_local += vr;
        }
        __syncthreads();

        // ---- S = Q K^T (warp tile 16q x 32kv) ----
        float sacc[4][4];
#pragma unroll
        for (int nt = 0; nt < 4; nt++)
#pragma unroll
            for (int u = 0; u < 4; u++) sacc[nt][u] = 0.0f;

#pragma unroll
        for (int ks = 0; ks < 8; ks++) {
            const int k = ks * 8;
            const int m = wq0 + r;
            const uint32_t a0 = __float_as_uint(Qs[m * APAD + k + c]);
            const uint32_t a1 = __float_as_uint(Qs[(m + 8) * APAD + k + c]);
            const uint32_t a2 = __float_as_uint(Qs[m * APAD + k + c + 4]);
            const uint32_t a3 = __float_as_uint(Qs[(m + 8) * APAD + k + c + 4]);
#pragma unroll
            for (int nt = 0; nt < 4; nt++) {
                const int n = wn0 + nt * 8 + r;
                const uint32_t b0 = __float_as_uint(Ks[n * APAD + k + c]);
                const uint32_t b1 = __float_as_uint(Ks[n * APAD + k + c + 4]);
                MMA_TF32(sacc[nt], a0, a1, a2, a3, b0, b1);
            }
        }
        // scale + clamp, stage to Ss
#pragma unroll
        for (int nt = 0; nt < 4; nt++) {
            const int col = wn0 + nt * 8 + 2 * c;
            const int row = wq0 + r;
            float v0 = fminf(fmaxf(sacc[nt][0] * 0.125f, -1e9f), 1e9f);
            float v1 = fminf(fmaxf(sacc[nt][1] * 0.125f, -1e9f), 1e9f);
            float v2 = fminf(fmaxf(sacc[nt][2] * 0.125f, -1e9f), 1e9f);
            float v3 = fminf(fmaxf(sacc[nt][3] * 0.125f, -1e9f), 1e9f);
            *(float2*)&Ss[row * APAD + col]       = make_float2(v0, v1);
            *(float2*)&Ss[(row + 8) * APAD + col] = make_float2(v2, v3);
        }
        __syncthreads();

        // ---- online softmax: 4 threads per row, strided (conflict-free) ----
        {
            const int row = tid >> 2;
            const int p   = tid & 3;
            float* srow = &Ss[row * APAD];
            float mt = -1e30f;
#pragma unroll
            for (int j = 0; j < 16; j++) mt = fmaxf(mt, srow[p + 4 * j]);
            mt = fmaxf(mt, __shfl_xor_sync(0xffffffffu, mt, 1));
            mt = fmaxf(mt, __shfl_xor_sync(0xffffffffu, mt, 2));
            const float mo = m_s[row];
            mt = fmaxf(mt, mo);
            float sum = 0.0f;
#pragma unroll
            for (int j = 0; j < 16; j++) {
                float e = __expf(srow[p + 4 * j] - mt);
                srow[p + 4 * j] = tf32r(e);
                sum += e;
            }
            sum += __shfl_xor_sync(0xffffffffu, sum, 1);
            sum += __shfl_xor_sync(0xffffffffu, sum, 2);
            if (p == 0) {
                const float sc = __expf(mo - mt);
                m_s[row]  = mt;
                l_s[row]  = l_s[row] * sc + sum;
                sc_s[row] = sc;
            }
        }
        __syncthreads();

        // rescale accumulators
        {
            const float sc0 = sc_s[wq0 + r];
            const float sc1 = sc_s[wq0 + r + 8];
#pragma unroll
            for (int nt = 0; nt < 4; nt++) {
                oacc[nt][0] *= sc0; oacc[nt][1] *= sc0;
                oacc[nt][2] *= sc1; oacc[nt][3] *= sc1;
            }
        }

        // ---- O += P V (warp tile 16q x 32d) ----
#pragma unroll
        for (int ks = 0; ks < 8; ks++) {
            const int k = ks * 8;
            const int m = wq0 + r;
            const uint32_t a0 = __float_as_uint(Ss[m * APAD + k + c]);
            const uint32_t a1 = __float_as_uint(Ss[(m + 8) * APAD + k + c]);
            const uint32_t a2 = __float_as_uint(Ss[m * APAD + k + c + 4]);
            const uint32_t a3 = __float_as_uint(Ss[(m + 8) * APAD + k + c + 4]);
#pragma unroll
            for (int nt = 0; nt < 4; nt++) {
                const int n = wn0 + nt * 8 + r;
                const uint32_t b0 = __float_as_uint(Vt[n * APAD + k + c]);
                const uint32_t b1 = __float_as_uint(Vt[n * APAD + k + c + 4]);
                MMA_TF32(oacc[nt], a0, a1, a2, a3, b0, b1);
            }
        }
        __syncthreads();
    }

    // reduce colsum(V): 4 partials per d
    svr[(tid >> 6) * 64 + (tid & 63)] = sv_local;
    __syncthreads();
    if (tid < 64)
        sv_s[tid] = 1e-9f * (svr[tid] + svr[64 + tid] + svr[128 + tid] + svr[192 + tid]);
    __syncthreads();

    // epilogue
    {
        const float linv0 = 1.0f / l_s[wq0 + r];
        const float linv1 = 1.0f / l_s[wq0 + r + 8];
        const int row = qstart + wq0 + r;
#pragma unroll
        for (int nt = 0; nt < 4; nt++) {
            const int col = wn0 + nt * 8 + 2 * c;
            const float e0 = sv_s[col], e1 = sv_s[col + 1];
            float2 o0 = make_float2(oacc[nt][0] * linv0 + e0,
                                    oacc[nt][1] * linv0 + e1);
            float2 o1 = make_float2(oacc[nt][2] * linv1 + e0,
                                    oacc[nt][3] * linv1 + e1);
            *(float2*)&O[base + (size_t)row * H + col]       = o0;
            *(float2*)&O[base + (size_t)(row + 8) * H + col] = o1;
        }
    }
}

// ---------------------------------------------------------------------------
// Fused residual-add + LayerNorm (unchanged).
// ---------------------------------------------------------------------------
__global__ __launch_bounds__(256)
void add_ln_kernel(const float* __restrict__ A, const float* __restrict__ Bres,
                   const float* __restrict__ gam, const float* __restrict__ bet,
                   float* __restrict__ out)
{
    const int row = blockIdx.x;
    const int tid = threadIdx.x;
    const float4 va = ((const float4*)(A    + (size_t)row * H))[tid];
    const float4 vb = ((const float4*)(Bres + (size_t)row * H))[tid];
    float x0 = va.x + vb.x, x1 = va.y + vb.y, x2 = va.z + vb.z, x3 = va.w + vb.w;

    __shared__ float red[8];
    __shared__ float s_mu, s_rstd;

    float s = x0 + x1 + x2 + x3;
#pragma unroll
    for (int o = 16; o; o >>= 1) s += __shfl_down_sync(0xffffffffu, s, o);
    if ((tid & 31) == 0) red[tid >> 5] = s;
    __syncthreads();
    if (tid == 0) {
        float t = 0.f;
#pragma unroll
        for (int i = 0; i < 8; i++) t += red[i];
        s_mu = t * (1.0f / H);
    }
    __syncthreads();
    const float mu = s_mu;
    float d0 = x0 - mu, d1 = x1 - mu, d2 = x2 - mu, d3 = x3 - mu;
    float ss = d0 * d0 + d1 * d1 + d2 * d2 + d3 * d3;
#pragma unroll
    for (int o = 16; o; o >>= 1) ss += __shfl_down_sync(0xffffffffu, ss, o);
    __syncthreads();
    if ((tid & 31) == 0) red[tid >> 5] = ss;
    __syncthreads();
    if (tid == 0) {
        float t = 0.f;
#pragma unroll
        for (int i = 0; i < 8; i++) t += red[i];
        s_rstd = rsqrtf(t * (1.0f / H) + 1e-12f);
    }
    __syncthreads();
    const float rstd = s_rstd;

    const float4 g4 = ((const float4*)gam)[tid];
    const float4 b4 = ((const float4*)bet)[tid];
    float4 o;
    o.x = d0 * rstd * g4.x + b4.x;
    o.y = d1 * rstd * g4.y + b4.y;
    o.z = d2 * rstd * g4.z + b4.z;
    o.w = d3 * rstd * g4.w + b4.w;
    ((float4*)(out + (size_t)row * H))[tid] = o;
}

// ---------------------------------------------------------------------------
// Launch
// ---------------------------------------------------------------------------
extern "C" void kernel_launch(void* const* d_in, const int* in_sizes, int n_in,
                              void* d_out, int out_size)
{
    const float* hs   = (const float*)d_in[0];
    const float* Wq   = (const float*)d_in[1];
    const float* bq   = (const float*)d_in[2];
    const float* Wk   = (const float*)d_in[3];
    const float* bk   = (const float*)d_in[4];
    const float* Wv   = (const float*)d_in[5];
    const float* bv   = (const float*)d_in[6];
    const float* ln1g = (const float*)d_in[7];
    const float* ln1b = (const float*)d_in[8];
    const float* W1   = (const float*)d_in[9];
    const float* b1   = (const float*)d_in[10];
    const float* W2   = (const float*)d_in[11];
    const float* b2   = (const float*)d_in[12];
    const float* ln2g = (const float*)d_in[13];
    const float* ln2b = (const float*)d_in[14];
    float* out = (float*)d_out;

    static float *pq = nullptr, *pk = nullptr, *pv = nullptr, *pctx = nullptr,
                 *px = nullptr, *pinter = nullptr, *pffn = nullptr,
                 *pwtq = nullptr, *pwtk = nullptr, *pwtv = nullptr,
                 *pwt1 = nullptr, *pwt2 = nullptr;
    if (!pq) {  // first call is the (uncaptured) correctness run
        cudaGetSymbolAddress((void**)&pq,     g_q);
        cudaGetSymbolAddress((void**)&pk,     g_k);
        cudaGetSymbolAddress((void**)&pv,     g_v);
        cudaGetSymbolAddress((void**)&pctx,   g_ctx);
        cudaGetSymbolAddress((void**)&px,     g_x);
        cudaGetSymbolAddress((void**)&pinter, g_inter);
        cudaGetSymbolAddress((void**)&pffn,   g_ffn);
        cudaGetSymbolAddress((void**)&pwtq,   g_wtq);
        cudaGetSymbolAddress((void**)&pwtk,   g_wtk);
        cudaGetSymbolAddress((void**)&pwtv,   g_wtv);
        cudaGetSymbolAddress((void**)&pwt1,   g_wt1);
        cudaGetSymbolAddress((void**)&pwt2,   g_wt2);
        cudaFuncSetAttribute(attn_mma_kernel,
                             cudaFuncAttributeMaxDynamicSharedMemorySize, ATTN_SMEM);
    }

    // weight transposes (+ tf32 rounding), every replay: ~45us
    transpose_tf32_k<<<dim3(H / 32, H / 32), 256>>>(Wq, pwtq, H, H);
    transpose_tf32_k<<<dim3(H / 32, H / 32), 256>>>(Wk, pwtk, H, H);
    transpose_tf32_k<<<dim3(H / 32, H / 32), 256>>>(Wv, pwtv, H, H);
    transpose_tf32_k<<<dim3(FF / 32, H / 32), 256>>>(W1, pwt1, H, FF);
    transpose_tf32_k<<<dim3(H / 32, FF / 32), 256>>>(W2, pwt2, FF, H);

    // QKV projections (tf32 mma.sync)
    mma_gemm<0><<<dim3(H / 128, BTOK / 128), 256>>>(hs, pwtq, bq, pq, BTOK, H, H);
    mma_gemm<0><<<dim3(H / 128, BTOK / 128), 256>>>(hs, pwtk, bk, pk, BTOK, H, H);
    mma_gemm<0><<<dim3(H / 128, BTOK / 128), 256>>>(hs, pwtv, bv, pv, BTOK, H, H);
    // attention -> ctx (tf32 mma.sync flash)
    attn_mma_kernel<<<dim3(SEQ / 64, 4 * NH), 256, ATTN_SMEM>>>(pq, pk, pv, pctx);
    // residual + LN1 -> x
    add_ln_kernel<<<BTOK, 256>>>(hs, pctx, ln1g, ln1b, px);
    // FFN (tf32 mma.sync)
    mma_gemm<1><<<dim3(FF / 128, BTOK / 128), 256>>>(px, pwt1, b1, pinter, BTOK, FF, H);
    mma_gemm<0><<<dim3(H / 128, BTOK / 128), 256>>>(pinter, pwt2, b2, pffn, BTOK, H, FF);
    // residual + LN2 -> out
    add_ln_kernel<<<BTOK, 256>>>(pffn, px, ln2g, ln2b, out);
}

// round 10
// speedup vs baseline: 2.5719x; 1.0326x over previous
#include <cuda_runtime.h>
#include <math.h>
#include <stdint.h>

#define H    1024
#define NH   16
#define HD   64
#define FF   4096
#define SEQ  2048
#define BTOK 8192   // 4 * 2048 tokens
#define H3   3072   // fused QKV width

// ---------------------------------------------------------------------------
// Scratch (static __device__ globals: allocation-free rule)
// ---------------------------------------------------------------------------
__device__ float g_qkv[(size_t)BTOK * H3];
__device__ float g_ctx[BTOK * H];
__device__ float g_x[BTOK * H];
__device__ float g_inter[(size_t)BTOK * FF];
__device__ float g_ffn[BTOK * H];
// transposed (tf32-rounded) weights
__device__ float g_wtqkv[(size_t)H3 * H];  // rows 0..1023 Wq^T, 1024.. Wk^T, 2048.. Wv^T
__device__ float g_wt1[(size_t)H * FF];    // [FF][H]
__device__ float g_wt2[(size_t)FF * H];    // [H][FF]
__device__ float g_bqkv[H3];

// ---------------------------------------------------------------------------
// Helpers
// ---------------------------------------------------------------------------
__device__ __forceinline__ float tf32r(float x) {
    uint32_t u;
    asm("cvt.rna.tf32.f32 %0, %1;" : "=r"(u) : "f"(x));
    return __uint_as_float(u);
}
__device__ __forceinline__ float gelu_exact(float x) {
    return 0.5f * x * (1.0f + erff(x * 0.70710678118654752f));
}

#define MMA_TF32(ACC, A0, A1, A2, A3, B0, B1)                                  \
    asm volatile(                                                              \
        "mma.sync.aligned.m16n8k8.row.col.f32.tf32.tf32.f32 "                  \
        "{%0,%1,%2,%3}, {%4,%5,%6,%7}, {%8,%9}, {%0,%1,%2,%3};"                \
        : "+f"((ACC)[0]), "+f"((ACC)[1]), "+f"((ACC)[2]), "+f"((ACC)[3])       \
        : "r"(A0), "r"(A1), "r"(A2), "r"(A3), "r"(B0), "r"(B1))

// ---------------------------------------------------------------------------
// Weight transpose + tf32 rounding: W[K][N] -> Wt[N][K]
// ---------------------------------------------------------------------------
__global__ __launch_bounds__(256)
void transpose_tf32_k(const float* __restrict__ W, float* __restrict__ Wt,
                      int K, int N)
{
    __shared__ float t[32][33];
    const int tx = threadIdx.x & 31;
    const int ty = threadIdx.x >> 5;   // 0..7
    const int n0 = blockIdx.x * 32;
    const int k0 = blockIdx.y * 32;
#pragma unroll
    for (int i = 0; i < 4; i++) {
        int r = ty + i * 8;
        t[r][tx] = tf32r(W[(size_t)(k0 + r) * N + n0 + tx]);
    }
    __syncthreads();
#pragma unroll
    for (int i = 0; i < 4; i++) {
        int r = ty + i * 8;
        Wt[(size_t)(n0 + r) * K + k0 + tx] = t[tx][r];
    }
}

// concat bq|bk|bv -> g_bqkv
__global__ __launch_bounds__(256)
void concat_bias_k(const float* __restrict__ bq, const float* __restrict__ bk,
                   const float* __restrict__ bv, float* __restrict__ o)
{
    int t = threadIdx.x + blockIdx.x * 256;
    if (t < H) o[t] = bq[t];
    else if (t < 2 * H) o[t] = bk[t - H];
    else o[t] = bv[t - 2 * H];
}

// ---------------------------------------------------------------------------
// TF32 tensor-core GEMM via mma.sync.m16n8k8 (proven R6/R7 structure).
// ---------------------------------------------------------------------------
#define BM 128
#define BN 128
#define BKG 16
#define PADK 20

template <int EPI>  // 0: +bias   1: gelu(+bias)+clamp
__global__ __launch_bounds__(256)
void mma_gemm(const float* __restrict__ A, const float* __restrict__ Bt,
              const float* __restrict__ bias, float* __restrict__ C,
              int M, int N, int K)
{
    __shared__ float As[2][BM][PADK];
    __shared__ float Bs[2][BN][PADK];

    const int tid  = threadIdx.x;
    const int lane = tid & 31;
    const int wid  = tid >> 5;
    const int wm0  = (wid >> 1) * 32;   // 0,32,64,96
    const int wn0  = (wid & 1) * 64;    // 0,64
    const int r    = lane >> 2;         // 0..7
    const int c    = lane & 3;          // 0..3

    const int row0 = blockIdx.y * BM;
    const int col0 = blockIdx.x * BN;

    const int ldr = tid >> 2;           // 0..63
    const int ldc = (tid & 3) * 4;      // 0,4,8,12

    const float* Ap = A  + (size_t)(row0 + ldr) * K + ldc;
    const float* Bp = Bt + (size_t)(col0 + ldr) * K + ldc;
    const size_t stride64 = (size_t)64 * K;

    float acc[2][8][4];
#pragma unroll
    for (int mt = 0; mt < 2; mt++)
#pragma unroll
        for (int nt = 0; nt < 8; nt++)
#pragma unroll
            for (int u = 0; u < 4; u++) acc[mt][nt][u] = 0.0f;

    float4 ra0, ra1, rb0, rb1;

    ra0 = *(const float4*)(Ap);
    ra1 = *(const float4*)(Ap + stride64);
    rb0 = *(const float4*)(Bp);
    rb1 = *(const float4*)(Bp + stride64);
    {
        float4 t0 = make_float4(tf32r(ra0.x), tf32r(ra0.y), tf32r(ra0.z), tf32r(ra0.w));
        float4 t1 = make_float4(tf32r(ra1.x), tf32r(ra1.y), tf32r(ra1.z), tf32r(ra1.w));
        *(float4*)&As[0][ldr][ldc]      = t0;
        *(float4*)&As[0][ldr + 64][ldc] = t1;
        *(float4*)&Bs[0][ldr][ldc]      = rb0;
        *(float4*)&Bs[0][ldr + 64][ldc] = rb1;
    }
    __syncthreads();

    const int NS = K / BKG;
    for (int s = 0; s < NS; s++) {
        const int cur = s & 1;
        if (s + 1 < NS) {
            const int k0 = (s + 1) * BKG;
            ra0 = *(const float4*)(Ap + k0);
            ra1 = *(const float4*)(Ap + stride64 + k0);
            rb0 = *(const float4*)(Bp + k0);
            rb1 = *(const float4*)(Bp + stride64 + k0);
        }

#pragma unroll
        for (int ks = 0; ks < 2; ks++) {
            const int k = ks * 8;
            uint32_t af[2][4];
#pragma unroll
            for (int mt = 0; mt < 2; mt++) {
                const int m = wm0 + mt * 16 + r;
                af[mt][0] = __float_as_uint(As[cur][m][k + c]);
                af[mt][1] = __float_as_uint(As[cur][m + 8][k + c]);
                af[mt][2] = __float_as_uint(As[cur][m][k + c + 4]);
                af[mt][3] = __float_as_uint(As[cur][m + 8][k + c + 4]);
            }
#pragma unroll
            for (int nt = 0; nt < 8; nt++) {
                const int n = wn0 + nt * 8 + r;
                const uint32_t b0 = __float_as_uint(Bs[cur][n][k + c]);
                const uint32_t b1 = __float_as_uint(Bs[cur][n][k + c + 4]);
                MMA_TF32(acc[0][nt], af[0][0], af[0][1], af[0][2], af[0][3], b0, b1);
                MMA_TF32(acc[1][nt], af[1][0], af[1][1], af[1][2], af[1][3], b0, b1);
            }
        }

        if (s + 1 < NS) {
            const int nxt = (s + 1) & 1;
            float4 t0 = make_float4(tf32r(ra0.x), tf32r(ra0.y), tf32r(ra0.z), tf32r(ra0.w));
            float4 t1 = make_float4(tf32r(ra1.x), tf32r(ra1.y), tf32r(ra1.z), tf32r(ra1.w));
            *(float4*)&As[nxt][ldr][ldc]      = t0;
            *(float4*)&As[nxt][ldr + 64][ldc] = t1;
            *(float4*)&Bs[nxt][ldr][ldc]      = rb0;
            *(float4*)&Bs[nxt][ldr + 64][ldc] = rb1;
        }
        __syncthreads();
    }

#pragma unroll
    for (int mt = 0; mt < 2; mt++) {
        const int rowA = row0 + wm0 + mt * 16 + r;
#pragma unroll
        for (int nt = 0; nt < 8; nt++) {
            const int col = col0 + wn0 + nt * 8 + 2 * c;
            const float bz0 = bias[col];
            const float bz1 = bias[col + 1];
            float v0 = acc[mt][nt][0] + bz0;
            float v1 = acc[mt][nt][1] + bz1;
            float v2 = acc[mt][nt][2] + bz0;
            float v3 = acc[mt][nt][3] + bz1;
            if (EPI == 1) {
                v0 = fminf(fmaxf(gelu_exact(v0), -1e9f), 1e9f);
                v1 = fminf(fmaxf(gelu_exact(v1), -1e9f), 1e9f);
                v2 = fminf(fmaxf(gelu_exact(v2), -1e9f), 1e9f);
                v3 = fminf(fmaxf(gelu_exact(v3), -1e9f), 1e9f);
            }
            *(float2*)(C + (size_t)rowA * N + col)       = make_float2(v0, v1);
            *(float2*)(C + (size_t)(rowA + 8) * N + col) = make_float2(v2, v3);
        }
    }
}

// ---------------------------------------------------------------------------
// Flash attention on tensor cores (mma.sync tf32), reading fused QKV buffer.
// Block: 64 queries of one (b,h); 256 threads = 8 warps (4 qm x 2 n-half).
// KV tiles prefetched into registers one iteration ahead (LDG latency hidden
// behind the QK/softmax/PV compute of the current tile).
// ---------------------------------------------------------------------------
#define APAD 68
#define ATILE (64 * APAD)
#define ATTN_SMEM ((4 * ATILE + 3 * 64 + 256 + 64) * 4)

__global__ __launch_bounds__(256)
void attn_mma_kernel(const float* __restrict__ QKV, float* __restrict__ O)
{
    extern __shared__ float smf[];
    float* Qs    = smf;                   // [q][d]
    float* Ks    = smf + ATILE;           // [kv][d]
    float* Vt    = smf + 2 * ATILE;       // [d][kv]
    float* Ss    = smf + 3 * ATILE;       // [q][kv]
    float* m_s   = smf + 4 * ATILE;
    float* l_s   = m_s + 64;
    float* sc_s  = l_s + 64;
    float* svr   = sc_s + 64;             // [4][64] partial colsum(V)
    float* sv_s  = svr + 256;             // [64] final 1e-9*colsum

    const int tid  = threadIdx.x;
    const int lane = tid & 31;
    const int wid  = tid >> 5;
    const int wq0  = (wid >> 1) * 16;     // 0,16,32,48
    const int wn0  = (wid & 1) * 32;      // 0,32
    const int r    = lane >> 2;           // 0..7
    const int c    = lane & 3;            // 0..3

    const int bh = blockIdx.y;
    const int b  = bh >> 4;
    const int h  = bh & 15;
    const int qstart = blockIdx.x * 64;
    const size_t rowbase = (size_t)b * SEQ;
    const float* Qp = QKV + (size_t)h * HD;
    const float* Kp = Qp + H;
    const float* Vp = Qp + 2 * H;
    const size_t obase = (size_t)b * SEQ * H + (size_t)h * HD;

    // per-thread tile element mapping (16 elements each of K and V)
    float kreg[16], vreg[16];

    // load Q tile (tf32-rounded) + prefetch KV tile 0
#pragma unroll
    for (int it = 0; it < 16; it++) {
        int idx = tid + it * 256;
        int rr = idx >> 6, cc = idx & 63;
        Qs[rr * APAD + cc] = tf32r(Qp[(rowbase + qstart + rr) * H3 + cc]);
        size_t gi = (rowbase + rr) * H3 + cc;
        kreg[it] = Kp[gi];
        vreg[it] = Vp[gi];
    }
    if (tid < 64) { m_s[tid] = -1e30f; l_s[tid] = 0.0f; }

    float oacc[4][4];
#pragma unroll
    for (int nt = 0; nt < 4; nt++)
#pragma unroll
        for (int u = 0; u < 4; u++) oacc[nt][u] = 0.0f;
    float sv_local = 0.0f;                // colsum(V) partial; d = tid&63 fixed

    __syncthreads();
    // store tile 0
#pragma unroll
    for (int it = 0; it < 16; it++) {
        int idx = tid + it * 256;
        int rr = idx >> 6, cc = idx & 63;
        Ks[rr * APAD + cc] = tf32r(kreg[it]);
        float vv = tf32r(vreg[it]);
        Vt[cc * APAD + rr] = vv;
        sv_local += vv;
    }
    __syncthreads();

    for (int kt = 0; kt < SEQ / 64; kt++) {
        // prefetch next KV tile into registers (overlaps with compute below)
        if (kt + 1 < SEQ / 64) {
            const int kstart = (kt + 1) * 64;
#pragma unroll
            for (int it = 0; it < 16; it++) {
                int idx = tid + it * 256;
                int rr = idx >> 6, cc = idx & 63;
                size_t gi = (rowbase + kstart + rr) * H3 + cc;
                kreg[it] = Kp[gi];
                vreg[it] = Vp[gi];
            }
        }

        // ---- S = Q K^T (warp tile 16q x 32kv) ----
        float sacc[4][4];
#pragma unroll
        for (int nt = 0; nt < 4; nt++)
#pragma unroll
            for (int u = 0; u < 4; u++) sacc[nt][u] = 0.0f;

#pragma unroll
        for (int ks = 0; ks < 8; ks++) {
            const int k = ks * 8;
            const int m = wq0 + r;
            const uint32_t a0 = __float_as_uint(Qs[m * APAD + k + c]);
            const uint32_t a1 = __float_as_uint(Qs[(m + 8) * APAD + k + c]);
            const uint32_t a2 = __float_as_uint(Qs[m * APAD + k + c + 4]);
            const uint32_t a3 = __float_as_uint(Qs[(m + 8) * APAD + k + c + 4]);
#pragma unroll
            for (int nt = 0; nt < 4; nt++) {
                const int n = wn0 + nt * 8 + r;
                const uint32_t b0 = __float_as_uint(Ks[n * APAD + k + c]);
                const uint32_t b1 = __float_as_uint(Ks[n * APAD + k + c + 4]);
                MMA_TF32(sacc[nt], a0, a1, a2, a3, b0, b1);
            }
        }
        // scale + clamp, stage to Ss
#pragma unroll
        for (int nt = 0; nt < 4; nt++) {
            const int col = wn0 + nt * 8 + 2 * c;
            const int row = wq0 + r;
            float v0 = fminf(fmaxf(sacc[nt][0] * 0.125f, -1e9f), 1e9f);
            float v1 = fminf(fmaxf(sacc[nt][1] * 0.125f, -1e9f), 1e9f);
            float v2 = fminf(fmaxf(sacc[nt][2] * 0.125f, -1e9f), 1e9f);
            float v3 = fminf(fmaxf(sacc[nt][3] * 0.125f, -1e9f), 1e9f);
            *(float2*)&Ss[row * APAD + col]       = make_float2(v0, v1);
            *(float2*)&Ss[(row + 8) * APAD + col] = make_float2(v2, v3);
        }
        __syncthreads();

        // ---- online softmax: 4 threads per row, strided (conflict-free) ----
        {
            const int row = tid >> 2;
            const int p   = tid & 3;
            float* srow = &Ss[row * APAD];
            float mt = -1e30f;
#pragma unroll
            for (int j = 0; j < 16; j++) mt = fmaxf(mt, srow[p + 4 * j]);
            mt = fmaxf(mt, __shfl_xor_sync(0xffffffffu, mt, 1));
            mt = fmaxf(mt, __shfl_xor_sync(0xffffffffu, mt, 2));
            const float mo = m_s[row];
            mt = fmaxf(mt, mo);
            float sum = 0.0f;
#pragma unroll
            for (int j = 0; j < 16; j++) {
                float e = __expf(srow[p + 4 * j] - mt);
                srow[p + 4 * j] = tf32r(e);
                sum += e;
            }
            sum += __shfl_xor_sync(0xffffffffu, sum, 1);
            sum += __shfl_xor_sync(0xffffffffu, sum, 2);
            if (p == 0) {
                const float sc = __expf(mo - mt);
                m_s[row]  = mt;
                l_s[row]  = l_s[row] * sc + sum;
                sc_s[row] = sc;
            }
        }
        __syncthreads();

        // rescale accumulators
        {
            const float sc0 = sc_s[wq0 + r];
            const float sc1 = sc_s[wq0 + r + 8];
#pragma unroll
            for (int nt = 0; nt < 4; nt++) {
                oacc[nt][0] *= sc0; oacc[nt][1] *= sc0;
                oacc[nt][2] *= sc1; oacc[nt][3] *= sc1;
            }
        }

        // ---- O += P V (warp tile 16q x 32d) ----
#pragma unroll
        for (int ks = 0; ks < 8; ks++) {
            const int k = ks * 8;
            const int m = wq0 + r;
            const uint32_t a0 = __float_as_uint(Ss[m * APAD + k + c]);
            const uint32_t a1 = __float_as_uint(Ss[(m + 8) * APAD + k + c]);
            const uint32_t a2 = __float_as_uint(Ss[m * APAD + k + c + 4]);
            const uint32_t a3 = __float_as_uint(Ss[(m + 8) * APAD + k + c + 4]);
#pragma unroll
            for (int nt = 0; nt < 4; nt++) {
                const int n = wn0 + nt * 8 + r;
                const uint32_t b0 = __float_as_uint(Vt[n * APAD + k + c]);
                const uint32_t b1 = __float_as_uint(Vt[n * APAD + k + c + 4]);
                MMA_TF32(oacc[nt], a0, a1, a2, a3, b0, b1);
            }
        }
        __syncthreads();   // all reads of Ks/Vt/Ss done

        // store prefetched tile kt+1
        if (kt + 1 < SEQ / 64) {
#pragma unroll
            for (int it = 0; it < 16; it++) {
                int idx = tid + it * 256;
                int rr = idx >> 6, cc = idx & 63;
                Ks[rr * APAD + cc] = tf32r(kreg[it]);
                float vv = tf32r(vreg[it]);
                Vt[cc * APAD + rr] = vv;
                sv_local += vv;
            }
            __syncthreads();
        }
    }

    // reduce colsum(V): 4 partials per d
    svr[(tid >> 6) * 64 + (tid & 63)] = sv_local;
    __syncthreads();
    if (tid < 64)
        sv_s[tid] = 1e-9f * (svr[tid] + svr[64 + tid] + svr[128 + tid] + svr[192 + tid]);
    __syncthreads();

    // epilogue
    {
        const float linv0 = 1.0f / l_s[wq0 + r];
        const float linv1 = 1.0f / l_s[wq0 + r + 8];
        const int row = qstart + wq0 + r;
#pragma unroll
        for (int nt = 0; nt < 4; nt++) {
            const int col = wn0 + nt * 8 + 2 * c;
            const float e0 = sv_s[col], e1 = sv_s[col + 1];
            float2 o0 = make_float2(oacc[nt][0] * linv0 + e0,
                                    oacc[nt][1] * linv0 + e1);
            float2 o1 = make_float2(oacc[nt][2] * linv1 + e0,
                                    oacc[nt][3] * linv1 + e1);
            *(float2*)&O[obase + (size_t)row * H + col]       = o0;
            *(float2*)&O[obase + (size_t)(row + 8) * H + col] = o1;
        }
    }
}

// ---------------------------------------------------------------------------
// Fused residual-add + LayerNorm (unchanged).
// ---------------------------------------------------------------------------
__global__ __launch_bounds__(256)
void add_ln_kernel(const float* __restrict__ A, const float* __restrict__ Bres,
                   const float* __restrict__ gam, const float* __restrict__ bet,
                   float* __restrict__ out)
{
    const int row = blockIdx.x;
    const int tid = threadIdx.x;
    const float4 va = ((const float4*)(A    + (size_t)row * H))[tid];
    const float4 vb = ((const float4*)(Bres + (size_t)row * H))[tid];
    float x0 = va.x + vb.x, x1 = va.y + vb.y, x2 = va.z + vb.z, x3 = va.w + vb.w;

    __shared__ float red[8];
    __shared__ float s_mu, s_rstd;

    float s = x0 + x1 + x2 + x3;
#pragma unroll
    for (int o = 16; o; o >>= 1) s += __shfl_down_sync(0xffffffffu, s, o);
    if ((tid & 31) == 0) red[tid >> 5] = s;
    __syncthreads();
    if (tid == 0) {
        float t = 0.f;
#pragma unroll
        for (int i = 0; i < 8; i++) t += red[i];
        s_mu = t * (1.0f / H);
    }
    __syncthreads();
    const float mu = s_mu;
    float d0 = x0 - mu, d1 = x1 - mu, d2 = x2 - mu, d3 = x3 - mu;
    float ss = d0 * d0 + d1 * d1 + d2 * d2 + d3 * d3;
#pragma unroll
    for (int o = 16; o; o >>= 1) ss += __shfl_down_sync(0xffffffffu, ss, o);
    __syncthreads();
    if ((tid & 31) == 0) red[tid >> 5] = ss;
    __syncthreads();
    if (tid == 0) {
        float t = 0.f;
#pragma unroll
        for (int i = 0; i < 8; i++) t += red[i];
        s_rstd = rsqrtf(t * (1.0f / H) + 1e-12f);
    }
    __syncthreads();
    const float rstd = s_rstd;

    const float4 g4 = ((const float4*)gam)[tid];
    const float4 b4 = ((const float4*)bet)[tid];
    float4 o;
    o.x = d0 * rstd * g4.x + b4.x;
    o.y = d1 * rstd * g4.y + b4.y;
    o.z = d2 * rstd * g4.z + b4.z;
    o.w = d3 * rstd * g4.w + b4.w;
    ((float4*)(out + (size_t)row * H))[tid] = o;
}

// ---------------------------------------------------------------------------
// Launch
// ---------------------------------------------------------------------------
extern "C" void kernel_launch(void* const* d_in, const int* in_sizes, int n_in,
                              void* d_out, int out_size)
{
    const float* hs   = (const float*)d_in[0];
    const float* Wq   = (const float*)d_in[1];
    const float* bq   = (const float*)d_in[2];
    const float* Wk   = (const float*)d_in[3];
    const float* bk   = (const float*)d_in[4];
    const float* Wv   = (const float*)d_in[5];
    const float* bv   = (const float*)d_in[6];
    const float* ln1g = (const float*)d_in[7];
    const float* ln1b = (const float*)d_in[8];
    const float* W1   = (const float*)d_in[9];
    const float* b1   = (const float*)d_in[10];
    const float* W2   = (const float*)d_in[11];
    const float* b2   = (const float*)d_in[12];
    const float* ln2g = (const float*)d_in[13];
    const float* ln2b = (const float*)d_in[14];
    float* out = (float*)d_out;

    static float *pqkv = nullptr, *pctx = nullptr, *px = nullptr,
                 *pinter = nullptr, *pffn = nullptr, *pwqkv = nullptr,
                 *pwt1 = nullptr, *pwt2 = nullptr, *pbqkv = nullptr;
    if (!pqkv) {  // first call is the (uncaptured) correctness run
        cudaGetSymbolAddress((void**)&pqkv,   g_qkv);
        cudaGetSymbolAddress((void**)&pctx,   g_ctx);
        cudaGetSymbolAddress((void**)&px,     g_x);
        cudaGetSymbolAddress((void**)&pinter, g_inter);
        cudaGetSymbolAddress((void**)&pffn,   g_ffn);
        cudaGetSymbolAddress((void**)&pwqkv,  g_wtqkv);
        cudaGetSymbolAddress((void**)&pwt1,   g_wt1);
        cudaGetSymbolAddress((void**)&pwt2,   g_wt2);
        cudaGetSymbolAddress((void**)&pbqkv,  g_bqkv);
        cudaFuncSetAttribute(attn_mma_kernel,
                             cudaFuncAttributeMaxDynamicSharedMemorySize, ATTN_SMEM);
    }

    // weight transposes (+ tf32 rounding) and bias concat
    transpose_tf32_k<<<dim3(H / 32, H / 32), 256>>>(Wq, pwqkv,             H, H);
    transpose_tf32_k<<<dim3(H / 32, H / 32), 256>>>(Wk, pwqkv + H * H,     H, H);
    transpose_tf32_k<<<dim3(H / 32, H / 32), 256>>>(Wv, pwqkv + 2 * H * H, H, H);
    transpose_tf32_k<<<dim3(FF / 32, H / 32), 256>>>(W1, pwt1, H, FF);
    transpose_tf32_k<<<dim3(H / 32, FF / 32), 256>>>(W2, pwt2, FF, H);
    concat_bias_k<<<H3 / 256, 256>>>(bq, bk, bv, pbqkv);

    // fused QKV projection (tf32 mma.sync, N=3072)
    mma_gemm<0><<<dim3(H3 / 128, BTOK / 128), 256>>>(hs, pwqkv, pbqkv, pqkv,
                                                     BTOK, H3, H);
    // attention -> ctx (tf32 mma.sync flash, reads fused QKV)
    attn_mma_kernel<<<dim3(SEQ / 64, 4 * NH), 256, ATTN_SMEM>>>(pqkv, pctx);
    // residual + LN1 -> x
    add_ln_kernel<<<BTOK, 256>>>(hs, pctx, ln1g, ln1b, px);
    // FFN (tf32 mma.sync)
    mma_gemm<1><<<dim3(FF / 128, BTOK / 128), 256>>>(px, pwt1, b1, pinter, BTOK, FF, H);
    mma_gemm<0><<<dim3(H / 128, BTOK / 128), 256>>>(pinter, pwt2, b2, pffn, BTOK, H, FF);
    // residual + LN2 -> out
    add_ln_kernel<<<BTOK, 256>>>(pffn, px, ln2g, ln2b, out);
}

// round 11
// speedup vs baseline: 3.0319x; 1.1788x over previous
#include <cuda_runtime.h>
#include <math.h>
#include <stdint.h>

#define H    1024
#define NH   16
#define HD   64
#define FF   4096
#define SEQ  2048
#define BTOK 8192   // 4 * 2048 tokens
#define H3   3072   // fused QKV width

// ---------------------------------------------------------------------------
// Scratch (static __device__ globals: allocation-free rule)
// ---------------------------------------------------------------------------
__device__ float g_qkv[(size_t)BTOK * H3];
__device__ float g_ctx[BTOK * H];
__device__ float g_x[BTOK * H];
__device__ float g_inter[(size_t)BTOK * FF];
__device__ float g_ffn[BTOK * H];
// transposed (tf32-rounded) weights
__device__ float g_wtqkv[(size_t)H3 * H];  // rows 0..1023 Wq^T, 1024.. Wk^T, 2048.. Wv^T
__device__ float g_wt1[(size_t)H * FF];    // [FF][H]
__device__ float g_wt2[(size_t)FF * H];    // [H][FF]
__device__ float g_bqkv[H3];

// ---------------------------------------------------------------------------
// Helpers
// ---------------------------------------------------------------------------
__device__ __forceinline__ uint32_t smem_u32(const void* p) {
    uint32_t a;
    asm("{ .reg .u64 t; cvta.to.shared.u64 t, %1; cvt.u32.u64 %0, t; }"
        : "=r"(a) : "l"(p));
    return a;
}
__device__ __forceinline__ float tf32r(float x) {
    uint32_t u;
    asm("cvt.rna.tf32.f32 %0, %1;" : "=r"(u) : "f"(x));
    return __uint_as_float(u);
}
__device__ __forceinline__ float gelu_exact(float x) {
    return 0.5f * x * (1.0f + erff(x * 0.70710678118654752f));
}

#define MMA_TF32(ACC, A0, A1, A2, A3, B0, B1)                                  \
    asm volatile(                                                              \
        "mma.sync.aligned.m16n8k8.row.col.f32.tf32.tf32.f32 "                  \
        "{%0,%1,%2,%3}, {%4,%5,%6,%7}, {%8,%9}, {%0,%1,%2,%3};"                \
        : "+f"((ACC)[0]), "+f"((ACC)[1]), "+f"((ACC)[2]), "+f"((ACC)[3])       \
        : "r"(A0), "r"(A1), "r"(A2), "r"(A3), "r"(B0), "r"(B1))

// ldmatrix x4: pure 128-bit row mover; tf32 bits pass through as b16 pairs.
#define LDM_X4(R0, R1, R2, R3, ADDR)                                           \
    asm volatile(                                                              \
        "ldmatrix.sync.aligned.m8n8.x4.shared.b16 {%0,%1,%2,%3}, [%4];"        \
        : "=r"(R0), "=r"(R1), "=r"(R2), "=r"(R3) : "r"(ADDR))

// ---------------------------------------------------------------------------
// Weight transpose + tf32 rounding: W[K][N] -> Wt[N][K]
// ---------------------------------------------------------------------------
__global__ __launch_bounds__(256)
void transpose_tf32_k(const float* __restrict__ W, float* __restrict__ Wt,
                      int K, int N)
{
    __shared__ float t[32][33];
    const int tx = threadIdx.x & 31;
    const int ty = threadIdx.x >> 5;   // 0..7
    const int n0 = blockIdx.x * 32;
    const int k0 = blockIdx.y * 32;
#pragma unroll
    for (int i = 0; i < 4; i++) {
        int r = ty + i * 8;
        t[r][tx] = tf32r(W[(size_t)(k0 + r) * N + n0 + tx]);
    }
    __syncthreads();
#pragma unroll
    for (int i = 0; i < 4; i++) {
        int r = ty + i * 8;
        Wt[(size_t)(n0 + r) * K + k0 + tx] = t[tx][r];
    }
}

// concat bq|bk|bv -> g_bqkv
__global__ __launch_bounds__(256)
void concat_bias_k(const float* __restrict__ bq, const float* __restrict__ bk,
                   const float* __restrict__ bv, float* __restrict__ o)
{
    int t = threadIdx.x + blockIdx.x * 256;
    if (t < H) o[t] = bq[t];
    else if (t < 2 * H) o[t] = bk[t - H];
    else o[t] = bv[t - 2 * H];
}

// ---------------------------------------------------------------------------
// TF32 tensor-core GEMM via mma.sync.m16n8k8 with ldmatrix fragment loads.
// CTA tile 128x128, BK=16, 256 threads = 8 warps (4M x 2N), warp tile 32x64.
// ---------------------------------------------------------------------------
#define BM 128
#define BN 128
#define BKG 16
#define PADK 20

template <int EPI>  // 0: +bias   1: gelu(+bias)+clamp
__global__ __launch_bounds__(256)
void mma_gemm(const float* __restrict__ A, const float* __restrict__ Bt,
              const float* __restrict__ bias, float* __restrict__ C,
              int M, int N, int K)
{
    __shared__ __align__(16) float As[2][BM][PADK];
    __shared__ __align__(16) float Bs[2][BN][PADK];

    const int tid  = threadIdx.x;
    const int lane = tid & 31;
    const int wid  = tid >> 5;
    const int wm0  = (wid >> 1) * 32;   // 0,32,64,96
    const int wn0  = (wid & 1) * 64;    // 0,64
    const int r    = lane >> 2;         // 0..7
    const int c    = lane & 3;          // 0..3

    const int row0 = blockIdx.y * BM;
    const int col0 = blockIdx.x * BN;

    const int ldr = tid >> 2;           // 0..63
    const int ldc = (tid & 3) * 4;      // 0,4,8,12

    const float* Ap = A  + (size_t)(row0 + ldr) * K + ldc;
    const float* Bp = Bt + (size_t)(col0 + ldr) * K + ldc;
    const size_t stride64 = (size_t)64 * K;

    // ldmatrix per-lane row addresses
    const int lr = lane & 7, lg = lane >> 3;
    const uint32_t aLane = smem_u32(&As[0][0][0]) +
        (uint32_t)(((wm0 + lr + 8 * (lg & 1)) * PADK + 4 * (lg >> 1)) * 4);
    const uint32_t bLane = smem_u32(&Bs[0][0][0]) +
        (uint32_t)(((wn0 + lr + 8 * (lg >> 1)) * PADK + 4 * (lg & 1)) * 4);
    const uint32_t bufStride = BM * PADK * 4;   // 10240

    float acc[2][8][4];
#pragma unroll
    for (int mt = 0; mt < 2; mt++)
#pragma unroll
        for (int nt = 0; nt < 8; nt++)
#pragma unroll
            for (int u = 0; u < 4; u++) acc[mt][nt][u] = 0.0f;

    float4 ra0, ra1, rb0, rb1;

    ra0 = *(const float4*)(Ap);
    ra1 = *(const float4*)(Ap + stride64);
    rb0 = *(const float4*)(Bp);
    rb1 = *(const float4*)(Bp + stride64);
    {
        float4 t0 = make_float4(tf32r(ra0.x), tf32r(ra0.y), tf32r(ra0.z), tf32r(ra0.w));
        float4 t1 = make_float4(tf32r(ra1.x), tf32r(ra1.y), tf32r(ra1.z), tf32r(ra1.w));
        *(float4*)&As[0][ldr][ldc]      = t0;
        *(float4*)&As[0][ldr + 64][ldc] = t1;
        *(float4*)&Bs[0][ldr][ldc]      = rb0;
        *(float4*)&Bs[0][ldr + 64][ldc] = rb1;
    }
    __syncthreads();

    const int NS = K / BKG;
    for (int s = 0; s < NS; s++) {
        const int cur = s & 1;
        const uint32_t aCur = aLane + cur * bufStride;
        const uint32_t bCur = bLane + cur * bufStride;
        if (s + 1 < NS) {
            const int k0 = (s + 1) * BKG;
            ra0 = *(const float4*)(Ap + k0);
            ra1 = *(const float4*)(Ap + stride64 + k0);
            rb0 = *(const float4*)(Bp + k0);
            rb1 = *(const float4*)(Bp + stride64 + k0);
        }

#pragma unroll
        for (int ks = 0; ks < 2; ks++) {
            const uint32_t ko = ks * 32;
            uint32_t af[2][4];
            LDM_X4(af[0][0], af[0][1], af[0][2], af[0][3], aCur + ko);
            LDM_X4(af[1][0], af[1][1], af[1][2], af[1][3],
                   aCur + 16 * PADK * 4 + ko);
#pragma unroll
            for (int np = 0; np < 4; np++) {
                uint32_t b0, b1, b2, b3;
                LDM_X4(b0, b1, b2, b3, bCur + np * (16 * PADK * 4) + ko);
                MMA_TF32(acc[0][2 * np],     af[0][0], af[0][1], af[0][2], af[0][3], b0, b1);
                MMA_TF32(acc[1][2 * np],     af[1][0], af[1][1], af[1][2], af[1][3], b0, b1);
                MMA_TF32(acc[0][2 * np + 1], af[0][0], af[0][1], af[0][2], af[0][3], b2, b3);
                MMA_TF32(acc[1][2 * np + 1], af[1][0], af[1][1], af[1][2], af[1][3], b2, b3);
            }
        }

        if (s + 1 < NS) {
            const int nxt = (s + 1) & 1;
            float4 t0 = make_float4(tf32r(ra0.x), tf32r(ra0.y), tf32r(ra0.z), tf32r(ra0.w));
            float4 t1 = make_float4(tf32r(ra1.x), tf32r(ra1.y), tf32r(ra1.z), tf32r(ra1.w));
            *(float4*)&As[nxt][ldr][ldc]      = t0;
            *(float4*)&As[nxt][ldr + 64][ldc] = t1;
            *(float4*)&Bs[nxt][ldr][ldc]      = rb0;
            *(float4*)&Bs[nxt][ldr + 64][ldc] = rb1;
        }
        __syncthreads();
    }

#pragma unroll
    for (int mt = 0; mt < 2; mt++) {
        const int rowA = row0 + wm0 + mt * 16 + r;
#pragma unroll
        for (int nt = 0; nt < 8; nt++) {
            const int col = col0 + wn0 + nt * 8 + 2 * c;
            const float bz0 = bias[col];
            const float bz1 = bias[col + 1];
            float v0 = acc[mt][nt][0] + bz0;
            float v1 = acc[mt][nt][1] + bz1;
            float v2 = acc[mt][nt][2] + bz0;
            float v3 = acc[mt][nt][3] + bz1;
            if (EPI == 1) {
                v0 = fminf(fmaxf(gelu_exact(v0), -1e9f), 1e9f);
                v1 = fminf(fmaxf(gelu_exact(v1), -1e9f), 1e9f);
                v2 = fminf(fmaxf(gelu_exact(v2), -1e9f), 1e9f);
                v3 = fminf(fmaxf(gelu_exact(v3), -1e9f), 1e9f);
            }
            *(float2*)(C + (size_t)rowA * N + col)       = make_float2(v0, v1);
            *(float2*)(C + (size_t)(rowA + 8) * N + col) = make_float2(v2, v3);
        }
    }
}

// ---------------------------------------------------------------------------
// Flash attention on tensor cores (mma.sync tf32 + ldmatrix), fused QKV input.
// Block: 64 queries of one (b,h); 256 threads = 8 warps (4 qm x 2 n-half).
// ---------------------------------------------------------------------------
#define APAD 68
#define ATILE (64 * APAD)
#define ATTN_SMEM ((4 * ATILE + 3 * 64 + 256 + 64) * 4)

__global__ __launch_bounds__(256)
void attn_mma_kernel(const float* __restrict__ QKV, float* __restrict__ O)
{
    extern __shared__ __align__(16) float smf[];
    float* Qs    = smf;                   // [q][d]
    float* Ks    = smf + ATILE;           // [kv][d]
    float* Vt    = smf + 2 * ATILE;       // [d][kv]
    float* Ss    = smf + 3 * ATILE;       // [q][kv]
    float* m_s   = smf + 4 * ATILE;
    float* l_s   = m_s + 64;
    float* sc_s  = l_s + 64;
    float* svr   = sc_s + 64;             // [4][64] partial colsum(V)
    float* sv_s  = svr + 256;             // [64] final 1e-9*colsum

    const int tid  = threadIdx.x;
    const int lane = tid & 31;
    const int wid  = tid >> 5;
    const int wq0  = (wid >> 1) * 16;     // 0,16,32,48
    const int wn0  = (wid & 1) * 32;      // 0,32
    const int r    = lane >> 2;           // 0..7
    const int c    = lane & 3;            // 0..3

    const int bh = blockIdx.y;
    const int b  = bh >> 4;
    const int h  = bh & 15;
    const int qstart = blockIdx.x * 64;
    const size_t rowbase = (size_t)b * SEQ;
    const float* Qp = QKV + (size_t)h * HD;
    const float* Kp = Qp + H;
    const float* Vp = Qp + 2 * H;
    const size_t obase = (size_t)b * SEQ * H + (size_t)h * HD;

    // ldmatrix per-lane row addresses
    const int lr = lane & 7, lg = lane >> 3;
    const int aRow = wq0 + lr + 8 * (lg & 1);
    const int aKof = 4 * (lg >> 1);
    const int bRow = wn0 + lr + 8 * (lg >> 1);
    const int bKof = 4 * (lg & 1);
    const uint32_t qLane = smem_u32(Qs) + (uint32_t)((aRow * APAD + aKof) * 4);
    const uint32_t sLane = smem_u32(Ss) + (uint32_t)((aRow * APAD + aKof) * 4);
    const uint32_t kLane = smem_u32(Ks) + (uint32_t)((bRow * APAD + bKof) * 4);
    const uint32_t vLane = smem_u32(Vt) + (uint32_t)((bRow * APAD + bKof) * 4);

    float kreg[16], vreg[16];

    // load Q tile (tf32-rounded) + prefetch KV tile 0
#pragma unroll
    for (int it = 0; it < 16; it++) {
        int idx = tid + it * 256;
        int rr = idx >> 6, cc = idx & 63;
        Qs[rr * APAD + cc] = tf32r(Qp[(rowbase + qstart + rr) * H3 + cc]);
        size_t gi = (rowbase + rr) * H3 + cc;
        kreg[it] = Kp[gi];
        vreg[it] = Vp[gi];
    }
    if (tid < 64) { m_s[tid] = -1e30f; l_s[tid] = 0.0f; }

    float oacc[4][4];
#pragma unroll
    for (int nt = 0; nt < 4; nt++)
#pragma unroll
        for (int u = 0; u < 4; u++) oacc[nt][u] = 0.0f;
    float sv_local = 0.0f;                // colsum(V) partial; d = tid&63 fixed

    __syncthreads();
    // store tile 0
#pragma unroll
    for (int it = 0; it < 16; it++) {
        int idx = tid + it * 256;
        int rr = idx >> 6, cc = idx & 63;
        Ks[rr * APAD + cc] = tf32r(kreg[it]);
        float vv = tf32r(vreg[it]);
        Vt[cc * APAD + rr] = vv;
        sv_local += vv;
    }
    __syncthreads();

    for (int kt = 0; kt < SEQ / 64; kt++) {
        // prefetch next KV tile into registers (overlaps with compute below)
        if (kt + 1 < SEQ / 64) {
            const int kstart = (kt + 1) * 64;
#pragma unroll
            for (int it = 0; it < 16; it++) {
                int idx = tid + it * 256;
                int rr = idx >> 6, cc = idx & 63;
                size_t gi = (rowbase + kstart + rr) * H3 + cc;
                kreg[it] = Kp[gi];
                vreg[it] = Vp[gi];
            }
        }

        // ---- S = Q K^T (warp tile 16q x 32kv) ----
        float sacc[4][4];
#pragma unroll
        for (int nt = 0; nt < 4; nt++)
#pragma unroll
            for (int u = 0; u < 4; u++) sacc[nt][u] = 0.0f;

#pragma unroll
        for (int ks = 0; ks < 8; ks++) {
            const uint32_t ko = ks * 32;
            uint32_t a0, a1, a2, a3;
            LDM_X4(a0, a1, a2, a3, qLane + ko);
#pragma unroll
            for (int np = 0; np < 2; np++) {
                uint32_t b0, b1, b2, b3;
                LDM_X4(b0, b1, b2, b3, kLane + np * (16 * APAD * 4) + ko);
                MMA_TF32(sacc[2 * np],     a0, a1, a2, a3, b0, b1);
                MMA_TF32(sacc[2 * np + 1], a0, a1, a2, a3, b2, b3);
            }
        }
        // scale + clamp, stage to Ss
#pragma unroll
        for (int nt = 0; nt < 4; nt++) {
            const int col = wn0 + nt * 8 + 2 * c;
            const int row = wq0 + r;
            float v0 = fminf(fmaxf(sacc[nt][0] * 0.125f, -1e9f), 1e9f);
            float v1 = fminf(fmaxf(sacc[nt][1] * 0.125f, -1e9f), 1e9f);
            float v2 = fminf(fmaxf(sacc[nt][2] * 0.125f, -1e9f), 1e9f);
            float v3 = fminf(fmaxf(sacc[nt][3] * 0.125f, -1e9f), 1e9f);
            *(float2*)&Ss[row * APAD + col]       = make_float2(v0, v1);
            *(float2*)&Ss[(row + 8) * APAD + col] = make_float2(v2, v3);
        }
        __syncthreads();

        // ---- online softmax: 4 threads per row, strided (conflict-free) ----
        {
            const int row = tid >> 2;
            const int p   = tid & 3;
            float* srow = &Ss[row * APAD];
            float mt = -1e30f;
#pragma unroll
            for (int j = 0; j < 16; j++) mt = fmaxf(mt, srow[p + 4 * j]);
            mt = fmaxf(mt, __shfl_xor_sync(0xffffffffu, mt, 1));
            mt = fmaxf(mt, __shfl_xor_sync(0xffffffffu, mt, 2));
            const float mo = m_s[row];
            mt = fmaxf(mt, mo);
            float sum = 0.0f;
#pragma unroll
            for (int j = 0; j < 16; j++) {
                float e = __expf(srow[p + 4 * j] - mt);
                srow[p + 4 * j] = tf32r(e);
                sum += e;
            }
            sum += __shfl_xor_sync(0xffffffffu, sum, 1);
            sum += __shfl_xor_sync(0xffffffffu, sum, 2);
            if (p == 0) {
                const float sc = __expf(mo - mt);
                m_s[row]  = mt;
                l_s[row]  = l_s[row] * sc + sum;
                sc_s[row] = sc;
            }
        }
        __syncthreads();

        // rescale accumulators
        {
            const float sc0 = sc_s[wq0 + r];
            const float sc1 = sc_s[wq0 + r + 8];
#pragma unroll
            for (int nt = 0; nt < 4; nt++) {
                oacc[nt][0] *= sc0; oacc[nt][1] *= sc0;
                oacc[nt][2] *= sc1; oacc[nt][3] *= sc1;
            }
        }

        // ---- O += P V (warp tile 16q x 32d) ----
#pragma unroll
        for (int ks = 0; ks < 8; ks++) {
            const uint32_t ko = ks * 32;
            uint32_t a0, a1, a2, a3;
            LDM_X4(a0, a1, a2, a3, sLane + ko);
#pragma unroll
            for (int np = 0; np < 2; np++) {
                uint32_t b0, b1, b2, b3;
                LDM_X4(b0, b1, b2, b3, vLane + np * (16 * APAD * 4) + ko);
                MMA_TF32(oacc[2 * np],     a0, a1, a2, a3, b0, b1);
                MMA_TF32(oacc[2 * np + 1], a0, a1, a2, a3, b2, b3);
            }
        }
        __syncthreads();   // all reads of Ks/Vt/Ss done

        // store prefetched tile kt+1
        if (kt + 1 < SEQ / 64) {
#pragma unroll
            for (int it = 0; it < 16; it++) {
                int idx = tid + it * 256;
                int rr = idx >> 6, cc = idx & 63;
                Ks[rr * APAD + cc] = tf32r(kreg[it]);
                float vv = tf32r(vreg[it]);
                Vt[cc * APAD + rr] = vv;
                sv_local += vv;
            }
            __syncthreads();
        }
    }

    // reduce colsum(V): 4 partials per d
    svr[(tid >> 6) * 64 + (tid & 63)] = sv_local;
    __syncthreads();
    if (tid < 64)
        sv_s[tid] = 1e-9f * (svr[tid] + svr[64 + tid] + svr[128 + tid] + svr[192 + tid]);
    __syncthreads();

    // epilogue
    {
        const float linv0 = 1.0f / l_s[wq0 + r];
        const float linv1 = 1.0f / l_s[wq0 + r + 8];
        const int row = qstart + wq0 + r;
#pragma unroll
        for (int nt = 0; nt < 4; nt++) {
            const int col = wn0 + nt * 8 + 2 * c;
            const float e0 = sv_s[col], e1 = sv_s[col + 1];
            float2 o0 = make_float2(oacc[nt][0] * linv0 + e0,
                                    oacc[nt][1] * linv0 + e1);
            float2 o1 = make_float2(oacc[nt][2] * linv1 + e0,
                                    oacc[nt][3] * linv1 + e1);
            *(float2*)&O[obase + (size_t)row * H + col]       = o0;
            *(float2*)&O[obase + (size_t)(row + 8) * H + col] = o1;
        }
    }
}

// ---------------------------------------------------------------------------
// Fused residual-add + LayerNorm (unchanged).
// ---------------------------------------------------------------------------
__global__ __launch_bounds__(256)
void add_ln_kernel(const float* __restrict__ A, const float* __restrict__ Bres,
                   const float* __restrict__ gam, const float* __restrict__ bet,
                   float* __restrict__ out)
{
    const int row = blockIdx.x;
    const int tid = threadIdx.x;
    const float4 va = ((const float4*)(A    + (size_t)row * H))[tid];
    const float4 vb = ((const float4*)(Bres + (size_t)row * H))[tid];
    float x0 = va.x + vb.x, x1 = va.y + vb.y, x2 = va.z + vb.z, x3 = va.w + vb.w;

    __shared__ float red[8];
    __shared__ float s_mu, s_rstd;

    float s = x0 + x1 + x2 + x3;
#pragma unroll
    for (int o = 16; o; o >>= 1) s += __shfl_down_sync(0xffffffffu, s, o);
    if ((tid & 31) == 0) red[tid >> 5] = s;
    __syncthreads();
    if (tid == 0) {
        float t = 0.f;
#pragma unroll
        for (int i = 0; i < 8; i++) t += red[i];
        s_mu = t * (1.0f / H);
    }
    __syncthreads();
    const float mu = s_mu;
    float d0 = x0 - mu, d1 = x1 - mu, d2 = x2 - mu, d3 = x3 - mu;
    float ss = d0 * d0 + d1 * d1 + d2 * d2 + d3 * d3;
#pragma unroll
    for (int o = 16; o; o >>= 1) ss += __shfl_down_sync(0xffffffffu, ss, o);
    __syncthreads();
    if ((tid & 31) == 0) red[tid >> 5] = ss;
    __syncthreads();
    if (tid == 0) {
        float t = 0.f;
#pragma unroll
        for (int i = 0; i < 8; i++) t += red[i];
        s_rstd = rsqrtf(t * (1.0f / H) + 1e-12f);
    }
    __syncthreads();
    const float rstd = s_rstd;

    const float4 g4 = ((const float4*)gam)[tid];
    const float4 b4 = ((const float4*)bet)[tid];
    float4 o;
    o.x = d0 * rstd * g4.x + b4.x;
    o.y = d1 * rstd * g4.y + b4.y;
    o.z = d2 * rstd * g4.z + b4.z;
    o.w = d3 * rstd * g4.w + b4.w;
    ((float4*)(out + (size_t)row * H))[tid] = o;
}

// ---------------------------------------------------------------------------
// Launch
// ---------------------------------------------------------------------------
extern "C" void kernel_launch(void* const* d_in, const int* in_sizes, int n_in,
                              void* d_out, int out_size)
{
    const float* hs   = (const float*)d_in[0];
    const float* Wq   = (const float*)d_in[1];
    const float* bq   = (const float*)d_in[2];
    const float* Wk   = (const float*)d_in[3];
    const float* bk   = (const float*)d_in[4];
    const float* Wv   = (const float*)d_in[5];
    const float* bv   = (const float*)d_in[6];
    const float* ln1g = (const float*)d_in[7];
    const float* ln1b = (const float*)d_in[8];
    const float* W1   = (const float*)d_in[9];
    const float* b1   = (const float*)d_in[10];
    const float* W2   = (const float*)d_in[11];
    const float* b2   = (const float*)d_in[12];
    const float* ln2g = (const float*)d_in[13];
    const float* ln2b = (const float*)d_in[14];
    float* out = (float*)d_out;

    static float *pqkv = nullptr, *pctx = nullptr, *px = nullptr,
                 *pinter = nullptr, *pffn = nullptr, *pwqkv = nullptr,
                 *pwt1 = nullptr, *pwt2 = nullptr, *pbqkv = nullptr;
    if (!pqkv) {  // first call is the (uncaptured) correctness run
        cudaGetSymbolAddress((void**)&pqkv,   g_qkv);
        cudaGetSymbolAddress((void**)&pctx,   g_ctx);
        cudaGetSymbolAddress((void**)&px,     g_x);
        cudaGetSymbolAddress((void**)&pinter, g_inter);
        cudaGetSymbolAddress((void**)&pffn,   g_ffn);
        cudaGetSymbolAddress((void**)&pwqkv,  g_wtqkv);
        cudaGetSymbolAddress((void**)&pwt1,   g_wt1);
        cudaGetSymbolAddress((void**)&pwt2,   g_wt2);
        cudaGetSymbolAddress((void**)&pbqkv,  g_bqkv);
        cudaFuncSetAttribute(attn_mma_kernel,
                             cudaFuncAttributeMaxDynamicSharedMemorySize, ATTN_SMEM);
    }

    // weight transposes (+ tf32 rounding) and bias concat
    transpose_tf32_k<<<dim3(H / 32, H / 32), 256>>>(Wq, pwqkv,             H, H);
    transpose_tf32_k<<<dim3(H / 32, H / 32), 256>>>(Wk, pwqkv + H * H,     H, H);
    transpose_tf32_k<<<dim3(H / 32, H / 32), 256>>>(Wv, pwqkv + 2 * H * H, H, H);
    transpose_tf32_k<<<dim3(FF / 32, H / 32), 256>>>(W1, pwt1, H, FF);
    transpose_tf32_k<<<dim3(H / 32, FF / 32), 256>>>(W2, pwt2, FF, H);
    concat_bias_k<<<H3 / 256, 256>>>(bq, bk, bv, pbqkv);

    // fused QKV projection (tf32 mma.sync, N=3072)
    mma_gemm<0><<<dim3(H3 / 128, BTOK / 128), 256>>>(hs, pwqkv, pbqkv, pqkv,
                                                     BTOK, H3, H);
    // attention -> ctx (tf32 mma.sync flash, reads fused QKV)
    attn_mma_kernel<<<dim3(SEQ / 64, 4 * NH), 256, ATTN_SMEM>>>(pqkv, pctx);
    // residual + LN1 -> x
    add_ln_kernel<<<BTOK, 256>>>(hs, pctx, ln1g, ln1b, px);
    // FFN (tf32 mma.sync)
    mma_gemm<1><<<dim3(FF / 128, BTOK / 128), 256>>>(px, pwt1, b1, pinter, BTOK, FF, H);
    mma_gemm<0><<<dim3(H / 128, BTOK / 128), 256>>>(pinter, pwt2, b2, pffn, BTOK, H, FF);
    // residual + LN2 -> out
    add_ln_kernel<<<BTOK, 256>>>(pffn, px, ln2g, ln2b, out);
}

// round 12
// speedup vs baseline: 3.1043x; 1.0239x over previous
#include <cuda_runtime.h>
#include <math.h>
#include <stdint.h>

#define H    1024
#define NH   16
#define HD   64
#define FF   4096
#define SEQ  2048
#define BTOK 8192   // 4 * 2048 tokens
#define H3   3072   // fused QKV width

// ---------------------------------------------------------------------------
// Scratch (static __device__ globals: allocation-free rule)
// ---------------------------------------------------------------------------
__device__ float g_qkv[(size_t)BTOK * H3];   // tf32-rounded Q|K|V
__device__ float g_ctx[BTOK * H];
__device__ float g_x[BTOK * H];
__device__ float g_inter[(size_t)BTOK * FF]; // tf32-rounded gelu output
__device__ float g_ffn[BTOK * H];
// transposed (tf32-rounded) weights
__device__ float g_wtqkv[(size_t)H3 * H];  // rows 0..1023 Wq^T, 1024.. Wk^T, 2048.. Wv^T
__device__ float g_wt1[(size_t)H * FF];    // [FF][H]
__device__ float g_wt2[(size_t)FF * H];    // [H][FF]
__device__ float g_bqkv[H3];

// ---------------------------------------------------------------------------
// Helpers
// ---------------------------------------------------------------------------
__device__ __forceinline__ uint32_t smem_u32(const void* p) {
    uint32_t a;
    asm("{ .reg .u64 t; cvta.to.shared.u64 t, %1; cvt.u32.u64 %0, t; }"
        : "=r"(a) : "l"(p));
    return a;
}
__device__ __forceinline__ float tf32r(float x) {
    uint32_t u;
    asm("cvt.rna.tf32.f32 %0, %1;" : "=r"(u) : "f"(x));
    return __uint_as_float(u);
}
__device__ __forceinline__ float gelu_exact(float x) {
    return 0.5f * x * (1.0f + erff(x * 0.70710678118654752f));
}

#define MMA_TF32(ACC, A0, A1, A2, A3, B0, B1)                                  \
    asm volatile(                                                              \
        "mma.sync.aligned.m16n8k8.row.col.f32.tf32.tf32.f32 "                  \
        "{%0,%1,%2,%3}, {%4,%5,%6,%7}, {%8,%9}, {%0,%1,%2,%3};"                \
        : "+f"((ACC)[0]), "+f"((ACC)[1]), "+f"((ACC)[2]), "+f"((ACC)[3])       \
        : "r"(A0), "r"(A1), "r"(A2), "r"(A3), "r"(B0), "r"(B1))

// ldmatrix x4: pure 128-bit row mover; tf32 bits pass through as b16 pairs.
#define LDM_X4(R0, R1, R2, R3, ADDR)                                           \
    asm volatile(                                                              \
        "ldmatrix.sync.aligned.m8n8.x4.shared.b16 {%0,%1,%2,%3}, [%4];"        \
        : "=r"(R0), "=r"(R1), "=r"(R2), "=r"(R3) : "r"(ADDR))

#define CP_ASYNC16(DST, SRC)                                                   \
    asm volatile("cp.async.cg.shared.global [%0], [%1], 16;"                   \
                 :: "r"(DST), "l"(SRC))
#define CP_COMMIT() asm volatile("cp.async.commit_group;" ::: "memory")
#define CP_WAIT0()  asm volatile("cp.async.wait_group 0;" ::: "memory")

// ---------------------------------------------------------------------------
// Weight transpose + tf32 rounding: W[K][N] -> Wt[N][K]
// ---------------------------------------------------------------------------
__global__ __launch_bounds__(256)
void transpose_tf32_k(const float* __restrict__ W, float* __restrict__ Wt,
                      int K, int N)
{
    __shared__ float t[32][33];
    const int tx = threadIdx.x & 31;
    const int ty = threadIdx.x >> 5;   // 0..7
    const int n0 = blockIdx.x * 32;
    const int k0 = blockIdx.y * 32;
#pragma unroll
    for (int i = 0; i < 4; i++) {
        int r = ty + i * 8;
        t[r][tx] = tf32r(W[(size_t)(k0 + r) * N + n0 + tx]);
    }
    __syncthreads();
#pragma unroll
    for (int i = 0; i < 4; i++) {
        int r = ty + i * 8;
        Wt[(size_t)(n0 + r) * K + k0 + tx] = t[tx][r];
    }
}

// concat bq|bk|bv -> g_bqkv
__global__ __launch_bounds__(256)
void concat_bias_k(const float* __restrict__ bq, const float* __restrict__ bk,
                   const float* __restrict__ bv, float* __restrict__ o)
{
    int t = threadIdx.x + blockIdx.x * 256;
    if (t < H) o[t] = bq[t];
    else if (t < 2 * H) o[t] = bk[t - H];
    else o[t] = bv[t - 2 * H];
}

// ---------------------------------------------------------------------------
// TF32 tensor-core GEMM: mma.sync.m16n8k8 + ldmatrix + cp.async staging.
// CTA tile 128x128, BK=16, 256 threads = 8 warps (4M x 2N), warp tile 32x64.
// Template: EPI 0=bias 1=gelu+clamp; AR 1=A pre-rounded (cp.async A);
//           RO 1=tf32-round the output.
// ---------------------------------------------------------------------------
#define BM 128
#define BN 128
#define BKG 16
#define PADK 20

template <int EPI, int AR, int RO>
__global__ __launch_bounds__(256)
void mma_gemm(const float* __restrict__ A, const float* __restrict__ Bt,
              const float* __restrict__ bias, float* __restrict__ C,
              int M, int N, int K)
{
    __shared__ __align__(16) float As[2][BM][PADK];
    __shared__ __align__(16) float Bs[2][BN][PADK];

    const int tid  = threadIdx.x;
    const int lane = tid & 31;
    const int wid  = tid >> 5;
    const int wm0  = (wid >> 1) * 32;   // 0,32,64,96
    const int wn0  = (wid & 1) * 64;    // 0,64
    const int r    = lane >> 2;         // 0..7
    const int c    = lane & 3;          // 0..3

    const int row0 = blockIdx.y * BM;
    const int col0 = blockIdx.x * BN;

    const int ldr = tid >> 2;           // 0..63
    const int ldc = (tid & 3) * 4;      // 0,4,8,12

    const float* Ap = A  + (size_t)(row0 + ldr) * K + ldc;
    const float* Bp = Bt + (size_t)(col0 + ldr) * K + ldc;
    const size_t stride64 = (size_t)64 * K;

    // staging smem addresses for this thread
    const uint32_t sA = smem_u32(&As[0][0][0]);
    const uint32_t sB = smem_u32(&Bs[0][0][0]);
    const uint32_t stsOff0 = (uint32_t)((ldr * PADK + ldc) * 4);
    const uint32_t stsOff1 = (uint32_t)(((ldr + 64) * PADK + ldc) * 4);
    const uint32_t bufStride = BM * PADK * 4;   // 10240

    // ldmatrix per-lane row addresses
    const int lr = lane & 7, lg = lane >> 3;
    const uint32_t aLane = sA +
        (uint32_t)(((wm0 + lr + 8 * (lg & 1)) * PADK + 4 * (lg >> 1)) * 4);
    const uint32_t bLane = sB +
        (uint32_t)(((wn0 + lr + 8 * (lg >> 1)) * PADK + 4 * (lg & 1)) * 4);

    float acc[2][8][4];
#pragma unroll
    for (int mt = 0; mt < 2; mt++)
#pragma unroll
        for (int nt = 0; nt < 8; nt++)
#pragma unroll
            for (int u = 0; u < 4; u++) acc[mt][nt][u] = 0.0f;

    float4 ra0, ra1;

    // prologue: stage 0
    CP_ASYNC16(sB + stsOff0, Bp);
    CP_ASYNC16(sB + stsOff1, Bp + stride64);
    if (AR) {
        CP_ASYNC16(sA + stsOff0, Ap);
        CP_ASYNC16(sA + stsOff1, Ap + stride64);
    } else {
        ra0 = *(const float4*)(Ap);
        ra1 = *(const float4*)(Ap + stride64);
        float4 t0 = make_float4(tf32r(ra0.x), tf32r(ra0.y), tf32r(ra0.z), tf32r(ra0.w));
        float4 t1 = make_float4(tf32r(ra1.x), tf32r(ra1.y), tf32r(ra1.z), tf32r(ra1.w));
        *(float4*)&As[0][ldr][ldc]      = t0;
        *(float4*)&As[0][ldr + 64][ldc] = t1;
    }
    CP_COMMIT();
    CP_WAIT0();
    __syncthreads();

    const int NS = K / BKG;
    for (int s = 0; s < NS; s++) {
        const int cur = s & 1;
        const uint32_t aCur = aLane + cur * bufStride;
        const uint32_t bCur = bLane + cur * bufStride;

        // issue next-stage async copies into the idle buffer
        if (s + 1 < NS) {
            const int k0 = (s + 1) * BKG;
            const int nxt = cur ^ 1;
            const uint32_t bo = nxt * bufStride;
            CP_ASYNC16(sB + bo + stsOff0, Bp + k0);
            CP_ASYNC16(sB + bo + stsOff1, Bp + stride64 + k0);
            if (AR) {
                CP_ASYNC16(sA + bo + stsOff0, Ap + k0);
                CP_ASYNC16(sA + bo + stsOff1, Ap + stride64 + k0);
            } else {
                ra0 = *(const float4*)(Ap + k0);
                ra1 = *(const float4*)(Ap + stride64 + k0);
            }
            CP_COMMIT();
        }

#pragma unroll
        for (int ks = 0; ks < 2; ks++) {
            const uint32_t ko = ks * 32;
            uint32_t af[2][4];
            LDM_X4(af[0][0], af[0][1], af[0][2], af[0][3], aCur + ko);
            LDM_X4(af[1][0], af[1][1], af[1][2], af[1][3],
                   aCur + 16 * PADK * 4 + ko);
#pragma unroll
            for (int np = 0; np < 4; np++) {
                uint32_t b0, b1, b2, b3;
                LDM_X4(b0, b1, b2, b3, bCur + np * (16 * PADK * 4) + ko);
                MMA_TF32(acc[0][2 * np],     af[0][0], af[0][1], af[0][2], af[0][3], b0, b1);
                MMA_TF32(acc[1][2 * np],     af[1][0], af[1][1], af[1][2], af[1][3], b0, b1);
                MMA_TF32(acc[0][2 * np + 1], af[0][0], af[0][1], af[0][2], af[0][3], b2, b3);
                MMA_TF32(acc[1][2 * np + 1], af[1][0], af[1][1], af[1][2], af[1][3], b2, b3);
            }
        }

        if (s + 1 < NS) {
            if (!AR) {
                const int nxt = cur ^ 1;
                float4 t0 = make_float4(tf32r(ra0.x), tf32r(ra0.y), tf32r(ra0.z), tf32r(ra0.w));
                float4 t1 = make_float4(tf32r(ra1.x), tf32r(ra1.y), tf32r(ra1.z), tf32r(ra1.w));
                *(float4*)&As[nxt][ldr][ldc]      = t0;
                *(float4*)&As[nxt][ldr + 64][ldc] = t1;
            }
            CP_WAIT0();
        }
        __syncthreads();
    }

#pragma unroll
    for (int mt = 0; mt < 2; mt++) {
        const int rowA = row0 + wm0 + mt * 16 + r;
#pragma unroll
        for (int nt = 0; nt < 8; nt++) {
            const int col = col0 + wn0 + nt * 8 + 2 * c;
            const float bz0 = bias[col];
            const float bz1 = bias[col + 1];
            float v0 = acc[mt][nt][0] + bz0;
            float v1 = acc[mt][nt][1] + bz1;
            float v2 = acc[mt][nt][2] + bz0;
            float v3 = acc[mt][nt][3] + bz1;
            if (EPI == 1) {
                v0 = fminf(fmaxf(gelu_exact(v0), -1e9f), 1e9f);
                v1 = fminf(fmaxf(gelu_exact(v1), -1e9f), 1e9f);
                v2 = fminf(fmaxf(gelu_exact(v2), -1e9f), 1e9f);
                v3 = fminf(fmaxf(gelu_exact(v3), -1e9f), 1e9f);
            }
            if (RO) {
                v0 = tf32r(v0); v1 = tf32r(v1); v2 = tf32r(v2); v3 = tf32r(v3);
            }
            *(float2*)(C + (size_t)rowA * N + col)       = make_float2(v0, v1);
            *(float2*)(C + (size_t)(rowA + 8) * N + col) = make_float2(v2, v3);
        }
    }
}

// ---------------------------------------------------------------------------
// Flash attention on tensor cores (mma.sync tf32 + ldmatrix).
// QKV buffer is pre-rounded to tf32 by the projection GEMM -> no cvts here.
// Block: 64 queries of one (b,h); 256 threads = 8 warps (4 qm x 2 n-half).
// ---------------------------------------------------------------------------
#define APAD 68
#define ATILE (64 * APAD)
#define ATTN_SMEM ((4 * ATILE + 3 * 64 + 256 + 64) * 4)

__global__ __launch_bounds__(256)
void attn_mma_kernel(const float* __restrict__ QKV, float* __restrict__ O)
{
    extern __shared__ __align__(16) float smf[];
    float* Qs    = smf;                   // [q][d]
    float* Ks    = smf + ATILE;           // [kv][d]
    float* Vt    = smf + 2 * ATILE;       // [d][kv]
    float* Ss    = smf + 3 * ATILE;       // [q][kv]
    float* m_s   = smf + 4 * ATILE;
    float* l_s   = m_s + 64;
    float* sc_s  = l_s + 64;
    float* svr   = sc_s + 64;             // [4][64] partial colsum(V)
    float* sv_s  = svr + 256;             // [64] final 1e-9*colsum

    const int tid  = threadIdx.x;
    const int lane = tid & 31;
    const int wid  = tid >> 5;
    const int wq0  = (wid >> 1) * 16;     // 0,16,32,48
    const int wn0  = (wid & 1) * 32;      // 0,32
    const int r    = lane >> 2;           // 0..7
    const int c    = lane & 3;            // 0..3

    const int bh = blockIdx.y;
    const int b  = bh >> 4;
    const int h  = bh & 15;
    const int qstart = blockIdx.x * 64;
    const size_t rowbase = (size_t)b * SEQ;
    const float* Qp = QKV + (size_t)h * HD;
    const float* Kp = Qp + H;
    const float* Vp = Qp + 2 * H;
    const size_t obase = (size_t)b * SEQ * H + (size_t)h * HD;

    // ldmatrix per-lane row addresses
    const int lr = lane & 7, lg = lane >> 3;
    const int aRow = wq0 + lr + 8 * (lg & 1);
    const int aKof = 4 * (lg >> 1);
    const int bRow = wn0 + lr + 8 * (lg >> 1);
    const int bKof = 4 * (lg & 1);
    const uint32_t qLane = smem_u32(Qs) + (uint32_t)((aRow * APAD + aKof) * 4);
    const uint32_t sLane = smem_u32(Ss) + (uint32_t)((aRow * APAD + aKof) * 4);
    const uint32_t kLane = smem_u32(Ks) + (uint32_t)((bRow * APAD + bKof) * 4);
    const uint32_t vLane = smem_u32(Vt) + (uint32_t)((bRow * APAD + bKof) * 4);

    float kreg[16], vreg[16];

    // load Q tile (pre-rounded) + prefetch KV tile 0
#pragma unroll
    for (int it = 0; it < 16; it++) {
        int idx = tid + it * 256;
        int rr = idx >> 6, cc = idx & 63;
        Qs[rr * APAD + cc] = Qp[(rowbase + qstart + rr) * H3 + cc];
        size_t gi = (rowbase + rr) * H3 + cc;
        kreg[it] = Kp[gi];
        vreg[it] = Vp[gi];
    }
    if (tid < 64) { m_s[tid] = -1e30f; l_s[tid] = 0.0f; }

    float oacc[4][4];
#pragma unroll
    for (int nt = 0; nt < 4; nt++)
#pragma unroll
        for (int u = 0; u < 4; u++) oacc[nt][u] = 0.0f;
    float sv_local = 0.0f;                // colsum(V) partial; d = tid&63 fixed

    __syncthreads();
    // store tile 0
#pragma unroll
    for (int it = 0; it < 16; it++) {
        int idx = tid + it * 256;
        int rr = idx >> 6, cc = idx & 63;
        Ks[rr * APAD + cc] = kreg[it];
        Vt[cc * APAD + rr] = vreg[it];
        sv_local += vreg[it];
    }
    __syncthreads();

    for (int kt = 0; kt < SEQ / 64; kt++) {
        // prefetch next KV tile into registers (overlaps with compute below)
        if (kt + 1 < SEQ / 64) {
            const int kstart = (kt + 1) * 64;
#pragma unroll
            for (int it = 0; it < 16; it++) {
                int idx = tid + it * 256;
                int rr = idx >> 6, cc = idx & 63;
                size_t gi = (rowbase + kstart + rr) * H3 + cc;
                kreg[it] = Kp[gi];
                vreg[it] = Vp[gi];
            }
        }

        // ---- S = Q K^T (warp tile 16q x 32kv) ----
        float sacc[4][4];
#pragma unroll
        for (int nt = 0; nt < 4; nt++)
#pragma unroll
            for (int u = 0; u < 4; u++) sacc[nt][u] = 0.0f;

#pragma unroll
        for (int ks = 0; ks < 8; ks++) {
            const uint32_t ko = ks * 32;
            uint32_t a0, a1, a2, a3;
            LDM_X4(a0, a1, a2, a3, qLane + ko);
#pragma unroll
            for (int np = 0; np < 2; np++) {
                uint32_t b0, b1, b2, b3;
                LDM_X4(b0, b1, b2, b3, kLane + np * (16 * APAD * 4) + ko);
                MMA_TF32(sacc[2 * np],     a0, a1, a2, a3, b0, b1);
                MMA_TF32(sacc[2 * np + 1], a0, a1, a2, a3, b2, b3);
            }
        }
        // scale + clamp, stage to Ss
#pragma unroll
        for (int nt = 0; nt < 4; nt++) {
            const int col = wn0 + nt * 8 + 2 * c;
            const int row = wq0 + r;
            float v0 = fminf(fmaxf(sacc[nt][0] * 0.125f, -1e9f), 1e9f);
            float v1 = fminf(fmaxf(sacc[nt][1] * 0.125f, -1e9f), 1e9f);
            float v2 = fminf(fmaxf(sacc[nt][2] * 0.125f, -1e9f), 1e9f);
            float v3 = fminf(fmaxf(sacc[nt][3] * 0.125f, -1e9f), 1e9f);
            *(float2*)&Ss[row * APAD + col]       = make_float2(v0, v1);
            *(float2*)&Ss[(row + 8) * APAD + col] = make_float2(v2, v3);
        }
        __syncthreads();

        // ---- online softmax: 4 threads per row, strided (conflict-free) ----
        {
            const int row = tid >> 2;
            const int p   = tid & 3;
            float* srow = &Ss[row * APAD];
            float mt = -1e30f;
#pragma unroll
            for (int j = 0; j < 16; j++) mt = fmaxf(mt, srow[p + 4 * j]);
            mt = fmaxf(mt, __shfl_xor_sync(0xffffffffu, mt, 1));
            mt = fmaxf(mt, __shfl_xor_sync(0xffffffffu, mt, 2));
            const float mo = m_s[row];
            mt = fmaxf(mt, mo);
            float sum = 0.0f;
#pragma unroll
            for (int j = 0; j < 16; j++) {
                float e = __expf(srow[p + 4 * j] - mt);
                srow[p + 4 * j] = tf32r(e);
                sum += e;
            }
            sum += __shfl_xor_sync(0xffffffffu, sum, 1);
            sum += __shfl_xor_sync(0xffffffffu, sum, 2);
            if (p == 0) {
                const float sc = __expf(mo - mt);
                m_s[row]  = mt;
                l_s[row]  = l_s[row] * sc + sum;
                sc_s[row] = sc;
            }
        }
        __syncthreads();

        // rescale accumulators
        {
            const float sc0 = sc_s[wq0 + r];
            const float sc1 = sc_s[wq0 + r + 8];
#pragma unroll
            for (int nt = 0; nt < 4; nt++) {
                oacc[nt][0] *= sc0; oacc[nt][1] *= sc0;
                oacc[nt][2] *= sc1; oacc[nt][3] *= sc1;
            }
        }

        // ---- O += P V (warp tile 16q x 32d) ----
#pragma unroll
        for (int ks = 0; ks < 8; ks++) {
            const uint32_t ko = ks * 32;
            uint32_t a0, a1, a2, a3;
            LDM_X4(a0, a1, a2, a3, sLane + ko);
#pragma unroll
            for (int np = 0; np < 2; np++) {
                uint32_t b0, b1, b2, b3;
                LDM_X4(b0, b1, b2, b3, vLane + np * (16 * APAD * 4) + ko);
                MMA_TF32(oacc[2 * np],     a0, a1, a2, a3, b0, b1);
                MMA_TF32(oacc[2 * np + 1], a0, a1, a2, a3, b2, b3);
            }
        }
        __syncthreads();   // all reads of Ks/Vt/Ss done

        // store prefetched tile kt+1
        if (kt + 1 < SEQ / 64) {
#pragma unroll
            for (int it = 0; it < 16; it++) {
                int idx = tid + it * 256;
                int rr = idx >> 6, cc = idx & 63;
                Ks[rr * APAD + cc] = kreg[it];
                Vt[cc * APAD + rr] = vreg[it];
                sv_local += vreg[it];
            }
            __syncthreads();
        }
    }

    // reduce colsum(V): 4 partials per d
    svr[(tid >> 6) * 64 + (tid & 63)] = sv_local;
    __syncthreads();
    if (tid < 64)
        sv_s[tid] = 1e-9f * (svr[tid] + svr[64 + tid] + svr[128 + tid] + svr[192 + tid]);
    __syncthreads();

    // epilogue
    {
        const float linv0 = 1.0f / l_s[wq0 + r];
        const float linv1 = 1.0f / l_s[wq0 + r + 8];
        const int row = qstart + wq0 + r;
#pragma unroll
        for (int nt = 0; nt < 4; nt++) {
            const int col = wn0 + nt * 8 + 2 * c;
            const float e0 = sv_s[col], e1 = sv_s[col + 1];
            float2 o0 = make_float2(oacc[nt][0] * linv0 + e0,
                                    oacc[nt][1] * linv0 + e1);
            float2 o1 = make_float2(oacc[nt][2] * linv1 + e0,
                                    oacc[nt][3] * linv1 + e1);
            *(float2*)&O[obase + (size_t)row * H + col]       = o0;
            *(float2*)&O[obase + (size_t)(row + 8) * H + col] = o1;
        }
    }
}

// ---------------------------------------------------------------------------
// Fused residual-add + LayerNorm (unchanged).
// ---------------------------------------------------------------------------
__global__ __launch_bounds__(256)
void add_ln_kernel(const float* __restrict__ A, const float* __restrict__ Bres,
                   const float* __restrict__ gam, const float* __restrict__ bet,
                   float* __restrict__ out)
{
    const int row = blockIdx.x;
    const int tid = threadIdx.x;
    const float4 va = ((const float4*)(A    + (size_t)row * H))[tid];
    const float4 vb = ((const float4*)(Bres + (size_t)row * H))[tid];
    float x0 = va.x + vb.x, x1 = va.y + vb.y, x2 = va.z + vb.z, x3 = va.w + vb.w;

    __shared__ float red[8];
    __shared__ float s_mu, s_rstd;

    float s = x0 + x1 + x2 + x3;
#pragma unroll
    for (int o = 16; o; o >>= 1) s += __shfl_down_sync(0xffffffffu, s, o);
    if ((tid & 31) == 0) red[tid >> 5] = s;
    __syncthreads();
    if (tid == 0) {
        float t = 0.f;
#pragma unroll
        for (int i = 0; i < 8; i++) t += red[i];
        s_mu = t * (1.0f / H);
    }
    __syncthreads();
    const float mu = s_mu;
    float d0 = x0 - mu, d1 = x1 - mu, d2 = x2 - mu, d3 = x3 - mu;
    float ss = d0 * d0 + d1 * d1 + d2 * d2 + d3 * d3;
#pragma unroll
    for (int o = 16; o; o >>= 1) ss += __shfl_down_sync(0xffffffffu, ss, o);
    __syncthreads();
    if ((tid & 31) == 0) red[tid >> 5] = ss;
    __syncthreads();
    if (tid == 0) {
        float t = 0.f;
#pragma unroll
        for (int i = 0; i < 8; i++) t += red[i];
        s_rstd = rsqrtf(t * (1.0f / H) + 1e-12f);
    }
    __syncthreads();
    const float rstd = s_rstd;

    const float4 g4 = ((const float4*)gam)[tid];
    const float4 b4 = ((const float4*)bet)[tid];
    float4 o;
    o.x = d0 * rstd * g4.x + b4.x;
    o.y = d1 * rstd * g4.y + b4.y;
    o.z = d2 * rstd * g4.z + b4.z;
    o.w = d3 * rstd * g4.w + b4.w;
    ((float4*)(out + (size_t)row * H))[tid] = o;
}

// ---------------------------------------------------------------------------
// Launch
// ---------------------------------------------------------------------------
extern "C" void kernel_launch(void* const* d_in, const int* in_sizes, int n_in,
                              void* d_out, int out_size)
{
    const float* hs   = (const float*)d_in[0];
    const float* Wq   = (const float*)d_in[1];
    const float* bq   = (const float*)d_in[2];
    const float* Wk   = (const float*)d_in[3];
    const float* bk   = (const float*)d_in[4];
    const float* Wv   = (const float*)d_in[5];
    const float* bv   = (const float*)d_in[6];
    const float* ln1g = (const float*)d_in[7];
    const float* ln1b = (const float*)d_in[8];
    const float* W1   = (const float*)d_in[9];
    const float* b1   = (const float*)d_in[10];
    const float* W2   = (const float*)d_in[11];
    const float* b2   = (const float*)d_in[12];
    const float* ln2g = (const float*)d_in[13];
    const float* ln2b = (const float*)d_in[14];
    float* out = (float*)d_out;

    static float *pqkv = nullptr, *pctx = nullptr, *px = nullptr,
                 *pinter = nullptr, *pffn = nullptr, *pwqkv = nullptr,
                 *pwt1 = nullptr, *pwt2 = nullptr, *pbqkv = nullptr;
    if (!pqkv) {  // first call is the (uncaptured) correctness run
        cudaGetSymbolAddress((void**)&pqkv,   g_qkv);
        cudaGetSymbolAddress((void**)&pctx,   g_ctx);
        cudaGetSymbolAddress((void**)&px,     g_x);
        cudaGetSymbolAddress((void**)&pinter, g_inter);
        cudaGetSymbolAddress((void**)&pffn,   g_ffn);
        cudaGetSymbolAddress((void**)&pwqkv,  g_wtqkv);
        cudaGetSymbolAddress((void**)&pwt1,   g_wt1);
        cudaGetSymbolAddress((void**)&pwt2,   g_wt2);
        cudaGetSymbolAddress((void**)&pbqkv,  g_bqkv);
        cudaFuncSetAttribute(attn_mma_kernel,
                             cudaFuncAttributeMaxDynamicSharedMemorySize, ATTN_SMEM);
    }

    // weight transposes (+ tf32 rounding) and bias concat
    transpose_tf32_k<<<dim3(H / 32, H / 32), 256>>>(Wq, pwqkv,             H, H);
    transpose_tf32_k<<<dim3(H / 32, H / 32), 256>>>(Wk, pwqkv + H * H,     H, H);
    transpose_tf32_k<<<dim3(H / 32, H / 32), 256>>>(Wv, pwqkv + 2 * H * H, H, H);
    transpose_tf32_k<<<dim3(FF / 32, H / 32), 256>>>(W1, pwt1, H, FF);
    transpose_tf32_k<<<dim3(H / 32, FF / 32), 256>>>(W2, pwt2, FF, H);
    concat_bias_k<<<H3 / 256, 256>>>(bq, bk, bv, pbqkv);

    // fused QKV projection -> tf32-rounded output (consumed only by attention)
    mma_gemm<0, 0, 1><<<dim3(H3 / 128, BTOK / 128), 256>>>(hs, pwqkv, pbqkv,
                                                           pqkv, BTOK, H3, H);
    // attention -> ctx
    attn_mma_kernel<<<dim3(SEQ / 64, 4 * NH), 256, ATTN_SMEM>>>(pqkv, pctx);
    // residual + LN1 -> x
    add_ln_kernel<<<BTOK, 256>>>(hs, pctx, ln1g, ln1b, px);
    // FFN1: gelu output tf32-rounded (consumed only by FFN2)
    mma_gemm<1, 0, 1><<<dim3(FF / 128, BTOK / 128), 256>>>(px, pwt1, b1,
                                                           pinter, BTOK, FF, H);
    // FFN2: A pre-rounded -> full cp.async staging
    mma_gemm<0, 1, 0><<<dim3(H / 128, BTOK / 128), 256>>>(pinter, pwt2, b2,
                                                          pffn, BTOK, H, FF);
    // residual + LN2 -> out
    add_ln_kernel<<<BTOK, 256>>>(pffn, px, ln2g, ln2b, out);
}

// round 13
// speedup vs baseline: 3.2768x; 1.0556x over previous
#include <cuda_runtime.h>
#include <math.h>
#include <stdint.h>

#define H    1024
#define NH   16
#define HD   64
#define FF   4096
#define SEQ  2048
#define BTOK 8192   // 4 * 2048 tokens
#define H3   3072   // fused QKV width
#define NT   (SEQ / 64)

// ---------------------------------------------------------------------------
// Scratch (static __device__ globals: allocation-free rule)
// ---------------------------------------------------------------------------
__device__ float g_qkv[(size_t)BTOK * H3];   // tf32-rounded Q|K|V
__device__ float g_vt[(size_t)64 * 64 * SEQ]; // V transposed: [bh][d][kv]
__device__ float g_svp[8 * 64 * 64];          // colsum(V) partials [part][bh][d]
__device__ float g_ctx[BTOK * H];
__device__ float g_x[BTOK * H];
__device__ float g_xr[BTOK * H];              // tf32-rounded LN1 output
__device__ float g_hsr[BTOK * H];             // tf32-rounded hidden_states
__device__ float g_inter[(size_t)BTOK * FF];  // tf32-rounded gelu output
__device__ float g_ffn[BTOK * H];
// transposed (tf32-rounded) weights
__device__ float g_wtqkv[(size_t)H3 * H];
__device__ float g_wt1[(size_t)H * FF];
__device__ float g_wt2[(size_t)FF * H];
__device__ float g_bqkv[H3];

// ---------------------------------------------------------------------------
// Helpers
// ---------------------------------------------------------------------------
__device__ __forceinline__ uint32_t smem_u32(const void* p) {
    uint32_t a;
    asm("{ .reg .u64 t; cvta.to.shared.u64 t, %1; cvt.u32.u64 %0, t; }"
        : "=r"(a) : "l"(p));
    return a;
}
__device__ __forceinline__ float tf32r(float x) {
    uint32_t u;
    asm("cvt.rna.tf32.f32 %0, %1;" : "=r"(u) : "f"(x));
    return __uint_as_float(u);
}
__device__ __forceinline__ float gelu_exact(float x) {
    return 0.5f * x * (1.0f + erff(x * 0.70710678118654752f));
}

#define MMA_TF32(ACC, A0, A1, A2, A3, B0, B1)                                  \
    asm volatile(                                                              \
        "mma.sync.aligned.m16n8k8.row.col.f32.tf32.tf32.f32 "                  \
        "{%0,%1,%2,%3}, {%4,%5,%6,%7}, {%8,%9}, {%0,%1,%2,%3};"                \
        : "+f"((ACC)[0]), "+f"((ACC)[1]), "+f"((ACC)[2]), "+f"((ACC)[3])       \
        : "r"(A0), "r"(A1), "r"(A2), "r"(A3), "r"(B0), "r"(B1))

#define LDM_X4(R0, R1, R2, R3, ADDR)                                           \
    asm volatile(                                                              \
        "ldmatrix.sync.aligned.m8n8.x4.shared.b16 {%0,%1,%2,%3}, [%4];"        \
        : "=r"(R0), "=r"(R1), "=r"(R2), "=r"(R3) : "r"(ADDR))

#define CP_ASYNC16(DST, SRC)                                                   \
    asm volatile("cp.async.cg.shared.global [%0], [%1], 16;"                   \
                 :: "r"(DST), "l"(SRC))
#define CP_COMMIT() asm volatile("cp.async.commit_group;" ::: "memory")
#define CP_WAIT0()  asm volatile("cp.async.wait_group 0;" ::: "memory")
#define CP_WAIT1()  asm volatile("cp.async.wait_group 1;" ::: "memory")

// ---------------------------------------------------------------------------
// Weight transpose + tf32 rounding: W[K][N] -> Wt[N][K]
// ---------------------------------------------------------------------------
__global__ __launch_bounds__(256)
void transpose_tf32_k(const float* __restrict__ W, float* __restrict__ Wt,
                      int K, int N)
{
    __shared__ float t[32][33];
    const int tx = threadIdx.x & 31;
    const int ty = threadIdx.x >> 5;
    const int n0 = blockIdx.x * 32;
    const int k0 = blockIdx.y * 32;
#pragma unroll
    for (int i = 0; i < 4; i++) {
        int r = ty + i * 8;
        t[r][tx] = tf32r(W[(size_t)(k0 + r) * N + n0 + tx]);
    }
    __syncthreads();
#pragma unroll
    for (int i = 0; i < 4; i++) {
        int r = ty + i * 8;
        Wt[(size_t)(n0 + r) * K + k0 + tx] = t[tx][r];
    }
}

// concat bq|bk|bv -> g_bqkv
__global__ __launch_bounds__(256)
void concat_bias_k(const float* __restrict__ bq, const float* __restrict__ bk,
                   const float* __restrict__ bv, float* __restrict__ o)
{
    int t = threadIdx.x + blockIdx.x * 256;
    if (t < H) o[t] = bq[t];
    else if (t < 2 * H) o[t] = bk[t - H];
    else o[t] = bv[t - 2 * H];
}

// elementwise tf32 round (float4)
__global__ __launch_bounds__(256)
void round_tf32_k(const float* __restrict__ x, float* __restrict__ y)
{
    int i = blockIdx.x * 256 + threadIdx.x;
    float4 v = ((const float4*)x)[i];
    ((float4*)y)[i] = make_float4(tf32r(v.x), tf32r(v.y), tf32r(v.z), tf32r(v.w));
}

// V transpose: g_qkv V region -> VT[bh][d][kv]
__global__ __launch_bounds__(256)
void vt_transpose_k(const float* __restrict__ QKV, float* __restrict__ VT)
{
    __shared__ float t[32][33];
    const int bh = blockIdx.z;
    const int b = bh >> 4, h = bh & 15;
    const int kv0 = blockIdx.x * 32;
    const int d0  = blockIdx.y * 32;
    const int tx = threadIdx.x & 31;
    const int ty = threadIdx.x >> 5;
    const float* src = QKV + (size_t)b * SEQ * H3 + 2 * H + h * HD;
#pragma unroll
    for (int i = 0; i < 4; i++) {
        int kv = kv0 + ty + i * 8;
        t[ty + i * 8][tx] = src[(size_t)kv * H3 + d0 + tx];
    }
    __syncthreads();
    float* dst = VT + (size_t)bh * 64 * SEQ;
#pragma unroll
    for (int i = 0; i < 4; i++) {
        int d = d0 + ty + i * 8;
        dst[(size_t)d * SEQ + kv0 + tx] = t[tx][ty + i * 8];
    }
}

// colsum(V) partials: SVP[part][bh][d] = sum_{kv in part} V[kv][d]
__global__ __launch_bounds__(64)
void sv_partial_k(const float* __restrict__ QKV, float* __restrict__ SVP)
{
    const int bh = blockIdx.x, part = blockIdx.y;
    const int b = bh >> 4, h = bh & 15;
    const int d = threadIdx.x;
    const float* src = QKV + (size_t)(b * SEQ + part * 256) * H3 + 2 * H + h * HD + d;
    float s = 0.0f;
    for (int kv = 0; kv < 256; kv++) s += src[(size_t)kv * H3];
    SVP[(part * 64 + bh) * 64 + d] = s;
}

// ---------------------------------------------------------------------------
// TF32 tensor-core GEMM: mma.sync.m16n8k8 + ldmatrix + cp.async staging.
// Template: EPI 0=bias 1=gelu+clamp; AR 1=A pre-rounded (cp.async A);
//           RO 1=tf32-round the output.
// ---------------------------------------------------------------------------
#define BM 128
#define BN 128
#define BKG 16
#define PADK 20

template <int EPI, int AR, int RO>
__global__ __launch_bounds__(256)
void mma_gemm(const float* __restrict__ A, const float* __restrict__ Bt,
              const float* __restrict__ bias, float* __restrict__ C,
              int M, int N, int K)
{
    __shared__ __align__(16) float As[2][BM][PADK];
    __shared__ __align__(16) float Bs[2][BN][PADK];

    const int tid  = threadIdx.x;
    const int lane = tid & 31;
    const int wid  = tid >> 5;
    const int wm0  = (wid >> 1) * 32;
    const int wn0  = (wid & 1) * 64;
    const int r    = lane >> 2;
    const int c    = lane & 3;

    const int row0 = blockIdx.y * BM;
    const int col0 = blockIdx.x * BN;

    const int ldr = tid >> 2;
    const int ldc = (tid & 3) * 4;

    const float* Ap = A  + (size_t)(row0 + ldr) * K + ldc;
    const float* Bp = Bt + (size_t)(col0 + ldr) * K + ldc;
    const size_t stride64 = (size_t)64 * K;

    const uint32_t sA = smem_u32(&As[0][0][0]);
    const uint32_t sB = smem_u32(&Bs[0][0][0]);
    const uint32_t stsOff0 = (uint32_t)((ldr * PADK + ldc) * 4);
    const uint32_t stsOff1 = (uint32_t)(((ldr + 64) * PADK + ldc) * 4);
    const uint32_t bufStride = BM * PADK * 4;

    const int lr = lane & 7, lg = lane >> 3;
    const uint32_t aLane = sA +
        (uint32_t)(((wm0 + lr + 8 * (lg & 1)) * PADK + 4 * (lg >> 1)) * 4);
    const uint32_t bLane = sB +
        (uint32_t)(((wn0 + lr + 8 * (lg >> 1)) * PADK + 4 * (lg & 1)) * 4);

    float acc[2][8][4];
#pragma unroll
    for (int mt = 0; mt < 2; mt++)
#pragma unroll
        for (int nt = 0; nt < 8; nt++)
#pragma unroll
            for (int u = 0; u < 4; u++) acc[mt][nt][u] = 0.0f;

    float4 ra0, ra1;

    CP_ASYNC16(sB + stsOff0, Bp);
    CP_ASYNC16(sB + stsOff1, Bp + stride64);
    if (AR) {
        CP_ASYNC16(sA + stsOff0, Ap);
        CP_ASYNC16(sA + stsOff1, Ap + stride64);
    } else {
        ra0 = *(const float4*)(Ap);
        ra1 = *(const float4*)(Ap + stride64);
        float4 t0 = make_float4(tf32r(ra0.x), tf32r(ra0.y), tf32r(ra0.z), tf32r(ra0.w));
        float4 t1 = make_float4(tf32r(ra1.x), tf32r(ra1.y), tf32r(ra1.z), tf32r(ra1.w));
        *(float4*)&As[0][ldr][ldc]      = t0;
        *(float4*)&As[0][ldr + 64][ldc] = t1;
    }
    CP_COMMIT();
    CP_WAIT0();
    __syncthreads();

    const int NS = K / BKG;
    for (int s = 0; s < NS; s++) {
        const int cur = s & 1;
        const uint32_t aCur = aLane + cur * bufStride;
        const uint32_t bCur = bLane + cur * bufStride;

        if (s + 1 < NS) {
            const int k0 = (s + 1) * BKG;
            const int nxt = cur ^ 1;
            const uint32_t bo = nxt * bufStride;
            CP_ASYNC16(sB + bo + stsOff0, Bp + k0);
            CP_ASYNC16(sB + bo + stsOff1, Bp + stride64 + k0);
            if (AR) {
                CP_ASYNC16(sA + bo + stsOff0, Ap + k0);
                CP_ASYNC16(sA + bo + stsOff1, Ap + stride64 + k0);
            } else {
                ra0 = *(const float4*)(Ap + k0);
                ra1 = *(const float4*)(Ap + stride64 + k0);
            }
            CP_COMMIT();
        }

#pragma unroll
        for (int ks = 0; ks < 2; ks++) {
            const uint32_t ko = ks * 32;
            uint32_t af[2][4];
            LDM_X4(af[0][0], af[0][1], af[0][2], af[0][3], aCur + ko);
            LDM_X4(af[1][0], af[1][1], af[1][2], af[1][3],
                   aCur + 16 * PADK * 4 + ko);
#pragma unroll
            for (int np = 0; np < 4; np++) {
                uint32_t b0, b1, b2, b3;
                LDM_X4(b0, b1, b2, b3, bCur + np * (16 * PADK * 4) + ko);
                MMA_TF32(acc[0][2 * np],     af[0][0], af[0][1], af[0][2], af[0][3], b0, b1);
                MMA_TF32(acc[1][2 * np],     af[1][0], af[1][1], af[1][2], af[1][3], b0, b1);
                MMA_TF32(acc[0][2 * np + 1], af[0][0], af[0][1], af[0][2], af[0][3], b2, b3);
                MMA_TF32(acc[1][2 * np + 1], af[1][0], af[1][1], af[1][2], af[1][3], b2, b3);
            }
        }

        if (s + 1 < NS) {
            if (!AR) {
                const int nxt = cur ^ 1;
                float4 t0 = make_float4(tf32r(ra0.x), tf32r(ra0.y), tf32r(ra0.z), tf32r(ra0.w));
                float4 t1 = make_float4(tf32r(ra1.x), tf32r(ra1.y), tf32r(ra1.z), tf32r(ra1.w));
                *(float4*)&As[nxt][ldr][ldc]      = t0;
                *(float4*)&As[nxt][ldr + 64][ldc] = t1;
            }
            CP_WAIT0();
        }
        __syncthreads();
    }

#pragma unroll
    for (int mt = 0; mt < 2; mt++) {
        const int rowA = row0 + wm0 + mt * 16 + r;
#pragma unroll
        for (int nt = 0; nt < 8; nt++) {
            const int col = col0 + wn0 + nt * 8 + 2 * c;
            const float bz0 = bias[col];
            const float bz1 = bias[col + 1];
            float v0 = acc[mt][nt][0] + bz0;
            float v1 = acc[mt][nt][1] + bz1;
            float v2 = acc[mt][nt][2] + bz0;
            float v3 = acc[mt][nt][3] + bz1;
            if (EPI == 1) {
                v0 = fminf(fmaxf(gelu_exact(v0), -1e9f), 1e9f);
                v1 = fminf(fmaxf(gelu_exact(v1), -1e9f), 1e9f);
                v2 = fminf(fmaxf(gelu_exact(v2), -1e9f), 1e9f);
                v3 = fminf(fmaxf(gelu_exact(v3), -1e9f), 1e9f);
            }
            if (RO) {
                v0 = tf32r(v0); v1 = tf32r(v1); v2 = tf32r(v2); v3 = tf32r(v3);
            }
            *(float2*)(C + (size_t)rowA * N + col)       = make_float2(v0, v1);
            *(float2*)(C + (size_t)(rowA + 8) * N + col) = make_float2(v2, v3);
        }
    }
}

// ---------------------------------------------------------------------------
// Flash attention: mma.sync tf32 + ldmatrix, pure cp.async staging.
// Q,K from pre-rounded QKV buffer; V from pre-transposed VT; colsum(V) from SVP.
// Block: 64 queries of one (b,h); 256 threads = 8 warps (4 qm x 2 n-half).
// K/VT tiles double-buffered (commit/wait_group pipeline).
// ---------------------------------------------------------------------------
#define APAD 68
#define ATILE (64 * APAD)
#define ATTN_SMEM ((6 * ATILE + 4 * 64) * 4)

__global__ __launch_bounds__(256)
void attn_mma_kernel(const float* __restrict__ QKV, const float* __restrict__ VT,
                     const float* __restrict__ SVP, float* __restrict__ O)
{
    extern __shared__ __align__(16) float smf[];
    float* Qs   = smf;                    // [q][d]
    float* Ks   = smf + ATILE;            // [2][kv][d]
    float* Vt   = smf + 3 * ATILE;        // [2][d][kv]
    float* Ss   = smf + 5 * ATILE;        // [q][kv]
    float* m_s  = smf + 6 * ATILE;
    float* l_s  = m_s + 64;
    float* sc_s = l_s + 64;
    float* sv_s = sc_s + 64;

    const int tid  = threadIdx.x;
    const int lane = tid & 31;
    const int wid  = tid >> 5;
    const int wq0  = (wid >> 1) * 16;
    const int wn0  = (wid & 1) * 32;
    const int r    = lane >> 2;
    const int c    = lane & 3;

    const int bh = blockIdx.y;
    const int b  = bh >> 4;
    const int h  = bh & 15;
    const int qstart = blockIdx.x * 64;
    const size_t rowbase = (size_t)b * SEQ;
    const float* Qg = QKV + (size_t)h * HD;
    const float* Kg = QKV + H + (size_t)h * HD;
    const float* Vg = VT + (size_t)bh * 64 * SEQ;
    const size_t obase = (size_t)b * SEQ * H + (size_t)h * HD;

    // cp.async chunk mapping: 1024 chunks of 16B per 64x64 tile
    const int crow = tid >> 2;          // using idx = tid + it*256: row = idx>>4
    (void)crow;

    const uint32_t sQ = smem_u32(Qs);
    const uint32_t sK = smem_u32(Ks);
    const uint32_t sV = smem_u32(Vt);

    // ldmatrix per-lane addresses
    const int lr = lane & 7, lg = lane >> 3;
    const int aRow = wq0 + lr + 8 * (lg & 1);
    const int aKof = 4 * (lg >> 1);
    const int bRow = wn0 + lr + 8 * (lg >> 1);
    const int bKof = 4 * (lg & 1);
    const uint32_t qLane = sQ + (uint32_t)((aRow * APAD + aKof) * 4);
    const uint32_t sLane = smem_u32(Ss) + (uint32_t)((aRow * APAD + aKof) * 4);
    const uint32_t kLane = sK + (uint32_t)((bRow * APAD + bKof) * 4);
    const uint32_t vLane = sV + (uint32_t)((bRow * APAD + bKof) * 4);

    // ---- prologue: Q + tiles 0,1 via cp.async ----
#pragma unroll
    for (int it = 0; it < 4; it++) {
        const int idx = tid + it * 256;
        const int row = idx >> 4, ch = idx & 15;
        const uint32_t dsto = (uint32_t)((row * APAD + ch * 4) * 4);
        CP_ASYNC16(sQ + dsto, Qg + (rowbase + qstart + row) * H3 + ch * 4);
        CP_ASYNC16(sK + dsto, Kg + (rowbase + row) * H3 + ch * 4);
        CP_ASYNC16(sV + dsto, Vg + (size_t)row * SEQ + ch * 4);
    }
    CP_COMMIT();
#pragma unroll
    for (int it = 0; it < 4; it++) {
        const int idx = tid + it * 256;
        const int row = idx >> 4, ch = idx & 15;
        const uint32_t dsto = (uint32_t)((row * APAD + ch * 4) * 4) + ATILE * 4;
        CP_ASYNC16(sK + dsto, Kg + (rowbase + 64 + row) * H3 + ch * 4);
        CP_ASYNC16(sV + dsto, Vg + (size_t)row * SEQ + 64 + ch * 4);
    }
    CP_COMMIT();
    CP_WAIT1();

    if (tid < 64) {
        m_s[tid] = -1e30f;
        l_s[tid] = 0.0f;
        float s = 0.0f;
#pragma unroll
        for (int p = 0; p < 8; p++) s += SVP[(p * 64 + bh) * 64 + tid];
        sv_s[tid] = 1e-9f * s;
    }

    float oacc[4][4];
#pragma unroll
    for (int nt = 0; nt < 4; nt++)
#pragma unroll
        for (int u = 0; u < 4; u++) oacc[nt][u] = 0.0f;

    __syncthreads();

    for (int kt = 0; kt < NT; kt++) {
        const int cur = kt & 1;
        const uint32_t kCur = kLane + cur * (ATILE * 4);
        const uint32_t vCur = vLane + cur * (ATILE * 4);

        // ---- S = Q K^T ----
        float sacc[4][4];
#pragma unroll
        for (int nt = 0; nt < 4; nt++)
#pragma unroll
            for (int u = 0; u < 4; u++) sacc[nt][u] = 0.0f;

#pragma unroll
        for (int ks = 0; ks < 8; ks++) {
            const uint32_t ko = ks * 32;
            uint32_t a0, a1, a2, a3;
            LDM_X4(a0, a1, a2, a3, qLane + ko);
#pragma unroll
            for (int np = 0; np < 2; np++) {
                uint32_t b0, b1, b2, b3;
                LDM_X4(b0, b1, b2, b3, kCur + np * (16 * APAD * 4) + ko);
                MMA_TF32(sacc[2 * np],     a0, a1, a2, a3, b0, b1);
                MMA_TF32(sacc[2 * np + 1], a0, a1, a2, a3, b2, b3);
            }
        }
#pragma unroll
        for (int nt = 0; nt < 4; nt++) {
            const int col = wn0 + nt * 8 + 2 * c;
            const int row = wq0 + r;
            float v0 = fminf(fmaxf(sacc[nt][0] * 0.125f, -1e9f), 1e9f);
            float v1 = fminf(fmaxf(sacc[nt][1] * 0.125f, -1e9f), 1e9f);
            float v2 = fminf(fmaxf(sacc[nt][2] * 0.125f, -1e9f), 1e9f);
            float v3 = fminf(fmaxf(sacc[nt][3] * 0.125f, -1e9f), 1e9f);
            *(float2*)&Ss[row * APAD + col]       = make_float2(v0, v1);
            *(float2*)&Ss[(row + 8) * APAD + col] = make_float2(v2, v3);
        }
        __syncthreads();

        // ---- online softmax: 4 threads per row ----
        {
            const int row = tid >> 2;
            const int p   = tid & 3;
            float* srow = &Ss[row * APAD];
            float mt = -1e30f;
#pragma unroll
            for (int j = 0; j < 16; j++) mt = fmaxf(mt, srow[p + 4 * j]);
            mt = fmaxf(mt, __shfl_xor_sync(0xffffffffu, mt, 1));
            mt = fmaxf(mt, __shfl_xor_sync(0xffffffffu, mt, 2));
            const float mo = m_s[row];
            mt = fmaxf(mt, mo);
            float sum = 0.0f;
#pragma unroll
            for (int j = 0; j < 16; j++) {
                float e = __expf(srow[p + 4 * j] - mt);
                srow[p + 4 * j] = tf32r(e);
                sum += e;
            }
            sum += __shfl_xor_sync(0xffffffffu, sum, 1);
            sum += __shfl_xor_sync(0xffffffffu, sum, 2);
            if (p == 0) {
                const float sc = __expf(mo - mt);
                m_s[row]  = mt;
                l_s[row]  = l_s[row] * sc + sum;
                sc_s[row] = sc;
            }
        }
        __syncthreads();

        // rescale accumulators
        {
            const float sc0 = sc_s[wq0 + r];
            const float sc1 = sc_s[wq0 + r + 8];
#pragma unroll
            for (int nt = 0; nt < 4; nt++) {
                oacc[nt][0] *= sc0; oacc[nt][1] *= sc0;
                oacc[nt][2] *= sc1; oacc[nt][3] *= sc1;
            }
        }

        // ---- O += P V ----
#pragma unroll
        for (int ks = 0; ks < 8; ks++) {
            const uint32_t ko = ks * 32;
            uint32_t a0, a1, a2, a3;
            LDM_X4(a0, a1, a2, a3, sLane + ko);
#pragma unroll
            for (int np = 0; np < 2; np++) {
                uint32_t b0, b1, b2, b3;
                LDM_X4(b0, b1, b2, b3, vCur + np * (16 * APAD * 4) + ko);
                MMA_TF32(oacc[2 * np],     a0, a1, a2, a3, b0, b1);
                MMA_TF32(oacc[2 * np + 1], a0, a1, a2, a3, b2, b3);
            }
        }
        __syncthreads();   // all reads of buffer cur done

        // prefetch tile kt+2 into buffer cur
        if (kt + 2 < NT) {
            const int kstart = (kt + 2) * 64;
            const uint32_t bo = cur * (ATILE * 4);
#pragma unroll
            for (int it = 0; it < 4; it++) {
                const int idx = tid + it * 256;
                const int row = idx >> 4, ch = idx & 15;
                const uint32_t dsto = (uint32_t)((row * APAD + ch * 4) * 4) + bo;
                CP_ASYNC16(sK + dsto, Kg + (rowbase + kstart + row) * H3 + ch * 4);
                CP_ASYNC16(sV + dsto, Vg + (size_t)row * SEQ + kstart + ch * 4);
            }
            CP_COMMIT();
            CP_WAIT1();
        } else {
            CP_WAIT0();
        }
        __syncthreads();
    }

    // epilogue
    {
        const float linv0 = 1.0f / l_s[wq0 + r];
        const float linv1 = 1.0f / l_s[wq0 + r + 8];
        const int row = qstart + wq0 + r;
#pragma unroll
        for (int nt = 0; nt < 4; nt++) {
            const int col = wn0 + nt * 8 + 2 * c;
            const float e0 = sv_s[col], e1 = sv_s[col + 1];
            float2 o0 = make_float2(oacc[nt][0] * linv0 + e0,
                                    oacc[nt][1] * linv0 + e1);
            float2 o1 = make_float2(oacc[nt][2] * linv1 + e0,
                                    oacc[nt][3] * linv1 + e1);
            *(float2*)&O[obase + (size_t)row * H + col]       = o0;
            *(float2*)&O[obase + (size_t)(row + 8) * H + col] = o1;
        }
    }
}

// ---------------------------------------------------------------------------
// Fused residual-add + LayerNorm; optional second tf32-rounded output.
// ---------------------------------------------------------------------------
template <int WR>
__global__ __launch_bounds__(256)
void add_ln_kernel(const float* __restrict__ A, const float* __restrict__ Bres,
                   const float* __restrict__ gam, const float* __restrict__ bet,
                   float* __restrict__ out, float* __restrict__ out_r)
{
    const int row = blockIdx.x;
    const int tid = threadIdx.x;
    const float4 va = ((const float4*)(A    + (size_t)row * H))[tid];
    const float4 vb = ((const float4*)(Bres + (size_t)row * H))[tid];
    float x0 = va.x + vb.x, x1 = va.y + vb.y, x2 = va.z + vb.z, x3 = va.w + vb.w;

    __shared__ float red[8];
    __shared__ float s_mu, s_rstd;

    float s = x0 + x1 + x2 + x3;
#pragma unroll
    for (int o = 16; o; o >>= 1) s += __shfl_down_sync(0xffffffffu, s, o);
    if ((tid & 31) == 0) red[tid >> 5] = s;
    __syncthreads();
    if (tid == 0) {
        float t = 0.f;
#pragma unroll
        for (int i = 0; i < 8; i++) t += red[i];
        s_mu = t * (1.0f / H);
    }
    __syncthreads();
    const float mu = s_mu;
    float d0 = x0 - mu, d1 = x1 - mu, d2 = x2 - mu, d3 = x3 - mu;
    float ss = d0 * d0 + d1 * d1 + d2 * d2 + d3 * d3;
#pragma unroll
    for (int o = 16; o; o >>= 1) ss += __shfl_down_sync(0xffffffffu, ss, o);
    __syncthreads();
    if ((tid & 31) == 0) red[tid >> 5] = ss;
    __syncthreads();
    if (tid == 0) {
        float t = 0.f;
#pragma unroll
        for (int i = 0; i < 8; i++) t += red[i];
        s_rstd = rsqrtf(t * (1.0f / H) + 1e-12f);
    }
    __syncthreads();
    const float rstd = s_rstd;

    const float4 g4 = ((const float4*)gam)[tid];
    const float4 b4 = ((const float4*)bet)[tid];
    float4 o;
    o.x = d0 * rstd * g4.x + b4.x;
    o.y = d1 * rstd * g4.y + b4.y;
    o.z = d2 * rstd * g4.z + b4.z;
    o.w = d3 * rstd * g4.w + b4.w;
    ((float4*)(out + (size_t)row * H))[tid] = o;
    if (WR) {
        float4 orr = make_float4(tf32r(o.x), tf32r(o.y), tf32r(o.z), tf32r(o.w));
        ((float4*)(out_r + (size_t)row * H))[tid] = orr;
    }
}

// ---------------------------------------------------------------------------
// Launch
// ---------------------------------------------------------------------------
extern "C" void kernel_launch(void* const* d_in, const int* in_sizes, int n_in,
                              void* d_out, int out_size)
{
    const float* hs   = (const float*)d_in[0];
    const float* Wq   = (const float*)d_in[1];
    const float* bq   = (const float*)d_in[2];
    const float* Wk   = (const float*)d_in[3];
    const float* bk   = (const float*)d_in[4];
    const float* Wv   = (const float*)d_in[5];
    const float* bv   = (const float*)d_in[6];
    const float* ln1g = (const float*)d_in[7];
    const float* ln1b = (const float*)d_in[8];
    const float* W1   = (const float*)d_in[9];
    const float* b1   = (const float*)d_in[10];
    const float* W2   = (const float*)d_in[11];
    const float* b2   = (const float*)d_in[12];
    const float* ln2g = (const float*)d_in[13];
    const float* ln2b = (const float*)d_in[14];
    float* out = (float*)d_out;

    static float *pqkv = nullptr, *pvt = nullptr, *psvp = nullptr,
                 *pctx = nullptr, *px = nullptr, *pxr = nullptr,
                 *phsr = nullptr, *pinter = nullptr, *pffn = nullptr,
                 *pwqkv = nullptr, *pwt1 = nullptr, *pwt2 = nullptr,
                 *pbqkv = nullptr;
    if (!pqkv) {  // first call is the (uncaptured) correctness run
        cudaGetSymbolAddress((void**)&pqkv,   g_qkv);
        cudaGetSymbolAddress((void**)&pvt,    g_vt);
        cudaGetSymbolAddress((void**)&psvp,   g_svp);
        cudaGetSymbolAddress((void**)&pctx,   g_ctx);
        cudaGetSymbolAddress((void**)&px,     g_x);
        cudaGetSymbolAddress((void**)&pxr,    g_xr);
        cudaGetSymbolAddress((void**)&phsr,   g_hsr);
        cudaGetSymbolAddress((void**)&pinter, g_inter);
        cudaGetSymbolAddress((void**)&pffn,   g_ffn);
        cudaGetSymbolAddress((void**)&pwqkv,  g_wtqkv);
        cudaGetSymbolAddress((void**)&pwt1,   g_wt1);
        cudaGetSymbolAddress((void**)&pwt2,   g_wt2);
        cudaGetSymbolAddress((void**)&pbqkv,  g_bqkv);
        cudaFuncSetAttribute(attn_mma_kernel,
                             cudaFuncAttributeMaxDynamicSharedMemorySize, ATTN_SMEM);
    }

    // prep: weight transposes, bias concat, input rounding
    transpose_tf32_k<<<dim3(H / 32, H / 32), 256>>>(Wq, pwqkv,             H, H);
    transpose_tf32_k<<<dim3(H / 32, H / 32), 256>>>(Wk, pwqkv + H * H,     H, H);
    transpose_tf32_k<<<dim3(H / 32, H / 32), 256>>>(Wv, pwqkv + 2 * H * H, H, H);
    transpose_tf32_k<<<dim3(FF / 32, H / 32), 256>>>(W1, pwt1, H, FF);
    transpose_tf32_k<<<dim3(H / 32, FF / 32), 256>>>(W2, pwt2, FF, H);
    concat_bias_k<<<H3 / 256, 256>>>(bq, bk, bv, pbqkv);
    round_tf32_k<<<BTOK * H / 1024, 256>>>(hs, phsr);

    // fused QKV projection -> tf32-rounded output
    mma_gemm<0, 1, 1><<<dim3(H3 / 128, BTOK / 128), 256>>>(phsr, pwqkv, pbqkv,
                                                           pqkv, BTOK, H3, H);
    // V transpose + colsum partials
    vt_transpose_k<<<dim3(SEQ / 32, 2, 64), 256>>>(pqkv, pvt);
    sv_partial_k<<<dim3(64, 8), 64>>>(pqkv, psvp);
    // attention -> ctx
    attn_mma_kernel<<<dim3(SEQ / 64, 4 * NH), 256, ATTN_SMEM>>>(pqkv, pvt,
                                                                psvp, pctx);
    // residual + LN1 -> x (+ rounded copy for FFN1)
    add_ln_kernel<1><<<BTOK, 256>>>(hs, pctx, ln1g, ln1b, px, pxr);
    // FFN1 (A pre-rounded, gelu output tf32-rounded)
    mma_gemm<1, 1, 1><<<dim3(FF / 128, BTOK / 128), 256>>>(pxr, pwt1, b1,
                                                           pinter, BTOK, FF, H);
    // FFN2 (A pre-rounded)
    mma_gemm<0, 1, 0><<<dim3(H / 128, BTOK / 128), 256>>>(pinter, pwt2, b2,
                                                          pffn, BTOK, H, FF);
    // residual + LN2 -> out
    add_ln_kernel<0><<<BTOK, 256>>>(pffn, px, ln2g, ln2b, out, nullptr);
}

// round 14
// speedup vs baseline: 3.3967x; 1.0366x over previous
#include <cuda_runtime.h>
#include <math.h>
#include <stdint.h>

#define H    1024
#define NH   16
#define HD   64
#define FF   4096
#define SEQ  2048
#define BTOK 8192   // 4 * 2048 tokens
#define H3   3072   // fused QKV width
#define QT   128
#define NT   (SEQ / 64)

// ---------------------------------------------------------------------------
// Scratch (static __device__ globals: allocation-free rule)
// ---------------------------------------------------------------------------
__device__ float g_qkv[(size_t)BTOK * H3];    // tf32-rounded Q|K|V
__device__ float g_vt[(size_t)64 * 64 * SEQ]; // V transposed: [bh][d][kv]
__device__ float g_svp[8 * 64 * 64];          // colsum(V) partials [part][bh][d]
__device__ float g_ctx[BTOK * H];
__device__ float g_x[BTOK * H];
__device__ float g_xr[BTOK * H];              // tf32-rounded LN1 output
__device__ float g_hsr[BTOK * H];             // tf32-rounded hidden_states
__device__ float g_inter[(size_t)BTOK * FF];  // tf32-rounded gelu output
__device__ float g_ffn[BTOK * H];
__device__ float g_wtqkv[(size_t)H3 * H];
__device__ float g_wt1[(size_t)H * FF];
__device__ float g_wt2[(size_t)FF * H];
__device__ float g_bqkv[H3];

// ---------------------------------------------------------------------------
// Helpers
// ---------------------------------------------------------------------------
__device__ __forceinline__ uint32_t smem_u32(const void* p) {
    uint32_t a;
    asm("{ .reg .u64 t; cvta.to.shared.u64 t, %1; cvt.u32.u64 %0, t; }"
        : "=r"(a) : "l"(p));
    return a;
}
__device__ __forceinline__ float tf32r(float x) {
    uint32_t u;
    asm("cvt.rna.tf32.f32 %0, %1;" : "=r"(u) : "f"(x));
    return __uint_as_float(u);
}
__device__ __forceinline__ float gelu_exact(float x) {
    return 0.5f * x * (1.0f + erff(x * 0.70710678118654752f));
}

#define MMA_TF32(ACC, A0, A1, A2, A3, B0, B1)                                  \
    asm volatile(                                                              \
        "mma.sync.aligned.m16n8k8.row.col.f32.tf32.tf32.f32 "                  \
        "{%0,%1,%2,%3}, {%4,%5,%6,%7}, {%8,%9}, {%0,%1,%2,%3};"                \
        : "+f"((ACC)[0]), "+f"((ACC)[1]), "+f"((ACC)[2]), "+f"((ACC)[3])       \
        : "r"(A0), "r"(A1), "r"(A2), "r"(A3), "r"(B0), "r"(B1))

#define LDM_X4(R0, R1, R2, R3, ADDR)                                           \
    asm volatile(                                                              \
        "ldmatrix.sync.aligned.m8n8.x4.shared.b16 {%0,%1,%2,%3}, [%4];"        \
        : "=r"(R0), "=r"(R1), "=r"(R2), "=r"(R3) : "r"(ADDR))

#define CP_ASYNC16(DST, SRC)                                                   \
    asm volatile("cp.async.cg.shared.global [%0], [%1], 16;"                   \
                 :: "r"(DST), "l"(SRC))
#define CP_COMMIT() asm volatile("cp.async.commit_group;" ::: "memory")
#define CP_WAIT0()  asm volatile("cp.async.wait_group 0;" ::: "memory")
#define CP_WAIT1()  asm volatile("cp.async.wait_group 1;" ::: "memory")

// ---------------------------------------------------------------------------
// Weight transpose + tf32 rounding: W[K][N] -> Wt[N][K]
// ---------------------------------------------------------------------------
__global__ __launch_bounds__(256)
void transpose_tf32_k(const float* __restrict__ W, float* __restrict__ Wt,
                      int K, int N)
{
    __shared__ float t[32][33];
    const int tx = threadIdx.x & 31;
    const int ty = threadIdx.x >> 5;
    const int n0 = blockIdx.x * 32;
    const int k0 = blockIdx.y * 32;
#pragma unroll
    for (int i = 0; i < 4; i++) {
        int r = ty + i * 8;
        t[r][tx] = tf32r(W[(size_t)(k0 + r) * N + n0 + tx]);
    }
    __syncthreads();
#pragma unroll
    for (int i = 0; i < 4; i++) {
        int r = ty + i * 8;
        Wt[(size_t)(n0 + r) * K + k0 + tx] = t[tx][r];
    }
}

__global__ __launch_bounds__(256)
void concat_bias_k(const float* __restrict__ bq, const float* __restrict__ bk,
                   const float* __restrict__ bv, float* __restrict__ o)
{
    int t = threadIdx.x + blockIdx.x * 256;
    if (t < H) o[t] = bq[t];
    else if (t < 2 * H) o[t] = bk[t - H];
    else o[t] = bv[t - 2 * H];
}

__global__ __launch_bounds__(256)
void round_tf32_k(const float* __restrict__ x, float* __restrict__ y)
{
    int i = blockIdx.x * 256 + threadIdx.x;
    float4 v = ((const float4*)x)[i];
    ((float4*)y)[i] = make_float4(tf32r(v.x), tf32r(v.y), tf32r(v.z), tf32r(v.w));
}

// V transpose: g_qkv V region -> VT[bh][d][kv]
__global__ __launch_bounds__(256)
void vt_transpose_k(const float* __restrict__ QKV, float* __restrict__ VT)
{
    __shared__ float t[32][33];
    const int bh = blockIdx.z;
    const int b = bh >> 4, h = bh & 15;
    const int kv0 = blockIdx.x * 32;
    const int d0  = blockIdx.y * 32;
    const int tx = threadIdx.x & 31;
    const int ty = threadIdx.x >> 5;
    const float* src = QKV + (size_t)b * SEQ * H3 + 2 * H + h * HD;
#pragma unroll
    for (int i = 0; i < 4; i++) {
        int kv = kv0 + ty + i * 8;
        t[ty + i * 8][tx] = src[(size_t)kv * H3 + d0 + tx];
    }
    __syncthreads();
    float* dst = VT + (size_t)bh * 64 * SEQ;
#pragma unroll
    for (int i = 0; i < 4; i++) {
        int d = d0 + ty + i * 8;
        dst[(size_t)d * SEQ + kv0 + tx] = t[tx][ty + i * 8];
    }
}

__global__ __launch_bounds__(64)
void sv_partial_k(const float* __restrict__ QKV, float* __restrict__ SVP)
{
    const int bh = blockIdx.x, part = blockIdx.y;
    const int b = bh >> 4, h = bh & 15;
    const int d = threadIdx.x;
    const float* src = QKV + (size_t)(b * SEQ + part * 256) * H3 + 2 * H + h * HD + d;
    float s = 0.0f;
    for (int kv = 0; kv < 256; kv++) s += src[(size_t)kv * H3];
    SVP[(part * 64 + bh) * 64 + d] = s;
}

// ---------------------------------------------------------------------------
// TF32 GEMM: mma.sync.m16n8k8 + ldmatrix + 3-stage cp.async pipeline.
// A must be pre-rounded to tf32. EPI 0=bias 1=gelu+clamp; RO 1=round output.
// ---------------------------------------------------------------------------
#define BM 128
#define BN 128
#define BKG 16
#define PADK 20
#define GEMM_STAGE_B ((BM + BN) * PADK * 4)   // 20480 bytes per stage
#define GEMM_SMEM (3 * GEMM_STAGE_B)          // 61440

template <int EPI, int RO>
__global__ __launch_bounds__(256)
void mma_gemm(const float* __restrict__ A, const float* __restrict__ Bt,
              const float* __restrict__ bias, float* __restrict__ C,
              int M, int N, int K)
{
    extern __shared__ __align__(16) float gsm[];
    const uint32_t sBase = smem_u32(gsm);

    const int tid  = threadIdx.x;
    const int lane = tid & 31;
    const int wid  = tid >> 5;
    const int wm0  = (wid >> 1) * 32;
    const int wn0  = (wid & 1) * 64;
    const int r    = lane >> 2;
    const int c    = lane & 3;

    const int row0 = blockIdx.y * BM;
    const int col0 = blockIdx.x * BN;

    const int ldr = tid >> 2;
    const int ldc = (tid & 3) * 4;

    const float* Ap = A  + (size_t)(row0 + ldr) * K + ldc;
    const float* Bp = Bt + (size_t)(col0 + ldr) * K + ldc;
    const size_t stride64 = (size_t)64 * K;

    const uint32_t stsOff0 = (uint32_t)((ldr * PADK + ldc) * 4);
    const uint32_t stsOff1 = (uint32_t)(((ldr + 64) * PADK + ldc) * 4);
    const uint32_t bOff    = (uint32_t)(BM * PADK * 4);

    const int lr = lane & 7, lg = lane >> 3;
    const uint32_t aLaneOff =
        (uint32_t)(((wm0 + lr + 8 * (lg & 1)) * PADK + 4 * (lg >> 1)) * 4);
    const uint32_t bLaneOff = bOff +
        (uint32_t)(((wn0 + lr + 8 * (lg >> 1)) * PADK + 4 * (lg & 1)) * 4);

    float acc[2][8][4];
#pragma unroll
    for (int mt = 0; mt < 2; mt++)
#pragma unroll
        for (int nt = 0; nt < 8; nt++)
#pragma unroll
            for (int u = 0; u < 4; u++) acc[mt][nt][u] = 0.0f;

    const int NS = K / BKG;

    // prologue: issue stages 0 and 1
#pragma unroll
    for (int s = 0; s < 2; s++) {
        const uint32_t sb = sBase + s * GEMM_STAGE_B;
        const int k0 = s * BKG;
        CP_ASYNC16(sb + stsOff0, Ap + k0);
        CP_ASYNC16(sb + stsOff1, Ap + stride64 + k0);
        CP_ASYNC16(sb + bOff + stsOff0, Bp + k0);
        CP_ASYNC16(sb + bOff + stsOff1, Bp + stride64 + k0);
        CP_COMMIT();
    }

    int buf = 0;
    for (int s = 0; s < NS; s++) {
        if (s + 1 < NS) CP_WAIT1(); else CP_WAIT0();
        __syncthreads();

        const uint32_t sb   = sBase + buf * GEMM_STAGE_B;
        const uint32_t aCur = sb + aLaneOff;
        const uint32_t bCur = sb + bLaneOff;

#pragma unroll
        for (int ks = 0; ks < 2; ks++) {
            const uint32_t ko = ks * 32;
            uint32_t af[2][4];
            LDM_X4(af[0][0], af[0][1], af[0][2], af[0][3], aCur + ko);
            LDM_X4(af[1][0], af[1][1], af[1][2], af[1][3],
                   aCur + 16 * PADK * 4 + ko);
#pragma unroll
            for (int np = 0; np < 4; np++) {
                uint32_t b0, b1, b2, b3;
                LDM_X4(b0, b1, b2, b3, bCur + np * (16 * PADK * 4) + ko);
                MMA_TF32(acc[0][2 * np],     af[0][0], af[0][1], af[0][2], af[0][3], b0, b1);
                MMA_TF32(acc[1][2 * np],     af[1][0], af[1][1], af[1][2], af[1][3], b0, b1);
                MMA_TF32(acc[0][2 * np + 1], af[0][0], af[0][1], af[0][2], af[0][3], b2, b3);
                MMA_TF32(acc[1][2 * np + 1], af[1][0], af[1][1], af[1][2], af[1][3], b2, b3);
            }
        }

        if (s + 2 < NS) {
            const int nb = (buf + 2) % 3;
            const uint32_t nsb = sBase + nb * GEMM_STAGE_B;
            const int k0 = (s + 2) * BKG;
            CP_ASYNC16(nsb + stsOff0, Ap + k0);
            CP_ASYNC16(nsb + stsOff1, Ap + stride64 + k0);
            CP_ASYNC16(nsb + bOff + stsOff0, Bp + k0);
            CP_ASYNC16(nsb + bOff + stsOff1, Bp + stride64 + k0);
            CP_COMMIT();
        }
        buf = (buf + 1) % 3;
    }

#pragma unroll
    for (int mt = 0; mt < 2; mt++) {
        const int rowA = row0 + wm0 + mt * 16 + r;
#pragma unroll
        for (int nt = 0; nt < 8; nt++) {
            const int col = col0 + wn0 + nt * 8 + 2 * c;
            const float bz0 = bias[col];
            const float bz1 = bias[col + 1];
            float v0 = acc[mt][nt][0] + bz0;
            float v1 = acc[mt][nt][1] + bz1;
            float v2 = acc[mt][nt][2] + bz0;
            float v3 = acc[mt][nt][3] + bz1;
            if (EPI == 1) {
                v0 = fminf(fmaxf(gelu_exact(v0), -1e9f), 1e9f);
                v1 = fminf(fmaxf(gelu_exact(v1), -1e9f), 1e9f);
                v2 = fminf(fmaxf(gelu_exact(v2), -1e9f), 1e9f);
                v3 = fminf(fmaxf(gelu_exact(v3), -1e9f), 1e9f);
            }
            if (RO) {
                v0 = tf32r(v0); v1 = tf32r(v1); v2 = tf32r(v2); v3 = tf32r(v3);
            }
            *(float2*)(C + (size_t)rowA * N + col)       = make_float2(v0, v1);
            *(float2*)(C + (size_t)(rowA + 8) * N + col) = make_float2(v2, v3);
        }
    }
}

// ---------------------------------------------------------------------------
// Flash attention: 128-query tiles, 512 threads = 16 warps (8 qm x 2 n-half).
// mma.sync tf32 + ldmatrix, pure cp.async staging, double-buffered K/VT.
// ---------------------------------------------------------------------------
#define APAD 68
#define ATILE (64 * APAD)            // one 64x64 K/V tile (floats)
#define QTILE (QT * APAD)            // 128-row Q/S tile (floats)
// layout: Qs | Ks[2] | Vt[2] | Ss | m(128) l(128) sc(128) sv(64)
#define OFF_KS (QTILE)
#define OFF_VT (QTILE + 2 * ATILE)
#define OFF_SS (QTILE + 4 * ATILE)
#define OFF_MS (2 * QTILE + 4 * ATILE)
#define ATTN_SMEM ((2 * QTILE + 4 * ATILE + 3 * QT + 64) * 4)

__global__ __launch_bounds__(512)
void attn_mma_kernel(const float* __restrict__ QKV, const float* __restrict__ VT,
                     const float* __restrict__ SVP, float* __restrict__ O)
{
    extern __shared__ __align__(16) float smf[];
    float* Qs   = smf;
    float* m_s  = smf + OFF_MS;
    float* l_s  = m_s + QT;
    float* sc_s = l_s + QT;
    float* sv_s = sc_s + QT;

    const int tid  = threadIdx.x;
    const int lane = tid & 31;
    const int wid  = tid >> 5;           // 0..15
    const int wq0  = (wid >> 1) * 16;    // 0..112
    const int wn0  = (wid & 1) * 32;
    const int r    = lane >> 2;
    const int c    = lane & 3;

    const int bh = blockIdx.y;
    const int b  = bh >> 4;
    const int h  = bh & 15;
    const int qstart = blockIdx.x * QT;
    const size_t rowbase = (size_t)b * SEQ;
    const float* Qg = QKV + (size_t)h * HD;
    const float* Kg = QKV + H + (size_t)h * HD;
    const float* Vg = VT + (size_t)bh * 64 * SEQ;
    const size_t obase = (size_t)b * SEQ * H + (size_t)h * HD;

    const uint32_t sQ = smem_u32(Qs);
    const uint32_t sK = sQ + OFF_KS * 4;
    const uint32_t sV = sQ + OFF_VT * 4;
    const uint32_t sS = sQ + OFF_SS * 4;

    const int lr = lane & 7, lg = lane >> 3;
    const int aRow = wq0 + lr + 8 * (lg & 1);
    const int aKof = 4 * (lg >> 1);
    const int bRow = wn0 + lr + 8 * (lg >> 1);
    const int bKof = 4 * (lg & 1);
    const uint32_t qLane = sQ + (uint32_t)((aRow * APAD + aKof) * 4);
    const uint32_t sLane = sS + (uint32_t)((aRow * APAD + aKof) * 4);
    const uint32_t kLane = sK + (uint32_t)((bRow * APAD + bKof) * 4);
    const uint32_t vLane = sV + (uint32_t)((bRow * APAD + bKof) * 4);

    // ---- prologue: Q (128 rows) + KV tiles 0,1 ----
#pragma unroll
    for (int it = 0; it < 4; it++) {           // 2048 chunks of 16B
        const int idx = tid + it * 512;
        const int row = idx >> 4, ch = idx & 15;
        CP_ASYNC16(sQ + (uint32_t)((row * APAD + ch * 4) * 4),
                   Qg + (rowbase + qstart + row) * H3 + ch * 4);
    }
#pragma unroll
    for (int it = 0; it < 2; it++) {           // 1024 chunks
        const int idx = tid + it * 512;
        const int row = idx >> 4, ch = idx & 15;
        const uint32_t dsto = (uint32_t)((row * APAD + ch * 4) * 4);
        CP_ASYNC16(sK + dsto, Kg + (rowbase + row) * H3 + ch * 4);
        CP_ASYNC16(sV + dsto, Vg + (size_t)row * SEQ + ch * 4);
    }
    CP_COMMIT();
#pragma unroll
    for (int it = 0; it < 2; it++) {
        const int idx = tid + it * 512;
        const int row = idx >> 4, ch = idx & 15;
        const uint32_t dsto = (uint32_t)((row * APAD + ch * 4) * 4) + ATILE * 4;
        CP_ASYNC16(sK + dsto, Kg + (rowbase + 64 + row) * H3 + ch * 4);
        CP_ASYNC16(sV + dsto, Vg + (size_t)row * SEQ + 64 + ch * 4);
    }
    CP_COMMIT();
    CP_WAIT1();

    if (tid < QT) { m_s[tid] = -1e30f; l_s[tid] = 0.0f; }
    if (tid < 64) {
        float s = 0.0f;
#pragma unroll
        for (int p = 0; p < 8; p++) s += SVP[(p * 64 + bh) * 64 + tid];
        sv_s[tid] = 1e-9f * s;
    }

    float oacc[4][4];
#pragma unroll
    for (int nt = 0; nt < 4; nt++)
#pragma unroll
        for (int u = 0; u < 4; u++) oacc[nt][u] = 0.0f;

    __syncthreads();

    for (int kt = 0; kt < NT; kt++) {
        const int cur = kt & 1;
        const uint32_t kCur = kLane + cur * (ATILE * 4);
        const uint32_t vCur = vLane + cur * (ATILE * 4);

        // ---- S = Q K^T ----
        float sacc[4][4];
#pragma unroll
        for (int nt = 0; nt < 4; nt++)
#pragma unroll
            for (int u = 0; u < 4; u++) sacc[nt][u] = 0.0f;

#pragma unroll
        for (int ks = 0; ks < 8; ks++) {
            const uint32_t ko = ks * 32;
            uint32_t a0, a1, a2, a3;
            LDM_X4(a0, a1, a2, a3, qLane + ko);
#pragma unroll
            for (int np = 0; np < 2; np++) {
                uint32_t b0, b1, b2, b3;
                LDM_X4(b0, b1, b2, b3, kCur + np * (16 * APAD * 4) + ko);
                MMA_TF32(sacc[2 * np],     a0, a1, a2, a3, b0, b1);
                MMA_TF32(sacc[2 * np + 1], a0, a1, a2, a3, b2, b3);
            }
        }
#pragma unroll
        for (int nt = 0; nt < 4; nt++) {
            const int col = wn0 + nt * 8 + 2 * c;
            const int row = wq0 + r;
            float v0 = fminf(fmaxf(sacc[nt][0] * 0.125f, -1e9f), 1e9f);
            float v1 = fminf(fmaxf(sacc[nt][1] * 0.125f, -1e9f), 1e9f);
            float v2 = fminf(fmaxf(sacc[nt][2] * 0.125f, -1e9f), 1e9f);
            float v3 = fminf(fmaxf(sacc[nt][3] * 0.125f, -1e9f), 1e9f);
            float* Ssf = smf + OFF_SS;
            *(float2*)&Ssf[row * APAD + col]       = make_float2(v0, v1);
            *(float2*)&Ssf[(row + 8) * APAD + col] = make_float2(v2, v3);
        }
        __syncthreads();

        // ---- online softmax: 4 threads per row (512 threads / 128 rows) ----
        {
            const int row = tid >> 2;
            const int p   = tid & 3;
            float* srow = smf + OFF_SS + row * APAD;
            float mt = -1e30f;
#pragma unroll
            for (int j = 0; j < 16; j++) mt = fmaxf(mt, srow[p + 4 * j]);
            mt = fmaxf(mt, __shfl_xor_sync(0xffffffffu, mt, 1));
            mt = fmaxf(mt, __shfl_xor_sync(0xffffffffu, mt, 2));
            const float mo = m_s[row];
            mt = fmaxf(mt, mo);
            float sum = 0.0f;
#pragma unroll
            for (int j = 0; j < 16; j++) {
                float e = __expf(srow[p + 4 * j] - mt);
                srow[p + 4 * j] = tf32r(e);
                sum += e;
            }
            sum += __shfl_xor_sync(0xffffffffu, sum, 1);
            sum += __shfl_xor_sync(0xffffffffu, sum, 2);
            if (p == 0) {
                const float sc = __expf(mo - mt);
                m_s[row]  = mt;
                l_s[row]  = l_s[row] * sc + sum;
                sc_s[row] = sc;
            }
        }
        __syncthreads();

        // rescale accumulators
        {
            const float sc0 = sc_s[wq0 + r];
            const float sc1 = sc_s[wq0 + r + 8];
#pragma unroll
            for (int nt = 0; nt < 4; nt++) {
                oacc[nt][0] *= sc0; oacc[nt][1] *= sc0;
                oacc[nt][2] *= sc1; oacc[nt][3] *= sc1;
            }
        }

        // ---- O += P V ----
#pragma unroll
        for (int ks = 0; ks < 8; ks++) {
            const uint32_t ko = ks * 32;
            uint32_t a0, a1, a2, a3;
            LDM_X4(a0, a1, a2, a3, sLane + ko);
#pragma unroll
            for (int np = 0; np < 2; np++) {
                uint32_t b0, b1, b2, b3;
                LDM_X4(b0, b1, b2, b3, vCur + np * (16 * APAD * 4) + ko);
                MMA_TF32(oacc[2 * np],     a0, a1, a2, a3, b0, b1);
                MMA_TF32(oacc[2 * np + 1], a0, a1, a2, a3, b2, b3);
            }
        }
        __syncthreads();   // all reads of buffer cur done

        // prefetch tile kt+2 into buffer cur
        if (kt + 2 < NT) {
            const int kstart = (kt + 2) * 64;
            const uint32_t bo = cur * (ATILE * 4);
#pragma unroll
            for (int it = 0; it < 2; it++) {
                const int idx = tid + it * 512;
                const int row = idx >> 4, ch = idx & 15;
                const uint32_t dsto = (uint32_t)((row * APAD + ch * 4) * 4) + bo;
                CP_ASYNC16(sK + dsto, Kg + (rowbase + kstart + row) * H3 + ch * 4);
                CP_ASYNC16(sV + dsto, Vg + (size_t)row * SEQ + kstart + ch * 4);
            }
            CP_COMMIT();
            CP_WAIT1();
        } else {
            CP_WAIT0();
        }
        __syncthreads();
    }

    // epilogue
    {
        const float linv0 = 1.0f / l_s[wq0 + r];
        const float linv1 = 1.0f / l_s[wq0 + r + 8];
        const int row = qstart + wq0 + r;
#pragma unroll
        for (int nt = 0; nt < 4; nt++) {
            const int col = wn0 + nt * 8 + 2 * c;
            const float e0 = sv_s[col], e1 = sv_s[col + 1];
            float2 o0 = make_float2(oacc[nt][0] * linv0 + e0,
                                    oacc[nt][1] * linv0 + e1);
            float2 o1 = make_float2(oacc[nt][2] * linv1 + e0,
                                    oacc[nt][3] * linv1 + e1);
            *(float2*)&O[obase + (size_t)row * H + col]       = o0;
            *(float2*)&O[obase + (size_t)(row + 8) * H + col] = o1;
        }
    }
}

// ---------------------------------------------------------------------------
// Fused residual-add + LayerNorm; optional second tf32-rounded output.
// ---------------------------------------------------------------------------
template <int WR>
__global__ __launch_bounds__(256)
void add_ln_kernel(const float* __restrict__ A, const float* __restrict__ Bres,
                   const float* __restrict__ gam, const float* __restrict__ bet,
                   float* __restrict__ out, float* __restrict__ out_r)
{
    const int row = blockIdx.x;
    const int tid = threadIdx.x;
    const float4 va = ((const float4*)(A    + (size_t)row * H))[tid];
    const float4 vb = ((const float4*)(Bres + (size_t)row * H))[tid];
    float x0 = va.x + vb.x, x1 = va.y + vb.y, x2 = va.z + vb.z, x3 = va.w + vb.w;

    __shared__ float red[8];
    __shared__ float s_mu, s_rstd;

    float s = x0 + x1 + x2 + x3;
#pragma unroll
    for (int o = 16; o; o >>= 1) s += __shfl_down_sync(0xffffffffu, s, o);
    if ((tid & 31) == 0) red[tid >> 5] = s;
    __syncthreads();
    if (tid == 0) {
        float t = 0.f;
#pragma unroll
        for (int i = 0; i < 8; i++) t += red[i];
        s_mu = t * (1.0f / H);
    }
    __syncthreads();
    const float mu = s_mu;
    float d0 = x0 - mu, d1 = x1 - mu, d2 = x2 - mu, d3 = x3 - mu;
    float ss = d0 * d0 + d1 * d1 + d2 * d2 + d3 * d3;
#pragma unroll
    for (int o = 16; o; o >>= 1) ss += __shfl_down_sync(0xffffffffu, ss, o);
    __syncthreads();
    if ((tid & 31) == 0) red[tid >> 5] = ss;
    __syncthreads();
    if (tid == 0) {
        float t = 0.f;
#pragma unroll
        for (int i = 0; i < 8; i++) t += red[i];
        s_rstd = rsqrtf(t * (1.0f / H) + 1e-12f);
    }
    __syncthreads();
    const float rstd = s_rstd;

    const float4 g4 = ((const float4*)gam)[tid];
    const float4 b4 = ((const float4*)bet)[tid];
    float4 o;
    o.x = d0 * rstd * g4.x + b4.x;
    o.y = d1 * rstd * g4.y + b4.y;
    o.z = d2 * rstd * g4.z + b4.z;
    o.w = d3 * rstd * g4.w + b4.w;
    ((float4*)(out + (size_t)row * H))[tid] = o;
    if (WR) {
        float4 orr = make_float4(tf32r(o.x), tf32r(o.y), tf32r(o.z), tf32r(o.w));
        ((float4*)(out_r + (size_t)row * H))[tid] = orr;
    }
}

// ---------------------------------------------------------------------------
// Launch
// ---------------------------------------------------------------------------
extern "C" void kernel_launch(void* const* d_in, const int* in_sizes, int n_in,
                              void* d_out, int out_size)
{
    const float* hs   = (const float*)d_in[0];
    const float* Wq   = (const float*)d_in[1];
    const float* bq   = (const float*)d_in[2];
    const float* Wk   = (const float*)d_in[3];
    const float* bk   = (const float*)d_in[4];
    const float* Wv   = (const float*)d_in[5];
    const float* bv   = (const float*)d_in[6];
    const float* ln1g = (const float*)d_in[7];
    const float* ln1b = (const float*)d_in[8];
    const float* W1   = (const float*)d_in[9];
    const float* b1   = (const float*)d_in[10];
    const float* W2   = (const float*)d_in[11];
    const float* b2   = (const float*)d_in[12];
    const float* ln2g = (const float*)d_in[13];
    const float* ln2b = (const float*)d_in[14];
    float* out = (float*)d_out;

    static float *pqkv = nullptr, *pvt = nullptr, *psvp = nullptr,
                 *pctx = nullptr, *px = nullptr, *pxr = nullptr,
                 *phsr = nullptr, *pinter = nullptr, *pffn = nullptr,
                 *pwqkv = nullptr, *pwt1 = nullptr, *pwt2 = nullptr,
                 *pbqkv = nullptr;
    if (!pqkv) {  // first call is the (uncaptured) correctness run
        cudaGetSymbolAddress((void**)&pqkv,   g_qkv);
        cudaGetSymbolAddress((void**)&pvt,    g_vt);
        cudaGetSymbolAddress((void**)&psvp,   g_svp);
        cudaGetSymbolAddress((void**)&pctx,   g_ctx);
        cudaGetSymbolAddress((void**)&px,     g_x);
        cudaGetSymbolAddress((void**)&pxr,    g_xr);
        cudaGetSymbolAddress((void**)&phsr,   g_hsr);
        cudaGetSymbolAddress((void**)&pinter, g_inter);
        cudaGetSymbolAddress((void**)&pffn,   g_ffn);
        cudaGetSymbolAddress((void**)&pwqkv,  g_wtqkv);
        cudaGetSymbolAddress((void**)&pwt1,   g_wt1);
        cudaGetSymbolAddress((void**)&pwt2,   g_wt2);
        cudaGetSymbolAddress((void**)&pbqkv,  g_bqkv);
        cudaFuncSetAttribute(attn_mma_kernel,
                             cudaFuncAttributeMaxDynamicSharedMemorySize, ATTN_SMEM);
        cudaFuncSetAttribute(mma_gemm<0, 1>,
                             cudaFuncAttributeMaxDynamicSharedMemorySize, GEMM_SMEM);
        cudaFuncSetAttribute(mma_gemm<1, 1>,
                             cudaFuncAttributeMaxDynamicSharedMemorySize, GEMM_SMEM);
        cudaFuncSetAttribute(mma_gemm<0, 0>,
                             cudaFuncAttributeMaxDynamicSharedMemorySize, GEMM_SMEM);
    }

    // prep: weight transposes, bias concat, input rounding
    transpose_tf32_k<<<dim3(H / 32, H / 32), 256>>>(Wq, pwqkv,             H, H);
    transpose_tf32_k<<<dim3(H / 32, H / 32), 256>>>(Wk, pwqkv + H * H,     H, H);
    transpose_tf32_k<<<dim3(H / 32, H / 32), 256>>>(Wv, pwqkv + 2 * H * H, H, H);
    transpose_tf32_k<<<dim3(FF / 32, H / 32), 256>>>(W1, pwt1, H, FF);
    transpose_tf32_k<<<dim3(H / 32, FF / 32), 256>>>(W2, pwt2, FF, H);
    concat_bias_k<<<H3 / 256, 256>>>(bq, bk, bv, pbqkv);
    round_tf32_k<<<BTOK * H / 1024, 256>>>(hs, phsr);

    // fused QKV projection -> tf32-rounded output
    mma_gemm<0, 1><<<dim3(H3 / 128, BTOK / 128), 256, GEMM_SMEM>>>(
        phsr, pwqkv, pbqkv, pqkv, BTOK, H3, H);
    // V transpose + colsum partials
    vt_transpose_k<<<dim3(SEQ / 32, 2, 64), 256>>>(pqkv, pvt);
    sv_partial_k<<<dim3(64, 8), 64>>>(pqkv, psvp);
    // attention -> ctx (128-query tiles)
    attn_mma_kernel<<<dim3(SEQ / QT, 4 * NH), 512, ATTN_SMEM>>>(pqkv, pvt,
                                                                psvp, pctx);
    // residual + LN1 -> x (+ rounded copy for FFN1)
    add_ln_kernel<1><<<BTOK, 256>>>(hs, pctx, ln1g, ln1b, px, pxr);
    // FFN1 (gelu output tf32-rounded)
    mma_gemm<1, 1><<<dim3(FF / 128, BTOK / 128), 256, GEMM_SMEM>>>(
        pxr, pwt1, b1, pinter, BTOK, FF, H);
    // FFN2
    mma_gemm<0, 0><<<dim3(H / 128, BTOK / 128), 256, GEMM_SMEM>>>(
        pinter, pwt2, b2, pffn, BTOK, H, FF);
    // residual + LN2 -> out
    add_ln_kernel<0><<<BTOK, 256>>>(pffn, px, ln2g, ln2b, out, nullptr);
}

// round 15
// speedup vs baseline: 6.0299x; 1.7752x over previous
#include <cuda_runtime.h>
#include <cuda_fp16.h>
#include <math.h>
#include <stdint.h>

#define H    1024
#define NH   16
#define HD   64
#define FF   4096
#define SEQ  2048
#define BTOK 8192   // 4 * 2048 tokens
#define H3   3072   // fused QKV width
#define QT   128
#define NT   (SEQ / 64)

// ---------------------------------------------------------------------------
// Scratch (static __device__ globals: allocation-free rule)
// ---------------------------------------------------------------------------
__device__ __half g_qkv[(size_t)BTOK * H3];    // fp16 Q|K|V
__device__ __half g_vt[(size_t)64 * 64 * SEQ]; // V transposed: [bh][d][kv]
__device__ float  g_svp[8 * 64 * 64];          // colsum(V) partials
__device__ float  g_ctx[BTOK * H];
__device__ float  g_x[BTOK * H];
__device__ __half g_xr[BTOK * H];              // fp16 LN1 output
__device__ __half g_hsr[BTOK * H];             // fp16 hidden_states
__device__ __half g_inter[(size_t)BTOK * FF];  // fp16 gelu output
__device__ float  g_ffn[BTOK * H];
__device__ __half g_wtqkv[(size_t)H3 * H];     // fp16 transposed weights
__device__ __half g_wt1[(size_t)H * FF];
__device__ __half g_wt2[(size_t)FF * H];
__device__ float  g_bqkv[H3];

// ---------------------------------------------------------------------------
// Helpers
// ---------------------------------------------------------------------------
__device__ __forceinline__ uint32_t smem_u32(const void* p) {
    uint32_t a;
    asm("{ .reg .u64 t; cvta.to.shared.u64 t, %1; cvt.u32.u64 %0, t; }"
        : "=r"(a) : "l"(p));
    return a;
}
__device__ __forceinline__ float gelu_exact(float x) {
    return 0.5f * x * (1.0f + erff(x * 0.70710678118654752f));
}

#define MMA_F16(ACC, A0, A1, A2, A3, B0, B1)                                   \
    asm volatile(                                                              \
        "mma.sync.aligned.m16n8k16.row.col.f32.f16.f16.f32 "                   \
        "{%0,%1,%2,%3}, {%4,%5,%6,%7}, {%8,%9}, {%0,%1,%2,%3};"                \
        : "+f"((ACC)[0]), "+f"((ACC)[1]), "+f"((ACC)[2]), "+f"((ACC)[3])       \
        : "r"(A0), "r"(A1), "r"(A2), "r"(A3), "r"(B0), "r"(B1))

#define LDM_X4(R0, R1, R2, R3, ADDR)                                           \
    asm volatile(                                                              \
        "ldmatrix.sync.aligned.m8n8.x4.shared.b16 {%0,%1,%2,%3}, [%4];"        \
        : "=r"(R0), "=r"(R1), "=r"(R2), "=r"(R3) : "r"(ADDR))

#define CP_ASYNC16(DST, SRC)                                                   \
    asm volatile("cp.async.cg.shared.global [%0], [%1], 16;"                   \
                 :: "r"(DST), "l"(SRC))
#define CP_COMMIT() asm volatile("cp.async.commit_group;" ::: "memory")
#define CP_WAIT0()  asm volatile("cp.async.wait_group 0;" ::: "memory")
#define CP_WAIT1()  asm volatile("cp.async.wait_group 1;" ::: "memory")

// ---------------------------------------------------------------------------
// Prep kernels
// ---------------------------------------------------------------------------
// W[K][N] fp32 -> Wt[N][K] fp16
__global__ __launch_bounds__(256)
void transpose_f16_k(const float* __restrict__ W, __half* __restrict__ Wt,
                     int K, int N)
{
    __shared__ float t[32][33];
    const int tx = threadIdx.x & 31;
    const int ty = threadIdx.x >> 5;
    const int n0 = blockIdx.x * 32;
    const int k0 = blockIdx.y * 32;
#pragma unroll
    for (int i = 0; i < 4; i++) {
        int r = ty + i * 8;
        t[r][tx] = W[(size_t)(k0 + r) * N + n0 + tx];
    }
    __syncthreads();
#pragma unroll
    for (int i = 0; i < 4; i++) {
        int r = ty + i * 8;
        Wt[(size_t)(n0 + r) * K + k0 + tx] = __float2half(t[tx][r]);
    }
}

__global__ __launch_bounds__(256)
void concat_bias_k(const float* __restrict__ bq, const float* __restrict__ bk,
                   const float* __restrict__ bv, float* __restrict__ o)
{
    int t = threadIdx.x + blockIdx.x * 256;
    if (t < H) o[t] = bq[t];
    else if (t < 2 * H) o[t] = bk[t - H];
    else o[t] = bv[t - 2 * H];
}

// fp32 -> fp16 elementwise
__global__ __launch_bounds__(256)
void cvt_f16_k(const float* __restrict__ x, __half* __restrict__ y)
{
    int i = blockIdx.x * 256 + threadIdx.x;
    float4 v = ((const float4*)x)[i];
    __half2* yo = (__half2*)y;
    yo[2 * i]     = __floats2half2_rn(v.x, v.y);
    yo[2 * i + 1] = __floats2half2_rn(v.z, v.w);
}

// V region of fp16 QKV -> VT[bh][d][kv]
__global__ __launch_bounds__(256)
void vt_transpose_k(const __half* __restrict__ QKV, __half* __restrict__ VT)
{
    __shared__ float t[32][33];
    const int bh = blockIdx.z;
    const int b = bh >> 4, h = bh & 15;
    const int kv0 = blockIdx.x * 32;
    const int d0  = blockIdx.y * 32;
    const int tx = threadIdx.x & 31;
    const int ty = threadIdx.x >> 5;
    const __half* src = QKV + (size_t)b * SEQ * H3 + 2 * H + h * HD;
#pragma unroll
    for (int i = 0; i < 4; i++) {
        int kv = kv0 + ty + i * 8;
        t[ty + i * 8][tx] = __half2float(src[(size_t)kv * H3 + d0 + tx]);
    }
    __syncthreads();
    __half* dst = VT + (size_t)bh * 64 * SEQ;
#pragma unroll
    for (int i = 0; i < 4; i++) {
        int d = d0 + ty + i * 8;
        dst[(size_t)d * SEQ + kv0 + tx] = __float2half(t[tx][ty + i * 8]);
    }
}

__global__ __launch_bounds__(64)
void sv_partial_k(const __half* __restrict__ QKV, float* __restrict__ SVP)
{
    const int bh = blockIdx.x, part = blockIdx.y;
    const int b = bh >> 4, h = bh & 15;
    const int d = threadIdx.x;
    const __half* src = QKV + (size_t)(b * SEQ + part * 256) * H3 + 2 * H + h * HD + d;
    float s = 0.0f;
    for (int kv = 0; kv < 256; kv++) s += __half2float(src[(size_t)kv * H3]);
    SVP[(part * 64 + bh) * 64 + d] = s;
}

// ---------------------------------------------------------------------------
// FP16 GEMM: mma.sync.m16n8k16 + ldmatrix + 3-stage cp.async pipeline.
// C[M,N] = A[M,K](fp16) @ Bt[N,K](fp16)^T + bias(fp32).
// CTA tile 128x128, BK=32 halfs/stage, 256 threads = 8 warps (4M x 2N).
// EPI 0=bias 1=gelu+clamp; CO 0=fp32 out 1=fp16 out.
// ---------------------------------------------------------------------------
#define BM 128
#define BN 128
#define PADKH 40                               // halfs per row (80B, cf-free)
#define GEMM_STAGE_B ((BM + BN) * PADKH * 2)   // 20480 bytes
#define GEMM_SMEM (3 * GEMM_STAGE_B)           // 61440
#define GEMM_BOFF (BM * PADKH * 2)             // 10240

template <int EPI, int CO>
__global__ __launch_bounds__(256)
void mma_gemm(const __half* __restrict__ A, const __half* __restrict__ Bt,
              const float* __restrict__ bias, void* __restrict__ Cv,
              int M, int N, int K)
{
    extern __shared__ __align__(16) char gsm[];
    const uint32_t sBase = smem_u32(gsm);

    const int tid  = threadIdx.x;
    const int lane = tid & 31;
    const int wid  = tid >> 5;
    const int wm0  = (wid >> 1) * 32;
    const int wn0  = (wid & 1) * 64;
    const int r    = lane >> 2;
    const int c    = lane & 3;

    const int row0 = blockIdx.y * BM;
    const int col0 = blockIdx.x * BN;

    // cp.async: 512 16B-chunks per operand per stage; 2 per thread each
    const int r0i = tid >> 1,              ch0 = (tid & 1);          // unused shape
    (void)r0i; (void)ch0;
    const int idxA0 = tid,       rowA0 = idxA0 >> 2, chA0 = idxA0 & 3;
    const int idxA1 = tid + 256, rowA1 = idxA1 >> 2, chA1 = idxA1 & 3;

    const __half* Ap0 = A  + (size_t)(row0 + rowA0) * K + chA0 * 8;
    const __half* Ap1 = A  + (size_t)(row0 + rowA1) * K + chA1 * 8;
    const __half* Bp0 = Bt + (size_t)(col0 + rowA0) * K + chA0 * 8;
    const __half* Bp1 = Bt + (size_t)(col0 + rowA1) * K + chA1 * 8;

    const uint32_t stsA0 = (uint32_t)((rowA0 * PADKH + chA0 * 8) * 2);
    const uint32_t stsA1 = (uint32_t)((rowA1 * PADKH + chA1 * 8) * 2);

    // ldmatrix lane offsets
    const uint32_t aLaneOff =
        (uint32_t)(((wm0 + (lane & 15)) * PADKH + (lane >> 4) * 8) * 2);
    const uint32_t bLaneOff = GEMM_BOFF +
        (uint32_t)(((wn0 + (lane & 7) + ((lane >> 4) & 1) * 8) * PADKH
                    + ((lane >> 3) & 1) * 8) * 2);

    float acc[2][8][4];
#pragma unroll
    for (int mt = 0; mt < 2; mt++)
#pragma unroll
        for (int nt = 0; nt < 8; nt++)
#pragma unroll
            for (int u = 0; u < 4; u++) acc[mt][nt][u] = 0.0f;

    const int NS = K / 32;

#pragma unroll
    for (int s = 0; s < 2; s++) {
        const uint32_t sb = sBase + s * GEMM_STAGE_B;
        const int k0 = s * 32;
        CP_ASYNC16(sb + stsA0, Ap0 + k0);
        CP_ASYNC16(sb + stsA1, Ap1 + k0);
        CP_ASYNC16(sb + GEMM_BOFF + stsA0, Bp0 + k0);
        CP_ASYNC16(sb + GEMM_BOFF + stsA1, Bp1 + k0);
        CP_COMMIT();
    }

    int buf = 0;
    for (int s = 0; s < NS; s++) {
        if (s + 1 < NS) CP_WAIT1(); else CP_WAIT0();
        __syncthreads();

        const uint32_t sb = sBase + buf * GEMM_STAGE_B;

#pragma unroll
        for (int ks = 0; ks < 2; ks++) {
            const uint32_t ko = ks * 32;    // 16 halfs = 32 bytes
            uint32_t af[2][4];
            LDM_X4(af[0][0], af[0][1], af[0][2], af[0][3],
                   sb + aLaneOff + ko);
            LDM_X4(af[1][0], af[1][1], af[1][2], af[1][3],
                   sb + aLaneOff + 16 * PADKH * 2 + ko);
#pragma unroll
            for (int np = 0; np < 4; np++) {
                uint32_t b0, b1, b2, b3;
                LDM_X4(b0, b1, b2, b3, sb + bLaneOff + np * (16 * PADKH * 2) + ko);
                MMA_F16(acc[0][2 * np],     af[0][0], af[0][1], af[0][2], af[0][3], b0, b1);
                MMA_F16(acc[1][2 * np],     af[1][0], af[1][1], af[1][2], af[1][3], b0, b1);
                MMA_F16(acc[0][2 * np + 1], af[0][0], af[0][1], af[0][2], af[0][3], b2, b3);
                MMA_F16(acc[1][2 * np + 1], af[1][0], af[1][1], af[1][2], af[1][3], b2, b3);
            }
        }

        if (s + 2 < NS) {
            const int nb = (buf + 2) % 3;
            const uint32_t nsb = sBase + nb * GEMM_STAGE_B;
            const int k0 = (s + 2) * 32;
            CP_ASYNC16(nsb + stsA0, Ap0 + k0);
            CP_ASYNC16(nsb + stsA1, Ap1 + k0);
            CP_ASYNC16(nsb + GEMM_BOFF + stsA0, Bp0 + k0);
            CP_ASYNC16(nsb + GEMM_BOFF + stsA1, Bp1 + k0);
            CP_COMMIT();
        }
        buf = (buf + 1) % 3;
    }

#pragma unroll
    for (int mt = 0; mt < 2; mt++) {
        const int rowA = row0 + wm0 + mt * 16 + r;
#pragma unroll
        for (int nt = 0; nt < 8; nt++) {
            const int col = col0 + wn0 + nt * 8 + 2 * c;
            const float bz0 = bias[col];
            const float bz1 = bias[col + 1];
            float v0 = acc[mt][nt][0] + bz0;
            float v1 = acc[mt][nt][1] + bz1;
            float v2 = acc[mt][nt][2] + bz0;
            float v3 = acc[mt][nt][3] + bz1;
            if (EPI == 1) {
                v0 = fminf(fmaxf(gelu_exact(v0), -1e9f), 1e9f);
                v1 = fminf(fmaxf(gelu_exact(v1), -1e9f), 1e9f);
                v2 = fminf(fmaxf(gelu_exact(v2), -1e9f), 1e9f);
                v3 = fminf(fmaxf(gelu_exact(v3), -1e9f), 1e9f);
            }
            if (CO) {
                __half* Ch = (__half*)Cv;
                *(__half2*)(Ch + (size_t)rowA * N + col) =
                    __floats2half2_rn(v0, v1);
                *(__half2*)(Ch + (size_t)(rowA + 8) * N + col) =
                    __floats2half2_rn(v2, v3);
            } else {
                float* Cf = (float*)Cv;
                *(float2*)(Cf + (size_t)rowA * N + col)       = make_float2(v0, v1);
                *(float2*)(Cf + (size_t)(rowA + 8) * N + col) = make_float2(v2, v3);
            }
        }
    }
}

// ---------------------------------------------------------------------------
// Flash attention, fp16 MMA: 128-query tiles, 512 threads = 16 warps.
// Q/K/V fp16 via cp.async; scores fp32; softmax fp32; probs fp16 -> PV.
// ---------------------------------------------------------------------------
#define QSTR 72                       // half stride for Q/K/V/P tiles (144B)
#define QBYTES (QT * QSTR * 2)        // 18432
#define KTILEB (64 * QSTR * 2)        // 9216 per tile
#define SPAD 68                       // float stride for scores
#define OFFB_Q  0
#define OFFB_K  18432
#define OFFB_V  (18432 + 2 * KTILEB)
#define OFFB_S  (OFFB_V + 2 * KTILEB)        // fp32 scores 128x68
#define OFFB_P  (OFFB_S + QT * SPAD * 4)     // fp16 probs 128x72
#define OFFB_ST (OFFB_P + QBYTES)            // stats
#define ATTN_SMEM (OFFB_ST + (3 * QT + 64) * 4)

__global__ __launch_bounds__(512)
void attn_mma_kernel(const __half* __restrict__ QKV, const __half* __restrict__ VT,
                     const float* __restrict__ SVP, float* __restrict__ O)
{
    extern __shared__ __align__(16) char smc[];
    float* Ssf  = (float*)(smc + OFFB_S);
    __half* Psh = (__half*)(smc + OFFB_P);
    float* m_s  = (float*)(smc + OFFB_ST);
    float* l_s  = m_s + QT;
    float* sc_s = l_s + QT;
    float* sv_s = sc_s + QT;

    const int tid  = threadIdx.x;
    const int lane = tid & 31;
    const int wid  = tid >> 5;           // 0..15
    const int wq0  = (wid >> 1) * 16;
    const int wn0  = (wid & 1) * 32;
    const int r    = lane >> 2;
    const int c    = lane & 3;

    const int bh = blockIdx.y;
    const int b  = bh >> 4;
    const int h  = bh & 15;
    const int qstart = blockIdx.x * QT;
    const size_t rowbase = (size_t)b * SEQ;
    const __half* Qg = QKV + (size_t)h * HD;
    const __half* Kg = QKV + H + (size_t)h * HD;
    const __half* Vg = VT + (size_t)bh * 64 * SEQ;
    const size_t obase = (size_t)b * SEQ * H + (size_t)h * HD;

    const uint32_t sQ = smem_u32(smc);
    const uint32_t sK = sQ + OFFB_K;
    const uint32_t sV = sQ + OFFB_V;
    const uint32_t sP = sQ + OFFB_P;

    // ldmatrix lane offsets (fp16 layouts)
    const uint32_t qLane = sQ +
        (uint32_t)(((wq0 + (lane & 15)) * QSTR + (lane >> 4) * 8) * 2);
    const uint32_t pLane = sP +
        (uint32_t)(((wq0 + (lane & 15)) * QSTR + (lane >> 4) * 8) * 2);
    const uint32_t bLaneOff =
        (uint32_t)(((wn0 + (lane & 7) + ((lane >> 4) & 1) * 8) * QSTR
                    + ((lane >> 3) & 1) * 8) * 2);

    // ---- prologue: Q + KV tiles 0,1 ----
#pragma unroll
    for (int it = 0; it < 2; it++) {          // 1024 Q chunks
        const int idx = tid + it * 512;
        const int row = idx >> 3, ch = idx & 7;
        CP_ASYNC16(sQ + (uint32_t)((row * QSTR + ch * 8) * 2),
                   Qg + (rowbase + qstart + row) * H3 + ch * 8);
    }
    {                                          // tile 0: 512 chunks each
        const int row = tid >> 3, ch = tid & 7;
        const uint32_t dsto = (uint32_t)((row * QSTR + ch * 8) * 2);
        CP_ASYNC16(sK + dsto, Kg + (rowbase + row) * H3 + ch * 8);
        CP_ASYNC16(sV + dsto, Vg + (size_t)row * SEQ + ch * 8);
    }
    CP_COMMIT();
    {                                          // tile 1
        const int row = tid >> 3, ch = tid & 7;
        const uint32_t dsto = (uint32_t)((row * QSTR + ch * 8) * 2) + KTILEB;
        CP_ASYNC16(sK + dsto, Kg + (rowbase + 64 + row) * H3 + ch * 8);
        CP_ASYNC16(sV + dsto, Vg + (size_t)row * SEQ + 64 + ch * 8);
    }
    CP_COMMIT();
    CP_WAIT1();

    if (tid < QT) { m_s[tid] = -1e30f; l_s[tid] = 0.0f; }
    if (tid < 64) {
        float s = 0.0f;
#pragma unroll
        for (int p = 0; p < 8; p++) s += SVP[(p * 64 + bh) * 64 + tid];
        sv_s[tid] = 1e-9f * s;
    }

    float oacc[4][4];
#pragma unroll
    for (int nt = 0; nt < 4; nt++)
#pragma unroll
        for (int u = 0; u < 4; u++) oacc[nt][u] = 0.0f;

    __syncthreads();

    for (int kt = 0; kt < NT; kt++) {
        const int cur = kt & 1;
        const uint32_t kCur = sK + cur * KTILEB + bLaneOff;
        const uint32_t vCur = sV + cur * KTILEB + bLaneOff;

        // ---- S = Q K^T (fp16 mma, k=d in 4 chunks of 16) ----
        float sacc[4][4];
#pragma unroll
        for (int nt = 0; nt < 4; nt++)
#pragma unroll
            for (int u = 0; u < 4; u++) sacc[nt][u] = 0.0f;

#pragma unroll
        for (int ks = 0; ks < 4; ks++) {
            const uint32_t ko = ks * 32;
            uint32_t a0, a1, a2, a3;
            LDM_X4(a0, a1, a2, a3, qLane + ko);
#pragma unroll
            for (int np = 0; np < 2; np++) {
                uint32_t b0, b1, b2, b3;
                LDM_X4(b0, b1, b2, b3, kCur + np * (16 * QSTR * 2) + ko);
                MMA_F16(sacc[2 * np],     a0, a1, a2, a3, b0, b1);
                MMA_F16(sacc[2 * np + 1], a0, a1, a2, a3, b2, b3);
            }
        }
#pragma unroll
        for (int nt = 0; nt < 4; nt++) {
            const int col = wn0 + nt * 8 + 2 * c;
            const int row = wq0 + r;
            float v0 = fminf(fmaxf(sacc[nt][0] * 0.125f, -1e9f), 1e9f);
            float v1 = fminf(fmaxf(sacc[nt][1] * 0.125f, -1e9f), 1e9f);
            float v2 = fminf(fmaxf(sacc[nt][2] * 0.125f, -1e9f), 1e9f);
            float v3 = fminf(fmaxf(sacc[nt][3] * 0.125f, -1e9f), 1e9f);
            *(float2*)&Ssf[row * SPAD + col]       = make_float2(v0, v1);
            *(float2*)&Ssf[(row + 8) * SPAD + col] = make_float2(v2, v3);
        }
        __syncthreads();

        // ---- online softmax: 4 threads per row; probs -> fp16 Ps ----
        {
            const int row = tid >> 2;
            const int p   = tid & 3;
            float* srow = &Ssf[row * SPAD];
            __half* prow = &Psh[row * QSTR];
            float mt = -1e30f;
#pragma unroll
            for (int j = 0; j < 16; j++) mt = fmaxf(mt, srow[p + 4 * j]);
            mt = fmaxf(mt, __shfl_xor_sync(0xffffffffu, mt, 1));
            mt = fmaxf(mt, __shfl_xor_sync(0xffffffffu, mt, 2));
            const float mo = m_s[row];
            mt = fmaxf(mt, mo);
            float sum = 0.0f;
#pragma unroll
            for (int j = 0; j < 16; j++) {
                float e = __expf(srow[p + 4 * j] - mt);
                prow[p + 4 * j] = __float2half(e);
                sum += e;
            }
            sum += __shfl_xor_sync(0xffffffffu, sum, 1);
            sum += __shfl_xor_sync(0xffffffffu, sum, 2);
            if (p == 0) {
                const float sc = __expf(mo - mt);
                m_s[row]  = mt;
                l_s[row]  = l_s[row] * sc + sum;
                sc_s[row] = sc;
            }
        }
        __syncthreads();

        // rescale accumulators
        {
            const float sc0 = sc_s[wq0 + r];
            const float sc1 = sc_s[wq0 + r + 8];
#pragma unroll
            for (int nt = 0; nt < 4; nt++) {
                oacc[nt][0] *= sc0; oacc[nt][1] *= sc0;
                oacc[nt][2] *= sc1; oacc[nt][3] *= sc1;
            }
        }

        // ---- O += P V (k=kv in 4 chunks of 16) ----
#pragma unroll
        for (int ks = 0; ks < 4; ks++) {
            const uint32_t ko = ks * 32;
            uint32_t a0, a1, a2, a3;
            LDM_X4(a0, a1, a2, a3, pLane + ko);
#pragma unroll
            for (int np = 0; np < 2; np++) {
                uint32_t b0, b1, b2, b3;
                LDM_X4(b0, b1, b2, b3, vCur + np * (16 * QSTR * 2) + ko);
                MMA_F16(oacc[2 * np],     a0, a1, a2, a3, b0, b1);
                MMA_F16(oacc[2 * np + 1], a0, a1, a2, a3, b2, b3);
            }
        }
        __syncthreads();   // all reads of buffer cur done

        // prefetch tile kt+2 into buffer cur
        if (kt + 2 < NT) {
            const int kstart = (kt + 2) * 64;
            const int row = tid >> 3, ch = tid & 7;
            const uint32_t dsto =
                (uint32_t)((row * QSTR + ch * 8) * 2) + cur * KTILEB;
            CP_ASYNC16(sK + dsto, Kg + (rowbase + kstart + row) * H3 + ch * 8);
            CP_ASYNC16(sV + dsto, Vg + (size_t)row * SEQ + kstart + ch * 8);
            CP_COMMIT();
            CP_WAIT1();
        } else {
            CP_WAIT0();
        }
        __syncthreads();
    }

    // epilogue
    {
        const float linv0 = 1.0f / l_s[wq0 + r];
        const float linv1 = 1.0f / l_s[wq0 + r + 8];
        const int row = qstart + wq0 + r;
#pragma unroll
        for (int nt = 0; nt < 4; nt++) {
            const int col = wn0 + nt * 8 + 2 * c;
            const float e0 = sv_s[col], e1 = sv_s[col + 1];
            float2 o0 = make_float2(oacc[nt][0] * linv0 + e0,
                                    oacc[nt][1] * linv0 + e1);
            float2 o1 = make_float2(oacc[nt][2] * linv1 + e0,
                                    oacc[nt][3] * linv1 + e1);
            *(float2*)&O[obase + (size_t)row * H + col]       = o0;
            *(float2*)&O[obase + (size_t)(row + 8) * H + col] = o1;
        }
    }
}

// ---------------------------------------------------------------------------
// Fused residual-add + LayerNorm; optional fp16 copy of the output.
// ---------------------------------------------------------------------------
template <int WR>
__global__ __launch_bounds__(256)
void add_ln_kernel(const float* __restrict__ A, const float* __restrict__ Bres,
                   const float* __restrict__ gam, const float* __restrict__ bet,
                   float* __restrict__ out, __half* __restrict__ out_r)
{
    const int row = blockIdx.x;
    const int tid = threadIdx.x;
    const float4 va = ((const float4*)(A    + (size_t)row * H))[tid];
    const float4 vb = ((const float4*)(Bres + (size_t)row * H))[tid];
    float x0 = va.x + vb.x, x1 = va.y + vb.y, x2 = va.z + vb.z, x3 = va.w + vb.w;

    __shared__ float red[8];
    __shared__ float s_mu, s_rstd;

    float s = x0 + x1 + x2 + x3;
#pragma unroll
    for (int o = 16; o; o >>= 1) s += __shfl_down_sync(0xffffffffu, s, o);
    if ((tid & 31) == 0) red[tid >> 5] = s;
    __syncthreads();
    if (tid == 0) {
        float t = 0.f;
#pragma unroll
        for (int i = 0; i < 8; i++) t += red[i];
        s_mu = t * (1.0f / H);
    }
    __syncthreads();
    const float mu = s_mu;
    float d0 = x0 - mu, d1 = x1 - mu, d2 = x2 - mu, d3 = x3 - mu;
    float ss = d0 * d0 + d1 * d1 + d2 * d2 + d3 * d3;
#pragma unroll
    for (int o = 16; o; o >>= 1) ss += __shfl_down_sync(0xffffffffu, ss, o);
    __syncthreads();
    if ((tid & 31) == 0) red[tid >> 5] = ss;
    __syncthreads();
    if (tid == 0) {
        float t = 0.f;
#pragma unroll
        for (int i = 0; i < 8; i++) t += red[i];
        s_rstd = rsqrtf(t * (1.0f / H) + 1e-12f);
    }
    __syncthreads();
    const float rstd = s_rstd;

    const float4 g4 = ((const float4*)gam)[tid];
    const float4 b4 = ((const float4*)bet)[tid];
    float4 o;
    o.x = d0 * rstd * g4.x + b4.x;
    o.y = d1 * rstd * g4.y + b4.y;
    o.z = d2 * rstd * g4.z + b4.z;
    o.w = d3 * rstd * g4.w + b4.w;
    ((float4*)(out + (size_t)row * H))[tid] = o;
    if (WR) {
        __half2* orh = (__half2*)(out_r + (size_t)row * H);
        orh[2 * tid]     = __floats2half2_rn(o.x, o.y);
        orh[2 * tid + 1] = __floats2half2_rn(o.z, o.w);
    }
}

// ---------------------------------------------------------------------------
// Launch
// ---------------------------------------------------------------------------
extern "C" void kernel_launch(void* const* d_in, const int* in_sizes, int n_in,
                              void* d_out, int out_size)
{
    const float* hs   = (const float*)d_in[0];
    const float* Wq   = (const float*)d_in[1];
    const float* bq   = (const float*)d_in[2];
    const float* Wk   = (const float*)d_in[3];
    const float* bk   = (const float*)d_in[4];
    const float* Wv   = (const float*)d_in[5];
    const float* bv   = (const float*)d_in[6];
    const float* ln1g = (const float*)d_in[7];
    const float* ln1b = (const float*)d_in[8];
    const float* W1   = (const float*)d_in[9];
    const float* b1   = (const float*)d_in[10];
    const float* W2   = (const float*)d_in[11];
    const float* b2   = (const float*)d_in[12];
    const float* ln2g = (const float*)d_in[13];
    const float* ln2b = (const float*)d_in[14];
    float* out = (float*)d_out;

    static __half *pqkv = nullptr, *pvt = nullptr, *pxr = nullptr,
                  *phsr = nullptr, *pinter = nullptr, *pwqkv = nullptr,
                  *pwt1 = nullptr, *pwt2 = nullptr;
    static float *psvp = nullptr, *pctx = nullptr, *px = nullptr,
                 *pffn = nullptr, *pbqkv = nullptr;
    if (!pqkv) {  // first call is the (uncaptured) correctness run
        cudaGetSymbolAddress((void**)&pqkv,   g_qkv);
        cudaGetSymbolAddress((void**)&pvt,    g_vt);
        cudaGetSymbolAddress((void**)&psvp,   g_svp);
        cudaGetSymbolAddress((void**)&pctx,   g_ctx);
        cudaGetSymbolAddress((void**)&px,     g_x);
        cudaGetSymbolAddress((void**)&pxr,    g_xr);
        cudaGetSymbolAddress((void**)&phsr,   g_hsr);
        cudaGetSymbolAddress((void**)&pinter, g_inter);
        cudaGetSymbolAddress((void**)&pffn,   g_ffn);
        cudaGetSymbolAddress((void**)&pwqkv,  g_wtqkv);
        cudaGetSymbolAddress((void**)&pwt1,   g_wt1);
        cudaGetSymbolAddress((void**)&pwt2,   g_wt2);
        cudaGetSymbolAddress((void**)&pbqkv,  g_bqkv);
        cudaFuncSetAttribute(attn_mma_kernel,
                             cudaFuncAttributeMaxDynamicSharedMemorySize, ATTN_SMEM);
        cudaFuncSetAttribute(mma_gemm<0, 1>,
                             cudaFuncAttributeMaxDynamicSharedMemorySize, GEMM_SMEM);
        cudaFuncSetAttribute(mma_gemm<1, 1>,
                             cudaFuncAttributeMaxDynamicSharedMemorySize, GEMM_SMEM);
        cudaFuncSetAttribute(mma_gemm<0, 0>,
                             cudaFuncAttributeMaxDynamicSharedMemorySize, GEMM_SMEM);
    }

    // prep: weight transposes (fp16), bias concat, hs conversion
    transpose_f16_k<<<dim3(H / 32, H / 32), 256>>>(Wq, pwqkv,             H, H);
    transpose_f16_k<<<dim3(H / 32, H / 32), 256>>>(Wk, pwqkv + H * H,     H, H);
    transpose_f16_k<<<dim3(H / 32, H / 32), 256>>>(Wv, pwqkv + 2 * H * H, H, H);
    transpose_f16_k<<<dim3(FF / 32, H / 32), 256>>>(W1, pwt1, H, FF);
    transpose_f16_k<<<dim3(H / 32, FF / 32), 256>>>(W2, pwt2, FF, H);
    concat_bias_k<<<H3 / 256, 256>>>(bq, bk, bv, pbqkv);
    cvt_f16_k<<<BTOK * H / 1024, 256>>>(hs, phsr);

    // fused QKV projection -> fp16 output
    mma_gemm<0, 1><<<dim3(H3 / 128, BTOK / 128), 256, GEMM_SMEM>>>(
        phsr, pwqkv, pbqkv, pqkv, BTOK, H3, H);
    // V transpose + colsum partials
    vt_transpose_k<<<dim3(SEQ / 32, 2, 64), 256>>>(pqkv, pvt);
    sv_partial_k<<<dim3(64, 8), 64>>>(pqkv, psvp);
    // attention -> ctx (fp32)
    attn_mma_kernel<<<dim3(SEQ / QT, 4 * NH), 512, ATTN_SMEM>>>(pqkv, pvt,
                                                                psvp, pctx);
    // residual + LN1 -> x (+ fp16 copy for FFN1)
    add_ln_kernel<1><<<BTOK, 256>>>(hs, pctx, ln1g, ln1b, px, pxr);
    // FFN1 (gelu output fp16)
    mma_gemm<1, 1><<<dim3(FF / 128, BTOK / 128), 256, GEMM_SMEM>>>(
        pxr, pwt1, b1, pinter, BTOK, FF, H);
    // FFN2 (fp32 output)
    mma_gemm<0, 0><<<dim3(H / 128, BTOK / 128), 256, GEMM_SMEM>>>(
        pinter, pwt2, b2, pffn, BTOK, H, FF);
    // residual + LN2 -> out
    add_ln_kernel<0><<<BTOK, 256>>>(pffn, px, ln2g, ln2b, out, nullptr);
}

// round 16
// speedup vs baseline: 6.2473x; 1.0361x over previous
#include <cuda_runtime.h>
#include <cuda_fp16.h>
#include <math.h>
#include <stdint.h>

#define H    1024
#define NH   16
#define HD   64
#define FF   4096
#define SEQ  2048
#define BTOK 8192   // 4 * 2048 tokens
#define H3   3072   // fused QKV width
#define QT   128
#define NT   (SEQ / 64)

// ---------------------------------------------------------------------------
// Scratch (static __device__ globals: allocation-free rule)
// ---------------------------------------------------------------------------
__device__ __half g_qkv[(size_t)BTOK * H3];    // fp16 Q|K|V
__device__ float  g_svp[8 * 64 * 64];          // colsum(V) partials
__device__ float  g_ctx[BTOK * H];
__device__ float  g_x[BTOK * H];
__device__ __half g_xr[BTOK * H];              // fp16 LN1 output
__device__ __half g_hsr[BTOK * H];             // fp16 hidden_states
__device__ __half g_inter[(size_t)BTOK * FF];  // fp16 gelu output
__device__ float  g_ffn[BTOK * H];
__device__ __half g_wtqkv[(size_t)H3 * H];     // fp16 transposed weights
__device__ __half g_wt1[(size_t)H * FF];
__device__ __half g_wt2[(size_t)FF * H];
__device__ float  g_bqkv[H3];

// ---------------------------------------------------------------------------
// Helpers
// ---------------------------------------------------------------------------
__device__ __forceinline__ uint32_t smem_u32(const void* p) {
    uint32_t a;
    asm("{ .reg .u64 t; cvta.to.shared.u64 t, %1; cvt.u32.u64 %0, t; }"
        : "=r"(a) : "l"(p));
    return a;
}
__device__ __forceinline__ float gelu_exact(float x) {
    return 0.5f * x * (1.0f + erff(x * 0.70710678118654752f));
}

#define MMA_F16(ACC, A0, A1, A2, A3, B0, B1)                                   \
    asm volatile(                                                              \
        "mma.sync.aligned.m16n8k16.row.col.f32.f16.f16.f32 "                   \
        "{%0,%1,%2,%3}, {%4,%5,%6,%7}, {%8,%9}, {%0,%1,%2,%3};"                \
        : "+f"((ACC)[0]), "+f"((ACC)[1]), "+f"((ACC)[2]), "+f"((ACC)[3])       \
        : "r"(A0), "r"(A1), "r"(A2), "r"(A3), "r"(B0), "r"(B1))

#define LDM_X4(R0, R1, R2, R3, ADDR)                                           \
    asm volatile(                                                              \
        "ldmatrix.sync.aligned.m8n8.x4.shared.b16 {%0,%1,%2,%3}, [%4];"        \
        : "=r"(R0), "=r"(R1), "=r"(R2), "=r"(R3) : "r"(ADDR))

#define LDM_X4_T(R0, R1, R2, R3, ADDR)                                         \
    asm volatile(                                                              \
        "ldmatrix.sync.aligned.m8n8.x4.trans.shared.b16 {%0,%1,%2,%3}, [%4];"  \
        : "=r"(R0), "=r"(R1), "=r"(R2), "=r"(R3) : "r"(ADDR))

#define CP_ASYNC16(DST, SRC)                                                   \
    asm volatile("cp.async.cg.shared.global [%0], [%1], 16;"                   \
                 :: "r"(DST), "l"(SRC))
#define CP_COMMIT() asm volatile("cp.async.commit_group;" ::: "memory")
#define CP_WAIT0()  asm volatile("cp.async.wait_group 0;" ::: "memory")
#define CP_WAIT1()  asm volatile("cp.async.wait_group 1;" ::: "memory")
#define CP_WAIT2()  asm volatile("cp.async.wait_group 2;" ::: "memory")

// ---------------------------------------------------------------------------
// Prep kernels
// ---------------------------------------------------------------------------
// W[K][N] fp32 -> Wt[N][K] fp16
__global__ __launch_bounds__(256)
void transpose_f16_k(const float* __restrict__ W, __half* __restrict__ Wt,
                     int K, int N)
{
    __shared__ float t[32][33];
    const int tx = threadIdx.x & 31;
    const int ty = threadIdx.x >> 5;
    const int n0 = blockIdx.x * 32;
    const int k0 = blockIdx.y * 32;
#pragma unroll
    for (int i = 0; i < 4; i++) {
        int r = ty + i * 8;
        t[r][tx] = W[(size_t)(k0 + r) * N + n0 + tx];
    }
    __syncthreads();
#pragma unroll
    for (int i = 0; i < 4; i++) {
        int r = ty + i * 8;
        Wt[(size_t)(n0 + r) * K + k0 + tx] = __float2half(t[tx][r]);
    }
}

__global__ __launch_bounds__(256)
void concat_bias_k(const float* __restrict__ bq, const float* __restrict__ bk,
                   const float* __restrict__ bv, float* __restrict__ o)
{
    int t = threadIdx.x + blockIdx.x * 256;
    if (t < H) o[t] = bq[t];
    else if (t < 2 * H) o[t] = bk[t - H];
    else o[t] = bv[t - 2 * H];
}

// fp32 -> fp16 elementwise
__global__ __launch_bounds__(256)
void cvt_f16_k(const float* __restrict__ x, __half* __restrict__ y)
{
    int i = blockIdx.x * 256 + threadIdx.x;
    float4 v = ((const float4*)x)[i];
    __half2* yo = (__half2*)y;
    yo[2 * i]     = __floats2half2_rn(v.x, v.y);
    yo[2 * i + 1] = __floats2half2_rn(v.z, v.w);
}

__global__ __launch_bounds__(64)
void sv_partial_k(const __half* __restrict__ QKV, float* __restrict__ SVP)
{
    const int bh = blockIdx.x, part = blockIdx.y;
    const int b = bh >> 4, h = bh & 15;
    const int d = threadIdx.x;
    const __half* src = QKV + (size_t)(b * SEQ + part * 256) * H3 + 2 * H + h * HD + d;
    float s = 0.0f;
    for (int kv = 0; kv < 256; kv++) s += __half2float(src[(size_t)kv * H3]);
    SVP[(part * 64 + bh) * 64 + d] = s;
}

// ---------------------------------------------------------------------------
// FP16 GEMM: mma.sync.m16n8k16 + ldmatrix + 4-stage cp.async pipeline.
// C[M,N] = A[M,K](fp16) @ Bt[N,K](fp16)^T + bias(fp32).
// CTA tile 128x128, BK=32 halfs/stage, 256 threads = 8 warps (4M x 2N).
// EPI 0=bias 1=gelu+clamp; CO 0=fp32 out 1=fp16 out.
// ---------------------------------------------------------------------------
#define BM 128
#define BN 128
#define PADKH 40                               // halfs per row (80B, cf-free)
#define GEMM_STAGE_B ((BM + BN) * PADKH * 2)   // 20480 bytes
#define GEMM_NSTG 4
#define GEMM_SMEM (GEMM_NSTG * GEMM_STAGE_B)   // 81920
#define GEMM_BOFF (BM * PADKH * 2)             // 10240

template <int EPI, int CO>
__global__ __launch_bounds__(256)
void mma_gemm(const __half* __restrict__ A, const __half* __restrict__ Bt,
              const float* __restrict__ bias, void* __restrict__ Cv,
              int M, int N, int K)
{
    extern __shared__ __align__(16) char gsm[];
    const uint32_t sBase = smem_u32(gsm);

    const int tid  = threadIdx.x;
    const int lane = tid & 31;
    const int wid  = tid >> 5;
    const int wm0  = (wid >> 1) * 32;
    const int wn0  = (wid & 1) * 64;
    const int r    = lane >> 2;
    const int c    = lane & 3;

    const int row0 = blockIdx.y * BM;
    const int col0 = blockIdx.x * BN;

    const int idxA0 = tid,       rowA0 = idxA0 >> 2, chA0 = idxA0 & 3;
    const int idxA1 = tid + 256, rowA1 = idxA1 >> 2, chA1 = idxA1 & 3;

    const __half* Ap0 = A  + (size_t)(row0 + rowA0) * K + chA0 * 8;
    const __half* Ap1 = A  + (size_t)(row0 + rowA1) * K + chA1 * 8;
    const __half* Bp0 = Bt + (size_t)(col0 + rowA0) * K + chA0 * 8;
    const __half* Bp1 = Bt + (size_t)(col0 + rowA1) * K + chA1 * 8;

    const uint32_t stsA0 = (uint32_t)((rowA0 * PADKH + chA0 * 8) * 2);
    const uint32_t stsA1 = (uint32_t)((rowA1 * PADKH + chA1 * 8) * 2);

    const uint32_t aLaneOff =
        (uint32_t)(((wm0 + (lane & 15)) * PADKH + (lane >> 4) * 8) * 2);
    const uint32_t bLaneOff = GEMM_BOFF +
        (uint32_t)(((wn0 + (lane & 7) + ((lane >> 4) & 1) * 8) * PADKH
                    + ((lane >> 3) & 1) * 8) * 2);

    float acc[2][8][4];
#pragma unroll
    for (int mt = 0; mt < 2; mt++)
#pragma unroll
        for (int nt = 0; nt < 8; nt++)
#pragma unroll
            for (int u = 0; u < 4; u++) acc[mt][nt][u] = 0.0f;

    const int NS = K / 32;

#pragma unroll
    for (int s = 0; s < 3; s++) {
        const uint32_t sb = sBase + s * GEMM_STAGE_B;
        const int k0 = s * 32;
        CP_ASYNC16(sb + stsA0, Ap0 + k0);
        CP_ASYNC16(sb + stsA1, Ap1 + k0);
        CP_ASYNC16(sb + GEMM_BOFF + stsA0, Bp0 + k0);
        CP_ASYNC16(sb + GEMM_BOFF + stsA1, Bp1 + k0);
        CP_COMMIT();
    }

    int buf = 0;
    for (int s = 0; s < NS; s++) {
        if (s + 1 >= NS) CP_WAIT0();
        else if (s + 2 >= NS) CP_WAIT1();
        else CP_WAIT2();
        __syncthreads();

        const uint32_t sb = sBase + buf * GEMM_STAGE_B;

#pragma unroll
        for (int ks = 0; ks < 2; ks++) {
            const uint32_t ko = ks * 32;    // 16 halfs = 32 bytes
            uint32_t af[2][4];
            LDM_X4(af[0][0], af[0][1], af[0][2], af[0][3],
                   sb + aLaneOff + ko);
            LDM_X4(af[1][0], af[1][1], af[1][2], af[1][3],
                   sb + aLaneOff + 16 * PADKH * 2 + ko);
#pragma unroll
            for (int np = 0; np < 4; np++) {
                uint32_t b0, b1, b2, b3;
                LDM_X4(b0, b1, b2, b3, sb + bLaneOff + np * (16 * PADKH * 2) + ko);
                MMA_F16(acc[0][2 * np],     af[0][0], af[0][1], af[0][2], af[0][3], b0, b1);
                MMA_F16(acc[1][2 * np],     af[1][0], af[1][1], af[1][2], af[1][3], b0, b1);
                MMA_F16(acc[0][2 * np + 1], af[0][0], af[0][1], af[0][2], af[0][3], b2, b3);
                MMA_F16(acc[1][2 * np + 1], af[1][0], af[1][1], af[1][2], af[1][3], b2, b3);
            }
        }

        if (s + 3 < NS) {
            const int nb = (buf + 3) & 3;
            const uint32_t nsb = sBase + nb * GEMM_STAGE_B;
            const int k0 = (s + 3) * 32;
            CP_ASYNC16(nsb + stsA0, Ap0 + k0);
            CP_ASYNC16(nsb + stsA1, Ap1 + k0);
            CP_ASYNC16(nsb + GEMM_BOFF + stsA0, Bp0 + k0);
            CP_ASYNC16(nsb + GEMM_BOFF + stsA1, Bp1 + k0);
            CP_COMMIT();
        }
        buf = (buf + 1) & 3;
    }

#pragma unroll
    for (int mt = 0; mt < 2; mt++) {
        const int rowA = row0 + wm0 + mt * 16 + r;
#pragma unroll
        for (int nt = 0; nt < 8; nt++) {
            const int col = col0 + wn0 + nt * 8 + 2 * c;
            const float bz0 = bias[col];
            const float bz1 = bias[col + 1];
            float v0 = acc[mt][nt][0] + bz0;
            float v1 = acc[mt][nt][1] + bz1;
            float v2 = acc[mt][nt][2] + bz0;
            float v3 = acc[mt][nt][3] + bz1;
            if (EPI == 1) {
                v0 = fminf(fmaxf(gelu_exact(v0), -1e9f), 1e9f);
                v1 = fminf(fmaxf(gelu_exact(v1), -1e9f), 1e9f);
                v2 = fminf(fmaxf(gelu_exact(v2), -1e9f), 1e9f);
                v3 = fminf(fmaxf(gelu_exact(v3), -1e9f), 1e9f);
            }
            if (CO) {
                __half* Ch = (__half*)Cv;
                *(__half2*)(Ch + (size_t)rowA * N + col) =
                    __floats2half2_rn(v0, v1);
                *(__half2*)(Ch + (size_t)(rowA + 8) * N + col) =
                    __floats2half2_rn(v2, v3);
            } else {
                float* Cf = (float*)Cv;
                *(float2*)(Cf + (size_t)rowA * N + col)       = make_float2(v0, v1);
                *(float2*)(Cf + (size_t)(rowA + 8) * N + col) = make_float2(v2, v3);
            }
        }
    }
}

// ---------------------------------------------------------------------------
// Flash attention, fp16 MMA: 128-query tiles, 512 threads = 16 warps.
// Q/K/V fp16 via cp.async straight from QKV; V fragments via ldmatrix.trans
// (no pre-transposed VT buffer). Scores/softmax fp32; probs fp16 -> PV.
// ---------------------------------------------------------------------------
#define QSTR 72                       // half stride for Q/K/V/P tiles (144B)
#define QBYTES (QT * QSTR * 2)        // 18432
#define KTILEB (64 * QSTR * 2)        // 9216 per tile
#define SPAD 68                       // float stride for scores
#define OFFB_Q  0
#define OFFB_K  18432
#define OFFB_V  (18432 + 2 * KTILEB)
#define OFFB_S  (OFFB_V + 2 * KTILEB)        // fp32 scores 128x68
#define OFFB_P  (OFFB_S + QT * SPAD * 4)     // fp16 probs 128x72
#define OFFB_ST (OFFB_P + QBYTES)            // stats
#define ATTN_SMEM (OFFB_ST + (3 * QT + 64) * 4)

__global__ __launch_bounds__(512)
void attn_mma_kernel(const __half* __restrict__ QKV,
                     const float* __restrict__ SVP, float* __restrict__ O)
{
    extern __shared__ __align__(16) char smc[];
    float* Ssf  = (float*)(smc + OFFB_S);
    __half* Psh = (__half*)(smc + OFFB_P);
    float* m_s  = (float*)(smc + OFFB_ST);
    float* l_s  = m_s + QT;
    float* sc_s = l_s + QT;
    float* sv_s = sc_s + QT;

    const int tid  = threadIdx.x;
    const int lane = tid & 31;
    const int wid  = tid >> 5;           // 0..15
    const int wq0  = (wid >> 1) * 16;
    const int wn0  = (wid & 1) * 32;
    const int r    = lane >> 2;
    const int c    = lane & 3;

    const int bh = blockIdx.y;
    const int b  = bh >> 4;
    const int h  = bh & 15;
    const int qstart = blockIdx.x * QT;
    const size_t rowbase = (size_t)b * SEQ;
    const __half* Qg = QKV + (size_t)h * HD;
    const __half* Kg = Qg + H;
    const __half* Vg = Qg + 2 * H;
    const size_t obase = (size_t)b * SEQ * H + (size_t)h * HD;

    const uint32_t sQ = smem_u32(smc);
    const uint32_t sK = sQ + OFFB_K;
    const uint32_t sV = sQ + OFFB_V;
    const uint32_t sP = sQ + OFFB_P;

    // ldmatrix lane offsets
    const uint32_t qLane = sQ +
        (uint32_t)(((wq0 + (lane & 15)) * QSTR + (lane >> 4) * 8) * 2);
    const uint32_t pLane = sP +
        (uint32_t)(((wq0 + (lane & 15)) * QSTR + (lane >> 4) * 8) * 2);
    // K (B operand, [n=kv][k=d], normal ldmatrix)
    const uint32_t kLaneOff =
        (uint32_t)(((wn0 + (lane & 7) + ((lane >> 4) & 1) * 8) * QSTR
                    + ((lane >> 3) & 1) * 8) * 2);
    // V (B operand from [k=kv][n=d], ldmatrix.trans)
    const uint32_t vLaneOff =
        (uint32_t)((((lane & 7) + ((lane >> 3) & 1) * 8) * QSTR
                    + wn0 + ((lane >> 4) & 1) * 8) * 2);

    // ---- prologue: Q + KV tiles 0,1 ----
#pragma unroll
    for (int it = 0; it < 2; it++) {          // 1024 Q chunks
        const int idx = tid + it * 512;
        const int row = idx >> 3, ch = idx & 7;
        CP_ASYNC16(sQ + (uint32_t)((row * QSTR + ch * 8) * 2),
                   Qg + (rowbase + qstart + row) * H3 + ch * 8);
    }
    {                                          // tile 0
        const int row = tid >> 3, ch = tid & 7;
        const uint32_t dsto = (uint32_t)((row * QSTR + ch * 8) * 2);
        CP_ASYNC16(sK + dsto, Kg + (rowbase + row) * H3 + ch * 8);
        CP_ASYNC16(sV + dsto, Vg + (rowbase + row) * H3 + ch * 8);
    }
    CP_COMMIT();
    {                                          // tile 1
        const int row = tid >> 3, ch = tid & 7;
        const uint32_t dsto = (uint32_t)((row * QSTR + ch * 8) * 2) + KTILEB;
        CP_ASYNC16(sK + dsto, Kg + (rowbase + 64 + row) * H3 + ch * 8);
        CP_ASYNC16(sV + dsto, Vg + (rowbase + 64 + row) * H3 + ch * 8);
    }
    CP_COMMIT();
    CP_WAIT1();

    if (tid < QT) { m_s[tid] = -1e30f; l_s[tid] = 0.0f; }
    if (tid < 64) {
        float s = 0.0f;
#pragma unroll
        for (int p = 0; p < 8; p++) s += SVP[(p * 64 + bh) * 64 + tid];
        sv_s[tid] = 1e-9f * s;
    }

    float oacc[4][4];
#pragma unroll
    for (int nt = 0; nt < 4; nt++)
#pragma unroll
        for (int u = 0; u < 4; u++) oacc[nt][u] = 0.0f;

    __syncthreads();

    for (int kt = 0; kt < NT; kt++) {
        const int cur = kt & 1;
        const uint32_t kCur = sK + cur * KTILEB + kLaneOff;
        const uint32_t vCur = sV + cur * KTILEB + vLaneOff;

        // ---- S = Q K^T ----
        float sacc[4][4];
#pragma unroll
        for (int nt = 0; nt < 4; nt++)
#pragma unroll
            for (int u = 0; u < 4; u++) sacc[nt][u] = 0.0f;

#pragma unroll
        for (int ks = 0; ks < 4; ks++) {
            const uint32_t ko = ks * 32;
            uint32_t a0, a1, a2, a3;
            LDM_X4(a0, a1, a2, a3, qLane + ko);
#pragma unroll
            for (int np = 0; np < 2; np++) {
                uint32_t b0, b1, b2, b3;
                LDM_X4(b0, b1, b2, b3, kCur + np * (16 * QSTR * 2) + ko);
                MMA_F16(sacc[2 * np],     a0, a1, a2, a3, b0, b1);
                MMA_F16(sacc[2 * np + 1], a0, a1, a2, a3, b2, b3);
            }
        }
#pragma unroll
        for (int nt = 0; nt < 4; nt++) {
            const int col = wn0 + nt * 8 + 2 * c;
            const int row = wq0 + r;
            float v0 = fminf(fmaxf(sacc[nt][0] * 0.125f, -1e9f), 1e9f);
            float v1 = fminf(fmaxf(sacc[nt][1] * 0.125f, -1e9f), 1e9f);
            float v2 = fminf(fmaxf(sacc[nt][2] * 0.125f, -1e9f), 1e9f);
            float v3 = fminf(fmaxf(sacc[nt][3] * 0.125f, -1e9f), 1e9f);
            *(float2*)&Ssf[row * SPAD + col]       = make_float2(v0, v1);
            *(float2*)&Ssf[(row + 8) * SPAD + col] = make_float2(v2, v3);
        }
        __syncthreads();

        // ---- online softmax: 4 threads per row; probs -> fp16 Ps ----
        {
            const int row = tid >> 2;
            const int p   = tid & 3;
            float* srow = &Ssf[row * SPAD];
            __half* prow = &Psh[row * QSTR];
            float mt = -1e30f;
#pragma unroll
            for (int j = 0; j < 16; j++) mt = fmaxf(mt, srow[p + 4 * j]);
            mt = fmaxf(mt, __shfl_xor_sync(0xffffffffu, mt, 1));
            mt = fmaxf(mt, __shfl_xor_sync(0xffffffffu, mt, 2));
            const float mo = m_s[row];
            mt = fmaxf(mt, mo);
            float sum = 0.0f;
#pragma unroll
            for (int j = 0; j < 16; j++) {
                float e = __expf(srow[p + 4 * j] - mt);
                prow[p + 4 * j] = __float2half(e);
                sum += e;
            }
            sum += __shfl_xor_sync(0xffffffffu, sum, 1);
            sum += __shfl_xor_sync(0xffffffffu, sum, 2);
            if (p == 0) {
                const float sc = __expf(mo - mt);
                m_s[row]  = mt;
                l_s[row]  = l_s[row] * sc + sum;
                sc_s[row] = sc;
            }
        }
        __syncthreads();

        // rescale accumulators
        {
            const float sc0 = sc_s[wq0 + r];
            const float sc1 = sc_s[wq0 + r + 8];
#pragma unroll
            for (int nt = 0; nt < 4; nt++) {
                oacc[nt][0] *= sc0; oacc[nt][1] *= sc0;
                oacc[nt][2] *= sc1; oacc[nt][3] *= sc1;
            }
        }

        // ---- O += P V (V fragments via ldmatrix.trans from [kv][d]) ----
#pragma unroll
        for (int ks = 0; ks < 4; ks++) {
            uint32_t a0, a1, a2, a3;
            LDM_X4(a0, a1, a2, a3, pLane + ks * 32);
#pragma unroll
            for (int np = 0; np < 2; np++) {
                uint32_t b0, b1, b2, b3;
                LDM_X4_T(b0, b1, b2, b3,
                         vCur + ks * (16 * QSTR * 2) + np * 32);
                MMA_F16(oacc[2 * np],     a0, a1, a2, a3, b0, b1);
                MMA_F16(oacc[2 * np + 1], a0, a1, a2, a3, b2, b3);
            }
        }
        __syncthreads();   // all reads of buffer cur done

        // prefetch tile kt+2 into buffer cur
        if (kt + 2 < NT) {
            const int kstart = (kt + 2) * 64;
            const int row = tid >> 3, ch = tid & 7;
            const uint32_t dsto =
                (uint32_t)((row * QSTR + ch * 8) * 2) + cur * KTILEB;
            CP_ASYNC16(sK + dsto, Kg + (rowbase + kstart + row) * H3 + ch * 8);
            CP_ASYNC16(sV + dsto, Vg + (rowbase + kstart + row) * H3 + ch * 8);
            CP_COMMIT();
            CP_WAIT1();
        } else {
            CP_WAIT0();
        }
        __syncthreads();
    }

    // epilogue
    {
        const float linv0 = 1.0f / l_s[wq0 + r];
        const float linv1 = 1.0f / l_s[wq0 + r + 8];
        const int row = qstart + wq0 + r;
#pragma unroll
        for (int nt = 0; nt < 4; nt++) {
            const int col = wn0 + nt * 8 + 2 * c;
            const float e0 = sv_s[col], e1 = sv_s[col + 1];
            float2 o0 = make_float2(oacc[nt][0] * linv0 + e0,
                                    oacc[nt][1] * linv0 + e1);
            float2 o1 = make_float2(oacc[nt][2] * linv1 + e0,
                                    oacc[nt][3] * linv1 + e1);
            *(float2*)&O[obase + (size_t)row * H + col]       = o0;
            *(float2*)&O[obase + (size_t)(row + 8) * H + col] = o1;
        }
    }
}

// ---------------------------------------------------------------------------
// Fused residual-add + LayerNorm; optional fp16 copy of the output.
// ---------------------------------------------------------------------------
template <int WR>
__global__ __launch_bounds__(256)
void add_ln_kernel(const float* __restrict__ A, const float* __restrict__ Bres,
                   const float* __restrict__ gam, const float* __restrict__ bet,
                   float* __restrict__ out, __half* __restrict__ out_r)
{
    const int row = blockIdx.x;
    const int tid = threadIdx.x;
    const float4 va = ((const float4*)(A    + (size_t)row * H))[tid];
    const float4 vb = ((const float4*)(Bres + (size_t)row * H))[tid];
    float x0 = va.x + vb.x, x1 = va.y + vb.y, x2 = va.z + vb.z, x3 = va.w + vb.w;

    __shared__ float red[8];
    __shared__ float s_mu, s_rstd;

    float s = x0 + x1 + x2 + x3;
#pragma unroll
    for (int o = 16; o; o >>= 1) s += __shfl_down_sync(0xffffffffu, s, o);
    if ((tid & 31) == 0) red[tid >> 5] = s;
    __syncthreads();
    if (tid == 0) {
        float t = 0.f;
#pragma unroll
        for (int i = 0; i < 8; i++) t += red[i];
        s_mu = t * (1.0f / H);
    }
    __syncthreads();
    const float mu = s_mu;
    float d0 = x0 - mu, d1 = x1 - mu, d2 = x2 - mu, d3 = x3 - mu;
    float ss = d0 * d0 + d1 * d1 + d2 * d2 + d3 * d3;
#pragma unroll
    for (int o = 16; o; o >>= 1) ss += __shfl_down_sync(0xffffffffu, ss, o);
    __syncthreads();
    if ((tid & 31) == 0) red[tid >> 5] = ss;
    __syncthreads();
    if (tid == 0) {
        float t = 0.f;
#pragma unroll
        for (int i = 0; i < 8; i++) t += red[i];
        s_rstd = rsqrtf(t * (1.0f / H) + 1e-12f);
    }
    __syncthreads();
    const float rstd = s_rstd;

    const float4 g4 = ((const float4*)gam)[tid];
    const float4 b4 = ((const float4*)bet)[tid];
    float4 o;
    o.x = d0 * rstd * g4.x + b4.x;
    o.y = d1 * rstd * g4.y + b4.y;
    o.z = d2 * rstd * g4.z + b4.z;
    o.w = d3 * rstd * g4.w + b4.w;
    ((float4*)(out + (size_t)row * H))[tid] = o;
    if (WR) {
        __half2* orh = (__half2*)(out_r + (size_t)row * H);
        orh[2 * tid]     = __floats2half2_rn(o.x, o.y);
        orh[2 * tid + 1] = __floats2half2_rn(o.z, o.w);
    }
}

// ---------------------------------------------------------------------------
// Launch
// ---------------------------------------------------------------------------
extern "C" void kernel_launch(void* const* d_in, const int* in_sizes, int n_in,
                              void* d_out, int out_size)
{
    const float* hs   = (const float*)d_in[0];
    const float* Wq   = (const float*)d_in[1];
    const float* bq   = (const float*)d_in[2];
    const float* Wk   = (const float*)d_in[3];
    const float* bk   = (const float*)d_in[4];
    const float* Wv   = (const float*)d_in[5];
    const float* bv   = (const float*)d_in[6];
    const float* ln1g = (const float*)d_in[7];
    const float* ln1b = (const float*)d_in[8];
    const float* W1   = (const float*)d_in[9];
    const float* b1   = (const float*)d_in[10];
    const float* W2   = (const float*)d_in[11];
    const float* b2   = (const float*)d_in[12];
    const float* ln2g = (const float*)d_in[13];
    const float* ln2b = (const float*)d_in[14];
    float* out = (float*)d_out;

    static __half *pqkv = nullptr, *pxr = nullptr, *phsr = nullptr,
                  *pinter = nullptr, *pwqkv = nullptr, *pwt1 = nullptr,
                  *pwt2 = nullptr;
    static float *psvp = nullptr, *pctx = nullptr, *px = nullptr,
                 *pffn = nullptr, *pbqkv = nullptr;
    static cudaStream_t st1 = nullptr, st2 = nullptr;
    static cudaEvent_t ev0, ev1, ev2;
    if (!pqkv) {  // first call is the (uncaptured) correctness run
        cudaGetSymbolAddress((void**)&pqkv,   g_qkv);
        cudaGetSymbolAddress((void**)&psvp,   g_svp);
        cudaGetSymbolAddress((void**)&pctx,   g_ctx);
        cudaGetSymbolAddress((void**)&px,     g_x);
        cudaGetSymbolAddress((void**)&pxr,    g_xr);
        cudaGetSymbolAddress((void**)&phsr,   g_hsr);
        cudaGetSymbolAddress((void**)&pinter, g_inter);
        cudaGetSymbolAddress((void**)&pffn,   g_ffn);
        cudaGetSymbolAddress((void**)&pwqkv,  g_wtqkv);
        cudaGetSymbolAddress((void**)&pwt1,   g_wt1);
        cudaGetSymbolAddress((void**)&pwt2,   g_wt2);
        cudaGetSymbolAddress((void**)&pbqkv,  g_bqkv);
        cudaStreamCreateWithFlags(&st1, cudaStreamNonBlocking);
        cudaStreamCreateWithFlags(&st2, cudaStreamNonBlocking);
        cudaEventCreateWithFlags(&ev0, cudaEventDisableTiming);
        cudaEventCreateWithFlags(&ev1, cudaEventDisableTiming);
        cudaEventCreateWithFlags(&ev2, cudaEventDisableTiming);
        cudaFuncSetAttribute(attn_mma_kernel,
                             cudaFuncAttributeMaxDynamicSharedMemorySize, ATTN_SMEM);
        cudaFuncSetAttribute(mma_gemm<0, 1>,
                             cudaFuncAttributeMaxDynamicSharedMemorySize, GEMM_SMEM);
        cudaFuncSetAttribute(mma_gemm<1, 1>,
                             cudaFuncAttributeMaxDynamicSharedMemorySize, GEMM_SMEM);
        cudaFuncSetAttribute(mma_gemm<0, 0>,
                             cudaFuncAttributeMaxDynamicSharedMemorySize, GEMM_SMEM);
    }

    // fork: FFN weight transposes on side streams (join before FFN1)
    cudaEventRecord(ev0, 0);
    cudaStreamWaitEvent(st1, ev0, 0);
    cudaStreamWaitEvent(st2, ev0, 0);
    transpose_f16_k<<<dim3(FF / 32, H / 32), 256, 0, st1>>>(W1, pwt1, H, FF);
    transpose_f16_k<<<dim3(H / 32, FF / 32), 256, 0, st2>>>(W2, pwt2, FF, H);
    cudaEventRecord(ev1, st1);
    cudaEventRecord(ev2, st2);

    // critical-path prep (QKV-related only)
    transpose_f16_k<<<dim3(H / 32, H / 32), 256>>>(Wq, pwqkv,             H, H);
    transpose_f16_k<<<dim3(H / 32, H / 32), 256>>>(Wk, pwqkv + H * H,     H, H);
    transpose_f16_k<<<dim3(H / 32, H / 32), 256>>>(Wv, pwqkv + 2 * H * H, H, H);
    concat_bias_k<<<H3 / 256, 256>>>(bq, bk, bv, pbqkv);
    cvt_f16_k<<<BTOK * H / 1024, 256>>>(hs, phsr);

    // fused QKV projection -> fp16 output
    mma_gemm<0, 1><<<dim3(H3 / 128, BTOK / 128), 256, GEMM_SMEM>>>(
        phsr, pwqkv, pbqkv, pqkv, BTOK, H3, H);
    // colsum(V) partials
    sv_partial_k<<<dim3(64, 8), 64>>>(pqkv, psvp);
    // attention -> ctx (fp32)
    attn_mma_kernel<<<dim3(SEQ / QT, 4 * NH), 512, ATTN_SMEM>>>(pqkv, psvp, pctx);
    // residual + LN1 -> x (+ fp16 copy for FFN1)
    add_ln_kernel<1><<<BTOK, 256>>>(hs, pctx, ln1g, ln1b, px, pxr);

    // join the FFN weight branches
    cudaStreamWaitEvent(0, ev1, 0);
    cudaStreamWaitEvent(0, ev2, 0);

    // FFN1 (gelu output fp16)
    mma_gemm<1, 1><<<dim3(FF / 128, BTOK / 128), 256, GEMM_SMEM>>>(
        pxr, pwt1, b1, pinter, BTOK, FF, H);
    // FFN2 (fp32 output)
    mma_gemm<0, 0><<<dim3(H / 128, BTOK / 128), 256, GEMM_SMEM>>>(
        pinter, pwt2, b2, pffn, BTOK, H, FF);
    // residual + LN2 -> out
    add_ln_kernel<0><<<BTOK, 256>>>(pffn, px, ln2g, ln2b, out, nullptr);
}